// round 6
// baseline (speedup 1.0000x reference)
#include <cuda_runtime.h>
#include <cuda_fp16.h>
#include <cstdint>

#define T_DIM 2048
#define B_DIM 2
#define E_DIM 1024
#define H_DIM 16
#define HD_DIM 64
#define S_DIM 2048
#define MB_DIM (T_DIM * B_DIM)     // 4096
#define LDQ (B_DIM * E_DIM)        // 2048

// Static device scratch (fp16 operands; no gmem scores buffer anymore)
__device__ __half g_xq[(size_t)MB_DIM * E_DIM];
__device__ __half g_xk[(size_t)MB_DIM * E_DIM];
__device__ __half g_xv[(size_t)MB_DIM * E_DIM];
__device__ __half g_wq[(size_t)E_DIM * E_DIM];
__device__ __half g_wk[(size_t)E_DIM * E_DIM];
__device__ __half g_wv[(size_t)E_DIM * E_DIM];
__device__ __half g_wo[(size_t)E_DIM * E_DIM];
__device__ __half g_qh[(size_t)MB_DIM * E_DIM];
__device__ __half g_kh[(size_t)MB_DIM * E_DIM];
__device__ __half g_vh[(size_t)MB_DIM * E_DIM];
__device__ __half g_ctxh[(size_t)MB_DIM * E_DIM];
__device__ __half g_vt[(size_t)B_DIM * H_DIM * HD_DIM * S_DIM];
__device__ __half g_attn[(size_t)B_DIM * H_DIM * T_DIM * S_DIM];

__device__ __forceinline__ uint32_t smem_u32(const void* p) {
    uint32_t a;
    asm("{ .reg .u64 t; cvta.to.shared.u64 t, %1; cvt.u32.u64 %0, t; }" : "=r"(a) : "l"(p));
    return a;
}
__device__ __forceinline__ void cp16(uint32_t dst, const void* src) {
    asm volatile("cp.async.ca.shared.global [%0], [%1], 16;" :: "r"(dst), "l"(src) : "memory");
}
#define CP_COMMIT() asm volatile("cp.async.commit_group;" ::: "memory")
#define CP_WAIT1()  asm volatile("cp.async.wait_group 1;" ::: "memory")

__device__ __forceinline__ void ldm_x4(uint32_t r[4], uint32_t a) {
    asm volatile("ldmatrix.sync.aligned.m8n8.x4.shared.b16 {%0,%1,%2,%3}, [%4];"
        : "=r"(r[0]), "=r"(r[1]), "=r"(r[2]), "=r"(r[3]) : "r"(a));
}
__device__ __forceinline__ void mma_f16(float c[4], const uint32_t a[4], const uint32_t b[2]) {
    asm volatile(
        "mma.sync.aligned.m16n8k16.row.col.f32.f16.f16.f32 "
        "{%0,%1,%2,%3}, {%4,%5,%6,%7}, {%8,%9}, {%0,%1,%2,%3};"
        : "+f"(c[0]), "+f"(c[1]), "+f"(c[2]), "+f"(c[3])
        : "r"(a[0]), "r"(a[1]), "r"(a[2]), "r"(a[3]), "r"(b[0]), "r"(b[1]));
}

// ---------------------------------------------------------------------------
// fp16 mma.sync GEMM core (unchanged from R5).
// ---------------------------------------------------------------------------
template <int BN, int WARPS_M, int WARPS_N, bool C_HALF>
__device__ __forceinline__ void mm_core(
    const __half* __restrict__ A, int lda,
    const __half* __restrict__ B, int ldb,
    void* Cp, int ldc,
    const float* __restrict__ bias, float alpha, int K)
{
    constexpr int BM = 128, BK = 64, PAD = 72;
    constexpr int WM = BM / WARPS_M, WN = BN / WARPS_N;
    constexpr int MF = WM / 16, NF = WN / 8;
    constexpr int NCA = (BM * BK / 8) / 256;
    constexpr int NCB = (BN * BK / 8) / 256;
    constexpr uint32_t ASTG = BM * PAD * 2;
    constexpr uint32_t BSTG = BN * PAD * 2;

    extern __shared__ __align__(16) char dsm[];
    __half* As = (__half*)dsm;
    __half* Bs = (__half*)(dsm + 2 * ASTG);

    const int tid = threadIdx.x;
    const int wid = tid >> 5;
    const int lane = tid & 31;
    const int lr = lane >> 2;
    const int lc = lane & 3;
    const int warpM = wid % WARPS_M;
    const int warpN = wid / WARPS_M;
    const int m0 = blockIdx.y * BM;
    const int n0 = blockIdx.x * BN;

    const uint32_t as_base = smem_u32(As);
    const uint32_t bs_base = smem_u32(Bs);

    float acc[MF][NF][4];
#pragma unroll
    for (int i = 0; i < MF; i++)
#pragma unroll
        for (int j = 0; j < NF; j++)
#pragma unroll
            for (int q = 0; q < 4; q++) acc[i][j][q] = 0.f;

    auto ldgsts = [&](int kt, int p) {
        const int k0 = kt * BK;
#pragma unroll
        for (int i = 0; i < NCA; i++) {
            int ch = tid + i * 256, r = ch >> 3, c = (ch & 7) * 8;
            cp16(as_base + p * ASTG + (uint32_t)(r * PAD + c) * 2,
                 A + (size_t)(m0 + r) * lda + k0 + c);
        }
#pragma unroll
        for (int i = 0; i < NCB; i++) {
            int ch = tid + i * 256, r = ch >> 3, c = (ch & 7) * 8;
            cp16(bs_base + p * BSTG + (uint32_t)(r * PAD + c) * 2,
                 B + (size_t)(n0 + r) * ldb + k0 + c);
        }
    };

    auto compute = [&](int p) {
        const uint32_t ab = as_base + p * ASTG;
        const uint32_t bb = bs_base + p * BSTG;
#pragma unroll
        for (int ks = 0; ks < BK / 16; ks++) {
            const int kh = ks * 16;
            uint32_t af[MF][4], bf[NF][2];
#pragma unroll
            for (int i = 0; i < MF; i++) {
                uint32_t off = (uint32_t)((warpM * WM + i * 16 + (lane & 15)) * PAD +
                                          kh + ((lane >> 4) << 3));
                ldm_x4(af[i], ab + (off << 1));
            }
#pragma unroll
            for (int j = 0; j < NF; j += 2) {
                int row = warpN * WN + (j + (lane >> 4)) * 8 + (lane & 7);
                int col = kh + ((lane >> 3) & 1) * 8;
                uint32_t r4[4];
                ldm_x4(r4, bb + ((uint32_t)(row * PAD + col) << 1));
                bf[j][0] = r4[0]; bf[j][1] = r4[1];
                bf[j + 1][0] = r4[2]; bf[j + 1][1] = r4[3];
            }
#pragma unroll
            for (int i = 0; i < MF; i++)
#pragma unroll
                for (int j = 0; j < NF; j++)
                    mma_f16(acc[i][j], af[i], bf[j]);
        }
    };

    ldgsts(0, 0);
    CP_COMMIT();
    const int ktiles = K / BK;
    for (int kt = 0; kt < ktiles; kt++) {
        if (kt + 1 < ktiles) ldgsts(kt + 1, (kt + 1) & 1);
        CP_COMMIT();
        CP_WAIT1();
        __syncthreads();
        compute(kt & 1);
        __syncthreads();
    }

#pragma unroll
    for (int i = 0; i < MF; i++) {
        int r0 = m0 + warpM * WM + i * 16 + lr;
#pragma unroll
        for (int j = 0; j < NF; j++) {
            int c0 = n0 + warpN * WN + j * 8 + 2 * lc;
            float2 bv = bias ? *(const float2*)(bias + c0) : make_float2(0.f, 0.f);
            float x0 = acc[i][j][0] * alpha + bv.x;
            float x1 = acc[i][j][1] * alpha + bv.y;
            float x2 = acc[i][j][2] * alpha + bv.x;
            float x3 = acc[i][j][3] * alpha + bv.y;
            if constexpr (C_HALF) {
                __half* C = (__half*)Cp;
                *(__half2*)(C + (size_t)r0 * ldc + c0) = __floats2half2_rn(x0, x1);
                *(__half2*)(C + (size_t)(r0 + 8) * ldc + c0) = __floats2half2_rn(x2, x3);
            } else {
                float* C = (float*)Cp;
                *(float2*)(C + (size_t)r0 * ldc + c0) = make_float2(x0, x1);
                *(float2*)(C + (size_t)(r0 + 8) * ldc + c0) = make_float2(x2, x3);
            }
        }
    }
}

// ---------------- GEMM wrappers ----------------
__global__ void __launch_bounds__(256) k_proj_h(
    const __half* __restrict__ A, const __half* __restrict__ W,
    const float* __restrict__ bias, __half* __restrict__ C)
{
    mm_core<128, 2, 4, true>(A, E_DIM, W, E_DIM, C, E_DIM, bias, 1.f, E_DIM);
}

__global__ void __launch_bounds__(256) k_proj_f(
    const __half* __restrict__ A, const __half* __restrict__ W,
    const float* __restrict__ bias, float* __restrict__ C)
{
    mm_core<128, 2, 4, false>(A, E_DIM, W, E_DIM, C, E_DIM, bias, 1.f, E_DIM);
}

__global__ void __launch_bounds__(256) k_av(
    const __half* __restrict__ attn, const __half* __restrict__ vt, __half* __restrict__ ctx)
{
    int z = blockIdx.z;
    int b = z >> 4, h = z & 15;
    const __half* A = attn + (size_t)z * T_DIM * S_DIM;
    const __half* B = vt + (size_t)z * HD_DIM * S_DIM;
    __half* C = ctx + (size_t)b * E_DIM + h * HD_DIM;
    mm_core<64, 4, 2, true>(A, S_DIM, B, S_DIM, C, LDQ, nullptr, 1.f, S_DIM);
}

// ---------------------------------------------------------------------------
// Fused QK^T + softmax + fp16 attn + avg_w.
// CTA = (t-block of 16 rows, b). 512 threads = 16 warps; warp w owns score
// column slice [w*16, w*16+16) during GEMM and row w during softmax.
// ---------------------------------------------------------------------------
#define FBM 16
#define FCH 256
#define FNCH (S_DIM / FCH)   // 8
#define KPAD 72
#define SCPITCH 2056
#define SM_FUSED (FBM * SCPITCH * 4 + 2 * FCH * KPAD * 2 + FBM * KPAD * 2)

__global__ void __launch_bounds__(512) k_qk_softmax(
    const __half* __restrict__ qh, const __half* __restrict__ kh,
    __half* __restrict__ attn, float* __restrict__ avgw)
{
    extern __shared__ __align__(16) char dsm[];
    float*  sc  = (float*)dsm;                                         // [16][SCPITCH]
    __half* kst = (__half*)(dsm + FBM * SCPITCH * 4);                  // [2][FCH*KPAD]
    __half* qt  = (__half*)(dsm + FBM * SCPITCH * 4 + 2 * FCH * KPAD * 2); // [16*KPAD]
    float*  pmx = (float*)qt;  // alias: pmax[16 rows][16 warps], used after a-frags built

    const int tid = threadIdx.x;
    const int w = tid >> 5;
    const int lane = tid & 31;
    const int lr = lane >> 2, lc = lane & 3;
    const int t0 = blockIdx.x * FBM;
    const int b  = blockIdx.y;

    const uint32_t sb_k = smem_u32(kst);
    const uint32_t sb_q = smem_u32(qt);
    constexpr uint32_t KSTG = FCH * KPAD * 2;

    float2 avg[32];
#pragma unroll
    for (int i = 0; i < 32; i++) avg[i] = make_float2(0.f, 0.f);

    auto ldgK = [&](int h, int c, int buf) {
        const int s0 = c * FCH;
#pragma unroll
        for (int i = 0; i < 4; i++) {
            int ch = tid + i * 512, r = ch >> 3, seg = ch & 7;
            cp16(sb_k + buf * KSTG + (uint32_t)(r * KPAD + seg * 8) * 2,
                 kh + ((size_t)((s0 + r) * B_DIM + b)) * E_DIM + /*h*/ h * HD_DIM + seg * 8);
        }
    };

    ldgK(0, 0, 0); CP_COMMIT();

    for (int h = 0; h < H_DIM; h++) {
        // q tile -> smem
        if (tid < 128) {
            int r = tid >> 3, seg = tid & 7;
            uint4 v = *(const uint4*)(qh + ((size_t)((t0 + r) * B_DIM + b)) * E_DIM +
                                      h * HD_DIM + seg * 8);
            *(uint4*)(qt + r * KPAD + seg * 8) = v;
        }
        __syncthreads();

        // a-frags cached in regs for the whole head
        uint32_t af[4][4];
#pragma unroll
        for (int ks = 0; ks < 4; ks++) {
            uint32_t off = (uint32_t)((lane & 15) * KPAD + ks * 16 + ((lane >> 4) << 3));
            ldm_x4(af[ks], sb_q + (off << 1));
        }

        float pm0 = -1e30f, pm1 = -1e30f;
        for (int c = 0; c < FNCH; c++) {
            if (c + 1 < FNCH)        { ldgK(h, c + 1, (c + 1) & 1); CP_COMMIT(); }
            else if (h + 1 < H_DIM)  { ldgK(h + 1, 0, 0);           CP_COMMIT(); }
            else                     {                               CP_COMMIT(); }
            CP_WAIT1();
            __syncthreads();

            const uint32_t kb = sb_k + (uint32_t)(c & 1) * KSTG;
            float a0[4] = {0.f, 0.f, 0.f, 0.f};
            float a1[4] = {0.f, 0.f, 0.f, 0.f};
#pragma unroll
            for (int ks = 0; ks < 4; ks++) {
                int row = w * 16 + (lane >> 4) * 8 + (lane & 7);
                int col = ks * 16 + ((lane >> 3) & 1) * 8;
                uint32_t r4[4];
                ldm_x4(r4, kb + ((uint32_t)(row * KPAD + col) << 1));
                mma_f16(a0, af[ks], r4 + 0);
                mma_f16(a1, af[ks], r4 + 2);
            }
            float* s0p = sc + lr * SCPITCH + c * FCH + w * 16 + 2 * lc;
            float* s1p = sc + (lr + 8) * SCPITCH + c * FCH + w * 16 + 2 * lc;
            *(float2*)(s0p)     = make_float2(a0[0], a0[1]);
            *(float2*)(s0p + 8) = make_float2(a1[0], a1[1]);
            *(float2*)(s1p)     = make_float2(a0[2], a0[3]);
            *(float2*)(s1p + 8) = make_float2(a1[2], a1[3]);
            pm0 = fmaxf(pm0, fmaxf(fmaxf(a0[0], a0[1]), fmaxf(a1[0], a1[1])));
            pm1 = fmaxf(pm1, fmaxf(fmaxf(a0[2], a0[3]), fmaxf(a1[2], a1[3])));
            __syncthreads();
        }

        // fold per-lane partial maxes -> pmx[row][warp]
        pm0 = fmaxf(pm0, __shfl_xor_sync(0xffffffffu, pm0, 1));
        pm0 = fmaxf(pm0, __shfl_xor_sync(0xffffffffu, pm0, 2));
        pm1 = fmaxf(pm1, __shfl_xor_sync(0xffffffffu, pm1, 1));
        pm1 = fmaxf(pm1, __shfl_xor_sync(0xffffffffu, pm1, 2));
        if (lc == 0) {
            pmx[lr * 16 + w] = pm0;
            pmx[(lr + 8) * 16 + w] = pm1;
        }
        __syncthreads();

        // softmax: warp w owns row w
        float M = (lane < 16) ? pmx[w * 16 + lane] : -1e30f;
#pragma unroll
        for (int o = 16; o; o >>= 1) M = fmaxf(M, __shfl_xor_sync(0xffffffffu, M, o));

        const float* srow = sc + w * SCPITCH;
        float Z = 0.f;
        __half2 e2[32];
#pragma unroll
        for (int i = 0; i < 32; i++) {
            float2 v = *(const float2*)(srow + 2 * (lane + 32 * i));
            float e0 = __expf((v.x - M) * 0.125f);
            float e1 = __expf((v.y - M) * 0.125f);
            Z += e0 + e1;
            e2[i] = __floats2half2_rn(e0, e1);
        }
#pragma unroll
        for (int o = 16; o; o >>= 1) Z += __shfl_xor_sync(0xffffffffu, Z, o);
        const float inv = 1.f / Z;
        const __half2 hinv = __floats2half2_rn(inv, inv);

        __half* arow = attn + ((size_t)(b * H_DIM + h) * T_DIM + t0 + w) * S_DIM;
#pragma unroll
        for (int i = 0; i < 32; i++) {
            __half2 p = __hmul2(e2[i], hinv);
            *(__half2*)(arow + 2 * (lane + 32 * i)) = p;
            float2 pf = __half22float2(p);
            avg[i].x += pf.x;
            avg[i].y += pf.y;
        }
        __syncthreads();   // protect pmx/qt/sc before next head's writes
    }

    // write avg_w (row w of this t-block)
    float* vrow = avgw + ((size_t)(b * T_DIM) + t0 + w) * S_DIM;
    const float invH = 1.f / (float)H_DIM;
#pragma unroll
    for (int i = 0; i < 32; i++) {
        *(float2*)(vrow + 2 * (lane + 32 * i)) =
            make_float2(avg[i].x * invH, avg[i].y * invH);
    }
}

// fp32 -> fp16 convert (n % 4 == 0)
__global__ void __launch_bounds__(256) k_cvt(
    const float* __restrict__ x, __half* __restrict__ y, int n)
{
    int i = (blockIdx.x * 256 + threadIdx.x) * 4;
    if (i < n) {
        float4 v = *(const float4*)(x + i);
        __half2 a = __floats2half2_rn(v.x, v.y);
        __half2 b = __floats2half2_rn(v.z, v.w);
        union { __half2 h[2]; uint2 u; } p;
        p.h[0] = a; p.h[1] = b;
        *(uint2*)(y + i) = p.u;
    }
}

// V transpose fp16: vt[(z*64+d)*S + s] = vh[(s*2+b)*E + h*64+d]
__global__ void __launch_bounds__(256) k_transpose_v(
    const __half* __restrict__ v, __half* __restrict__ vt)
{
    __shared__ __half t[32][34];
    int z = blockIdx.z, b = z >> 4, h = z & 15;
    int s0 = blockIdx.x * 32, d0 = blockIdx.y * 32;
    int lx = threadIdx.x & 31, ly = threadIdx.x >> 5;
#pragma unroll
    for (int i = 0; i < 32; i += 8) {
        int s = s0 + ly + i;
        t[ly + i][lx] = v[(size_t)(s * B_DIM + b) * E_DIM + h * HD_DIM + d0 + lx];
    }
    __syncthreads();
#pragma unroll
    for (int i = 0; i < 32; i += 8) {
        int d = d0 + ly + i;
        vt[((size_t)z * HD_DIM + d) * S_DIM + s0 + lx] = t[lx][ly + i];
    }
}

// ---------------------------------------------------------------------------
extern "C" void kernel_launch(void* const* d_in, const int* in_sizes, int n_in,
                              void* d_out, int out_size)
{
    const float* query = (const float*)d_in[0];
    const float* key   = (const float*)d_in[1];
    const float* value = (const float*)d_in[2];
    const float* Wq = (const float*)d_in[3];
    const float* bq = (const float*)d_in[4];
    const float* Wk = (const float*)d_in[5];
    const float* bk = (const float*)d_in[6];
    const float* Wv = (const float*)d_in[7];
    const float* bv = (const float*)d_in[8];
    const float* Wo = (const float*)d_in[9];
    const float* bo = (const float*)d_in[10];

    float* out  = (float*)d_out;
    float* avgw = out + (size_t)MB_DIM * E_DIM;

    __half *xq, *xk, *xv, *wq, *wk, *wv, *wo, *qh, *kh, *vh, *ctxh, *vt, *attn;
    cudaGetSymbolAddress((void**)&xq,   g_xq);
    cudaGetSymbolAddress((void**)&xk,   g_xk);
    cudaGetSymbolAddress((void**)&xv,   g_xv);
    cudaGetSymbolAddress((void**)&wq,   g_wq);
    cudaGetSymbolAddress((void**)&wk,   g_wk);
    cudaGetSymbolAddress((void**)&wv,   g_wv);
    cudaGetSymbolAddress((void**)&wo,   g_wo);
    cudaGetSymbolAddress((void**)&qh,   g_qh);
    cudaGetSymbolAddress((void**)&kh,   g_kh);
    cudaGetSymbolAddress((void**)&vh,   g_vh);
    cudaGetSymbolAddress((void**)&ctxh, g_ctxh);
    cudaGetSymbolAddress((void**)&vt,   g_vt);
    cudaGetSymbolAddress((void**)&attn, g_attn);

    const int SM_BIG = 2 * (128 * 72 * 2) * 2;                   // 73728
    const int SM_AV  = 2 * (128 * 72 * 2) + 2 * (64 * 72 * 2);   // 55296
    cudaFuncSetAttribute(k_proj_h, cudaFuncAttributeMaxDynamicSharedMemorySize, SM_BIG);
    cudaFuncSetAttribute(k_proj_f, cudaFuncAttributeMaxDynamicSharedMemorySize, SM_BIG);
    cudaFuncSetAttribute(k_av,     cudaFuncAttributeMaxDynamicSharedMemorySize, SM_AV);
    cudaFuncSetAttribute(k_qk_softmax, cudaFuncAttributeMaxDynamicSharedMemorySize, SM_FUSED);

    const int NXE = MB_DIM * E_DIM;
    const int NWW = E_DIM * E_DIM;
    k_cvt<<<NXE / 1024, 256>>>(query, xq, NXE);
    k_cvt<<<NXE / 1024, 256>>>(key,   xk, NXE);
    k_cvt<<<NXE / 1024, 256>>>(value, xv, NXE);
    k_cvt<<<NWW / 1024, 256>>>(Wq, wq, NWW);
    k_cvt<<<NWW / 1024, 256>>>(Wk, wk, NWW);
    k_cvt<<<NWW / 1024, 256>>>(Wv, wv, NWW);
    k_cvt<<<NWW / 1024, 256>>>(Wo, wo, NWW);

    dim3 gp(E_DIM / 128, MB_DIM / 128);                 // (8, 32)
    k_proj_h<<<gp, 256, SM_BIG>>>(xq, wq, bq, qh);
    k_proj_h<<<gp, 256, SM_BIG>>>(xk, wk, bk, kh);
    k_proj_h<<<gp, 256, SM_BIG>>>(xv, wv, bv, vh);

    dim3 gt(S_DIM / 32, HD_DIM / 32, B_DIM * H_DIM);    // (64, 2, 32)
    k_transpose_v<<<gt, 256>>>(vh, vt);

    dim3 gf(T_DIM / FBM, B_DIM);                        // (128, 2)
    k_qk_softmax<<<gf, 512, SM_FUSED>>>(qh, kh, attn, avgw);

    dim3 ga(1, T_DIM / 128, B_DIM * H_DIM);             // (1, 16, 32)
    k_av<<<ga, 256, SM_AV>>>(attn, vt, ctxh);

    k_proj_f<<<gp, 256, SM_BIG>>>(ctxh, wo, bo, out);
}

// round 7
// speedup vs baseline: 1.2970x; 1.2970x over previous
#include <cuda_runtime.h>
#include <cuda_fp16.h>
#include <cstdint>

#define T_DIM 2048
#define B_DIM 2
#define E_DIM 1024
#define H_DIM 16
#define HD_DIM 64
#define S_DIM 2048
#define MB_DIM (T_DIM * B_DIM)     // 4096
#define LDQ (B_DIM * E_DIM)        // 2048

// Static device scratch
__device__ __half g_xq[(size_t)MB_DIM * E_DIM];
__device__ __half g_xk[(size_t)MB_DIM * E_DIM];
__device__ __half g_xv[(size_t)MB_DIM * E_DIM];
__device__ __half g_wq[(size_t)E_DIM * E_DIM];
__device__ __half g_wk[(size_t)E_DIM * E_DIM];
__device__ __half g_wv[(size_t)E_DIM * E_DIM];
__device__ __half g_wo[(size_t)E_DIM * E_DIM];
__device__ __half g_qh[(size_t)MB_DIM * E_DIM];
__device__ __half g_kh[(size_t)MB_DIM * E_DIM];
__device__ __half g_vh[(size_t)MB_DIM * E_DIM];
__device__ __half g_ctxh[(size_t)MB_DIM * E_DIM];
__device__ __half g_vt[(size_t)B_DIM * H_DIM * HD_DIM * S_DIM];
__device__ float  g_scores[(size_t)B_DIM * H_DIM * T_DIM * S_DIM];
__device__ __half g_attn[(size_t)B_DIM * H_DIM * T_DIM * S_DIM];

__device__ __forceinline__ uint32_t smem_u32(const void* p) {
    uint32_t a;
    asm("{ .reg .u64 t; cvta.to.shared.u64 t, %1; cvt.u32.u64 %0, t; }" : "=r"(a) : "l"(p));
    return a;
}
__device__ __forceinline__ void cp16(uint32_t dst, const void* src) {
    asm volatile("cp.async.ca.shared.global [%0], [%1], 16;" :: "r"(dst), "l"(src) : "memory");
}
#define CP_COMMIT() asm volatile("cp.async.commit_group;" ::: "memory")
#define CP_WAIT1()  asm volatile("cp.async.wait_group 1;" ::: "memory")
#define CP_WAIT0()  asm volatile("cp.async.wait_group 0;" ::: "memory")

__device__ __forceinline__ void ldm_x4(uint32_t r[4], uint32_t a) {
    asm volatile("ldmatrix.sync.aligned.m8n8.x4.shared.b16 {%0,%1,%2,%3}, [%4];"
        : "=r"(r[0]), "=r"(r[1]), "=r"(r[2]), "=r"(r[3]) : "r"(a));
}
__device__ __forceinline__ void mma_f16(float c[4], const uint32_t a[4], const uint32_t b[2]) {
    asm volatile(
        "mma.sync.aligned.m16n8k16.row.col.f32.f16.f16.f32 "
        "{%0,%1,%2,%3}, {%4,%5,%6,%7}, {%8,%9}, {%0,%1,%2,%3};"
        : "+f"(c[0]), "+f"(c[1]), "+f"(c[2]), "+f"(c[3])
        : "r"(a[0]), "r"(a[1]), "r"(a[2]), "r"(a[3]), "r"(b[0]), "r"(b[1]));
}

// ---------------------------------------------------------------------------
// fp16 mma.sync GEMM core, cp.async multi-stage pipeline (1 sync per k-tile).
// C[m][n] = alpha * sum_k A[m][k]*B[n][k] (+bias[n]).  BM=128, BK=64.
// ---------------------------------------------------------------------------
template <int BN, int WARPS_M, int WARPS_N, bool C_HALF, int STAGES>
__device__ __forceinline__ void mm_core(
    const __half* __restrict__ A, int lda,
    const __half* __restrict__ B, int ldb,
    void* Cp, int ldc,
    const float* __restrict__ bias, float alpha, int K)
{
    constexpr int BM = 128, BK = 64, PAD = 72;
    constexpr int WM = BM / WARPS_M, WN = BN / WARPS_N;
    constexpr int MF = WM / 16, NF = WN / 8;
    constexpr int NCA = (BM * BK / 8) / 256;
    constexpr int NCB = (BN * BK / 8) / 256;
    constexpr uint32_t ASTG = BM * PAD * 2;
    constexpr uint32_t BSTG = BN * PAD * 2;
    constexpr uint32_t STG  = ASTG + BSTG;

    extern __shared__ __align__(16) char dsm[];

    const int tid = threadIdx.x;
    const int wid = tid >> 5;
    const int lane = tid & 31;
    const int lr = lane >> 2;
    const int lc = lane & 3;
    const int warpM = wid % WARPS_M;
    const int warpN = wid / WARPS_M;
    const int m0 = blockIdx.y * BM;
    const int n0 = blockIdx.x * BN;

    const uint32_t smb = smem_u32(dsm);

    float acc[MF][NF][4];
#pragma unroll
    for (int i = 0; i < MF; i++)
#pragma unroll
        for (int j = 0; j < NF; j++)
#pragma unroll
            for (int q = 0; q < 4; q++) acc[i][j][q] = 0.f;

    auto ldgsts = [&](int kt, int p) {
        const int k0 = kt * BK;
        const uint32_t ab = smb + (uint32_t)p * STG;
        const uint32_t bb = ab + ASTG;
#pragma unroll
        for (int i = 0; i < NCA; i++) {
            int ch = tid + i * 256, r = ch >> 3, c = (ch & 7) * 8;
            cp16(ab + (uint32_t)(r * PAD + c) * 2,
                 A + (size_t)(m0 + r) * lda + k0 + c);
        }
#pragma unroll
        for (int i = 0; i < NCB; i++) {
            int ch = tid + i * 256, r = ch >> 3, c = (ch & 7) * 8;
            cp16(bb + (uint32_t)(r * PAD + c) * 2,
                 B + (size_t)(n0 + r) * ldb + k0 + c);
        }
    };

    auto compute = [&](int p) {
        const uint32_t ab = smb + (uint32_t)p * STG;
        const uint32_t bb = ab + ASTG;
#pragma unroll
        for (int ks = 0; ks < BK / 16; ks++) {
            const int kh = ks * 16;
            uint32_t af[MF][4], bf[NF][2];
#pragma unroll
            for (int i = 0; i < MF; i++) {
                uint32_t off = (uint32_t)((warpM * WM + i * 16 + (lane & 15)) * PAD +
                                          kh + ((lane >> 4) << 3));
                ldm_x4(af[i], ab + (off << 1));
            }
#pragma unroll
            for (int j = 0; j < NF; j += 2) {
                int row = warpN * WN + (j + (lane >> 4)) * 8 + (lane & 7);
                int col = kh + ((lane >> 3) & 1) * 8;
                uint32_t r4[4];
                ldm_x4(r4, bb + ((uint32_t)(row * PAD + col) << 1));
                bf[j][0] = r4[0]; bf[j][1] = r4[1];
                bf[j + 1][0] = r4[2]; bf[j + 1][1] = r4[3];
            }
#pragma unroll
            for (int i = 0; i < MF; i++)
#pragma unroll
                for (int j = 0; j < NF; j++)
                    mma_f16(acc[i][j], af[i], bf[j]);
        }
    };

    const int ktiles = K / BK;

    if constexpr (STAGES == 1) {
        for (int kt = 0; kt < ktiles; kt++) {
            ldgsts(kt, 0);
            CP_COMMIT();
            CP_WAIT0();
            __syncthreads();
            compute(0);
            if (kt + 1 < ktiles) __syncthreads();
        }
    } else {
        // 3-stage: one barrier per k-tile.
        ldgsts(0, 0);
        CP_COMMIT();
        if (ktiles > 1) ldgsts(1, 1);
        CP_COMMIT();
        for (int kt = 0; kt < ktiles; kt++) {
            if (kt + 1 < ktiles) { CP_WAIT1(); } else { CP_WAIT0(); }
            __syncthreads();
            if (kt + 2 < ktiles) ldgsts(kt + 2, (kt + 2) % 3);
            CP_COMMIT();
            compute(kt % 3);
        }
    }

    // Epilogue
#pragma unroll
    for (int i = 0; i < MF; i++) {
        int r0 = m0 + warpM * WM + i * 16 + lr;
#pragma unroll
        for (int j = 0; j < NF; j++) {
            int c0 = n0 + warpN * WN + j * 8 + 2 * lc;
            float2 bv = bias ? *(const float2*)(bias + c0) : make_float2(0.f, 0.f);
            float x0 = acc[i][j][0] * alpha + bv.x;
            float x1 = acc[i][j][1] * alpha + bv.y;
            float x2 = acc[i][j][2] * alpha + bv.x;
            float x3 = acc[i][j][3] * alpha + bv.y;
            if constexpr (C_HALF) {
                __half* C = (__half*)Cp;
                *(__half2*)(C + (size_t)r0 * ldc + c0) = __floats2half2_rn(x0, x1);
                *(__half2*)(C + (size_t)(r0 + 8) * ldc + c0) = __floats2half2_rn(x2, x3);
            } else {
                float* C = (float*)Cp;
                *(float2*)(C + (size_t)r0 * ldc + c0) = make_float2(x0, x1);
                *(float2*)(C + (size_t)(r0 + 8) * ldc + c0) = make_float2(x2, x3);
            }
        }
    }
}

// ---------------- GEMM wrappers ----------------
// Batched q/k/v projection: blockIdx.z selects the triple.
__global__ void __launch_bounds__(256) k_proj3(
    const __half* __restrict__ xq, const __half* __restrict__ xk, const __half* __restrict__ xv,
    const __half* __restrict__ wq, const __half* __restrict__ wk, const __half* __restrict__ wv,
    const float* __restrict__ bq, const float* __restrict__ bk, const float* __restrict__ bv,
    __half* __restrict__ qh, __half* __restrict__ kh, __half* __restrict__ vh)
{
    const __half* A; const __half* W; const float* bias; __half* C;
    if (blockIdx.z == 0)      { A = xq; W = wq; bias = bq; C = qh; }
    else if (blockIdx.z == 1) { A = xk; W = wk; bias = bk; C = kh; }
    else                      { A = xv; W = wv; bias = bv; C = vh; }
    mm_core<128, 2, 4, true, 3>(A, E_DIM, W, E_DIM, C, E_DIM, bias, 1.f, E_DIM);
}

__global__ void __launch_bounds__(256) k_proj_f(
    const __half* __restrict__ A, const __half* __restrict__ W,
    const float* __restrict__ bias, float* __restrict__ C)
{
    mm_core<128, 2, 4, false, 3>(A, E_DIM, W, E_DIM, C, E_DIM, bias, 1.f, E_DIM);
}

__global__ void __launch_bounds__(256) k_scores(
    const __half* __restrict__ q, const __half* __restrict__ k, float* __restrict__ sc)
{
    int z = blockIdx.z;
    int b = z >> 4, h = z & 15;
    const __half* A = q + (size_t)b * E_DIM + h * HD_DIM;
    const __half* B = k + (size_t)b * E_DIM + h * HD_DIM;
    float* C = sc + (size_t)z * T_DIM * S_DIM;
    mm_core<128, 2, 4, false, 1>(A, LDQ, B, LDQ, C, S_DIM, nullptr, 0.125f, HD_DIM);
}

__global__ void __launch_bounds__(256) k_av(
    const __half* __restrict__ attn, const __half* __restrict__ vt, __half* __restrict__ ctx)
{
    int z = blockIdx.z;
    int b = z >> 4, h = z & 15;
    const __half* A = attn + (size_t)z * T_DIM * S_DIM;
    const __half* B = vt + (size_t)z * HD_DIM * S_DIM;
    __half* C = ctx + (size_t)b * E_DIM + h * HD_DIM;
    mm_core<64, 4, 2, true, 3>(A, S_DIM, B, S_DIM, C, LDQ, nullptr, 1.f, S_DIM);
}

// ---------------- batched fp32 -> fp16 converts ----------------
__global__ void __launch_bounds__(256) k_cvt_in(
    const float* __restrict__ a, const float* __restrict__ b, const float* __restrict__ c,
    __half* __restrict__ oa, __half* __restrict__ ob, __half* __restrict__ oc, int n)
{
    const float* x; __half* y;
    if (blockIdx.z == 0)      { x = a; y = oa; }
    else if (blockIdx.z == 1) { x = b; y = ob; }
    else                      { x = c; y = oc; }
    int i = (blockIdx.x * 256 + threadIdx.x) * 8;
    if (i < n) {
        float4 v0 = *(const float4*)(x + i);
        float4 v1 = *(const float4*)(x + i + 4);
        union { __half2 h[4]; uint4 u; } p;
        p.h[0] = __floats2half2_rn(v0.x, v0.y);
        p.h[1] = __floats2half2_rn(v0.z, v0.w);
        p.h[2] = __floats2half2_rn(v1.x, v1.y);
        p.h[3] = __floats2half2_rn(v1.z, v1.w);
        *(uint4*)(y + i) = p.u;
    }
}

__global__ void __launch_bounds__(256) k_cvt_w(
    const float* __restrict__ a, const float* __restrict__ b,
    const float* __restrict__ c, const float* __restrict__ d,
    __half* __restrict__ oa, __half* __restrict__ ob,
    __half* __restrict__ oc, __half* __restrict__ od, int n)
{
    const float* x; __half* y;
    if (blockIdx.z == 0)      { x = a; y = oa; }
    else if (blockIdx.z == 1) { x = b; y = ob; }
    else if (blockIdx.z == 2) { x = c; y = oc; }
    else                      { x = d; y = od; }
    int i = (blockIdx.x * 256 + threadIdx.x) * 8;
    if (i < n) {
        float4 v0 = *(const float4*)(x + i);
        float4 v1 = *(const float4*)(x + i + 4);
        union { __half2 h[4]; uint4 u; } p;
        p.h[0] = __floats2half2_rn(v0.x, v0.y);
        p.h[1] = __floats2half2_rn(v0.z, v0.w);
        p.h[2] = __floats2half2_rn(v1.x, v1.y);
        p.h[3] = __floats2half2_rn(v1.z, v1.w);
        *(uint4*)(y + i) = p.u;
    }
}

// V transpose fp16: vt[(z*64+d)*S + s] = vh[(s*2+b)*E + h*64+d]
__global__ void __launch_bounds__(256) k_transpose_v(
    const __half* __restrict__ v, __half* __restrict__ vt)
{
    __shared__ __half t[32][34];
    int z = blockIdx.z, b = z >> 4, h = z & 15;
    int s0 = blockIdx.x * 32, d0 = blockIdx.y * 32;
    int lx = threadIdx.x & 31, ly = threadIdx.x >> 5;
#pragma unroll
    for (int i = 0; i < 32; i += 8) {
        int s = s0 + ly + i;
        t[ly + i][lx] = v[(size_t)(s * B_DIM + b) * E_DIM + h * HD_DIM + d0 + lx];
    }
    __syncthreads();
#pragma unroll
    for (int i = 0; i < 32; i += 8) {
        int d = d0 + ly + i;
        vt[((size_t)z * HD_DIM + d) * S_DIM + s0 + lx] = t[lx][ly + i];
    }
}

// ---------------- softmax + head-average ----------------
__global__ void __launch_bounds__(256) softmax_avg(
    const float* __restrict__ scores, __half* __restrict__ attn,
    float* __restrict__ avgw)
{
    const int t = blockIdx.x;
    const int b = blockIdx.y;
    const int tid = threadIdx.x;
    __shared__ float red[8];

    float avg[8];
#pragma unroll
    for (int i = 0; i < 8; i++) avg[i] = 0.f;

    for (int h = 0; h < H_DIM; h++) {
        const size_t roff = (((size_t)(b * H_DIM + h)) * T_DIM + t) * S_DIM;
        const float* row = scores + roff;
        __half* orow = attn + roff;
        float v[8];
        float m = -1e30f;
#pragma unroll
        for (int i = 0; i < 8; i++) {
            v[i] = row[tid + i * 256];
            m = fmaxf(m, v[i]);
        }
#pragma unroll
        for (int o = 16; o; o >>= 1) m = fmaxf(m, __shfl_xor_sync(0xffffffffu, m, o));
        if ((tid & 31) == 0) red[tid >> 5] = m;
        __syncthreads();
        float M = red[0];
#pragma unroll
        for (int i = 1; i < 8; i++) M = fmaxf(M, red[i]);
        __syncthreads();

        float s = 0.f;
#pragma unroll
        for (int i = 0; i < 8; i++) {
            v[i] = __expf(v[i] - M);
            s += v[i];
        }
#pragma unroll
        for (int o = 16; o; o >>= 1) s += __shfl_xor_sync(0xffffffffu, s, o);
        if ((tid & 31) == 0) red[tid >> 5] = s;
        __syncthreads();
        float Z = red[0];
#pragma unroll
        for (int i = 1; i < 8; i++) Z += red[i];
        const float inv = 1.f / Z;
#pragma unroll
        for (int i = 0; i < 8; i++) {
            v[i] *= inv;
            orow[tid + i * 256] = __float2half_rn(v[i]);
            avg[i] += v[i];
        }
        __syncthreads();
    }

    float* arow = avgw + ((size_t)b * T_DIM + t) * S_DIM;
    const float invH = 1.f / (float)H_DIM;
#pragma unroll
    for (int i = 0; i < 8; i++) arow[tid + i * 256] = avg[i] * invH;
}

// ---------------------------------------------------------------------------
extern "C" void kernel_launch(void* const* d_in, const int* in_sizes, int n_in,
                              void* d_out, int out_size)
{
    const float* query = (const float*)d_in[0];
    const float* key   = (const float*)d_in[1];
    const float* value = (const float*)d_in[2];
    const float* Wq = (const float*)d_in[3];
    const float* bq = (const float*)d_in[4];
    const float* Wk = (const float*)d_in[5];
    const float* bk = (const float*)d_in[6];
    const float* Wv = (const float*)d_in[7];
    const float* bv = (const float*)d_in[8];
    const float* Wo = (const float*)d_in[9];
    const float* bo = (const float*)d_in[10];

    float* out  = (float*)d_out;
    float* avgw = out + (size_t)MB_DIM * E_DIM;

    __half *xq, *xk, *xv, *wq, *wk, *wv, *wo, *qh, *kh, *vh, *ctxh, *vt, *attn;
    float *sc;
    cudaGetSymbolAddress((void**)&xq,   g_xq);
    cudaGetSymbolAddress((void**)&xk,   g_xk);
    cudaGetSymbolAddress((void**)&xv,   g_xv);
    cudaGetSymbolAddress((void**)&wq,   g_wq);
    cudaGetSymbolAddress((void**)&wk,   g_wk);
    cudaGetSymbolAddress((void**)&wv,   g_wv);
    cudaGetSymbolAddress((void**)&wo,   g_wo);
    cudaGetSymbolAddress((void**)&qh,   g_qh);
    cudaGetSymbolAddress((void**)&kh,   g_kh);
    cudaGetSymbolAddress((void**)&vh,   g_vh);
    cudaGetSymbolAddress((void**)&ctxh, g_ctxh);
    cudaGetSymbolAddress((void**)&vt,   g_vt);
    cudaGetSymbolAddress((void**)&attn, g_attn);
    cudaGetSymbolAddress((void**)&sc,   g_scores);

    // smem: stage = (BM + BN) * 72 * 2 bytes
    const int SM_P3 = 3 * (128 + 128) * 72 * 2;   // 110592
    const int SM_SC = 1 * (128 + 128) * 72 * 2;   // 36864
    const int SM_AV = 3 * (128 + 64) * 72 * 2;    // 82944
    cudaFuncSetAttribute(k_proj3,  cudaFuncAttributeMaxDynamicSharedMemorySize, SM_P3);
    cudaFuncSetAttribute(k_proj_f, cudaFuncAttributeMaxDynamicSharedMemorySize, SM_P3);
    cudaFuncSetAttribute(k_scores, cudaFuncAttributeMaxDynamicSharedMemorySize, SM_SC);
    cudaFuncSetAttribute(k_av,     cudaFuncAttributeMaxDynamicSharedMemorySize, SM_AV);

    const int NXE = MB_DIM * E_DIM;   // 4M
    const int NWW = E_DIM * E_DIM;    // 1M
    dim3 gci(NXE / 2048, 1, 3);
    k_cvt_in<<<gci, 256>>>(query, key, value, xq, xk, xv, NXE);
    dim3 gcw(NWW / 2048, 1, 4);
    k_cvt_w<<<gcw, 256>>>(Wq, Wk, Wv, Wo, wq, wk, wv, wo, NWW);

    dim3 gp3(E_DIM / 128, MB_DIM / 128, 3);             // (8, 32, 3)
    k_proj3<<<gp3, 256, SM_P3>>>(xq, xk, xv, wq, wk, wv, bq, bk, bv, qh, kh, vh);

    dim3 gt(S_DIM / 32, HD_DIM / 32, B_DIM * H_DIM);    // (64, 2, 32)
    k_transpose_v<<<gt, 256>>>(vh, vt);

    dim3 gs(S_DIM / 128, T_DIM / 128, B_DIM * H_DIM);   // (16, 16, 32)
    k_scores<<<gs, 256, SM_SC>>>(qh, kh, sc);

    dim3 gm(T_DIM, B_DIM);                              // (2048, 2)
    softmax_avg<<<gm, 256>>>(sc, attn, avgw);

    dim3 ga(1, T_DIM / 128, B_DIM * H_DIM);             // (1, 16, 32)
    k_av<<<ga, 256, SM_AV>>>(attn, vt, ctxh);

    dim3 gp(E_DIM / 128, MB_DIM / 128);                 // (8, 32)
    k_proj_f<<<gp, 256, SM_P3>>>(ctxh, wo, bo, out);
}

// round 8
// speedup vs baseline: 1.4585x; 1.1246x over previous
#include <cuda_runtime.h>
#include <cuda_fp16.h>
#include <cstdint>

#define T_DIM 2048
#define B_DIM 2
#define E_DIM 1024
#define H_DIM 16
#define HD_DIM 64
#define S_DIM 2048
#define MB_DIM (T_DIM * B_DIM)     // 4096
#define LDQ (B_DIM * E_DIM)        // 2048

// Static device scratch
__device__ __half g_xq[(size_t)MB_DIM * E_DIM];
__device__ __half g_xk[(size_t)MB_DIM * E_DIM];
__device__ __half g_xv[(size_t)MB_DIM * E_DIM];
__device__ __half g_wq[(size_t)E_DIM * E_DIM];
__device__ __half g_wk[(size_t)E_DIM * E_DIM];
__device__ __half g_wv[(size_t)E_DIM * E_DIM];
__device__ __half g_wo[(size_t)E_DIM * E_DIM];
__device__ __half g_qh[(size_t)MB_DIM * E_DIM];
__device__ __half g_kh[(size_t)MB_DIM * E_DIM];
__device__ __half g_vh[(size_t)MB_DIM * E_DIM];
__device__ __half g_ctxh[(size_t)MB_DIM * E_DIM];
__device__ __half g_vt[(size_t)B_DIM * H_DIM * HD_DIM * S_DIM];
__device__ __half g_ptil[(size_t)B_DIM * H_DIM * T_DIM * S_DIM];  // unnormalized exp scores
__device__ float  g_zinv[(size_t)B_DIM * H_DIM * T_DIM];          // per-row 1/Z

__device__ __forceinline__ uint32_t smem_u32(const void* p) {
    uint32_t a;
    asm("{ .reg .u64 t; cvta.to.shared.u64 t, %1; cvt.u32.u64 %0, t; }" : "=r"(a) : "l"(p));
    return a;
}
__device__ __forceinline__ void cp16(uint32_t dst, const void* src) {
    asm volatile("cp.async.ca.shared.global [%0], [%1], 16;" :: "r"(dst), "l"(src) : "memory");
}
#define CP_COMMIT() asm volatile("cp.async.commit_group;" ::: "memory")
#define CP_WAIT1()  asm volatile("cp.async.wait_group 1;" ::: "memory")
#define CP_WAIT0()  asm volatile("cp.async.wait_group 0;" ::: "memory")

__device__ __forceinline__ void ldm_x4(uint32_t r[4], uint32_t a) {
    asm volatile("ldmatrix.sync.aligned.m8n8.x4.shared.b16 {%0,%1,%2,%3}, [%4];"
        : "=r"(r[0]), "=r"(r[1]), "=r"(r[2]), "=r"(r[3]) : "r"(a));
}
__device__ __forceinline__ void mma_f16(float c[4], const uint32_t a[4], const uint32_t b[2]) {
    asm volatile(
        "mma.sync.aligned.m16n8k16.row.col.f32.f16.f16.f32 "
        "{%0,%1,%2,%3}, {%4,%5,%6,%7}, {%8,%9}, {%0,%1,%2,%3};"
        : "+f"(c[0]), "+f"(c[1]), "+f"(c[2]), "+f"(c[3])
        : "r"(a[0]), "r"(a[1]), "r"(a[2]), "r"(a[3]), "r"(b[0]), "r"(b[1]));
}

// ---------------------------------------------------------------------------
// fp16 mma.sync GEMM core, cp.async multi-stage pipeline (1 sync per k-tile).
// C[m][n] = op( alpha * sum_k A[m][k]*B[n][k] ) per CMODE:
//   CMODE 0: fp32 out (+bias)
//   CMODE 1: fp16 out (+bias), optional per-row scale (rowscale[m])
//   CMODE 2: fp16 out = expf(alpha * acc)
// ---------------------------------------------------------------------------
template <int BN, int WARPS_M, int WARPS_N, int CMODE, int STAGES>
__device__ __forceinline__ void mm_core(
    const __half* __restrict__ A, int lda,
    const __half* __restrict__ B, int ldb,
    void* Cp, int ldc,
    const float* __restrict__ bias, const float* __restrict__ rowscale,
    float alpha, int K)
{
    constexpr int BM = 128, BK = 64, PAD = 72;
    constexpr int WM = BM / WARPS_M, WN = BN / WARPS_N;
    constexpr int MF = WM / 16, NF = WN / 8;
    constexpr int NCA = (BM * BK / 8) / 256;
    constexpr int NCB = (BN * BK / 8) / 256;
    constexpr uint32_t ASTG = BM * PAD * 2;
    constexpr uint32_t BSTG = BN * PAD * 2;
    constexpr uint32_t STG  = ASTG + BSTG;

    extern __shared__ __align__(16) char dsm[];

    const int tid = threadIdx.x;
    const int wid = tid >> 5;
    const int lane = tid & 31;
    const int lr = lane >> 2;
    const int lc = lane & 3;
    const int warpM = wid % WARPS_M;
    const int warpN = wid / WARPS_M;
    const int m0 = blockIdx.y * BM;
    const int n0 = blockIdx.x * BN;

    const uint32_t smb = smem_u32(dsm);

    float acc[MF][NF][4];
#pragma unroll
    for (int i = 0; i < MF; i++)
#pragma unroll
        for (int j = 0; j < NF; j++)
#pragma unroll
            for (int q = 0; q < 4; q++) acc[i][j][q] = 0.f;

    auto ldgsts = [&](int kt, int p) {
        const int k0 = kt * BK;
        const uint32_t ab = smb + (uint32_t)p * STG;
        const uint32_t bb = ab + ASTG;
#pragma unroll
        for (int i = 0; i < NCA; i++) {
            int ch = tid + i * 256, r = ch >> 3, c = (ch & 7) * 8;
            cp16(ab + (uint32_t)(r * PAD + c) * 2,
                 A + (size_t)(m0 + r) * lda + k0 + c);
        }
#pragma unroll
        for (int i = 0; i < NCB; i++) {
            int ch = tid + i * 256, r = ch >> 3, c = (ch & 7) * 8;
            cp16(bb + (uint32_t)(r * PAD + c) * 2,
                 B + (size_t)(n0 + r) * ldb + k0 + c);
        }
    };

    auto compute = [&](int p) {
        const uint32_t ab = smb + (uint32_t)p * STG;
        const uint32_t bb = ab + ASTG;
#pragma unroll
        for (int ks = 0; ks < BK / 16; ks++) {
            const int kh = ks * 16;
            uint32_t af[MF][4], bf[NF][2];
#pragma unroll
            for (int i = 0; i < MF; i++) {
                uint32_t off = (uint32_t)((warpM * WM + i * 16 + (lane & 15)) * PAD +
                                          kh + ((lane >> 4) << 3));
                ldm_x4(af[i], ab + (off << 1));
            }
#pragma unroll
            for (int j = 0; j < NF; j += 2) {
                int row = warpN * WN + (j + (lane >> 4)) * 8 + (lane & 7);
                int col = kh + ((lane >> 3) & 1) * 8;
                uint32_t r4[4];
                ldm_x4(r4, bb + ((uint32_t)(row * PAD + col) << 1));
                bf[j][0] = r4[0]; bf[j][1] = r4[1];
                bf[j + 1][0] = r4[2]; bf[j + 1][1] = r4[3];
            }
#pragma unroll
            for (int i = 0; i < MF; i++)
#pragma unroll
                for (int j = 0; j < NF; j++)
                    mma_f16(acc[i][j], af[i], bf[j]);
        }
    };

    const int ktiles = K / BK;

    if constexpr (STAGES == 1) {
        for (int kt = 0; kt < ktiles; kt++) {
            ldgsts(kt, 0);
            CP_COMMIT();
            CP_WAIT0();
            __syncthreads();
            compute(0);
            if (kt + 1 < ktiles) __syncthreads();
        }
    } else {
        ldgsts(0, 0);
        CP_COMMIT();
        if (ktiles > 1) ldgsts(1, 1);
        CP_COMMIT();
        for (int kt = 0; kt < ktiles; kt++) {
            if (kt + 1 < ktiles) { CP_WAIT1(); } else { CP_WAIT0(); }
            __syncthreads();
            if (kt + 2 < ktiles) ldgsts(kt + 2, (kt + 2) % 3);
            CP_COMMIT();
            compute(kt % 3);
        }
    }

    // Epilogue
#pragma unroll
    for (int i = 0; i < MF; i++) {
        int r0 = m0 + warpM * WM + i * 16 + lr;
        float rs0 = 1.f, rs1 = 1.f;
        if constexpr (CMODE == 1) {
            if (rowscale) { rs0 = __ldg(rowscale + r0); rs1 = __ldg(rowscale + r0 + 8); }
        }
#pragma unroll
        for (int j = 0; j < NF; j++) {
            int c0 = n0 + warpN * WN + j * 8 + 2 * lc;
            if constexpr (CMODE == 2) {
                __half* C = (__half*)Cp;
                float x0 = __expf(acc[i][j][0] * alpha);
                float x1 = __expf(acc[i][j][1] * alpha);
                float x2 = __expf(acc[i][j][2] * alpha);
                float x3 = __expf(acc[i][j][3] * alpha);
                *(__half2*)(C + (size_t)r0 * ldc + c0) = __floats2half2_rn(x0, x1);
                *(__half2*)(C + (size_t)(r0 + 8) * ldc + c0) = __floats2half2_rn(x2, x3);
            } else {
                float2 bv = bias ? *(const float2*)(bias + c0) : make_float2(0.f, 0.f);
                float x0 = acc[i][j][0] * alpha * rs0 + bv.x;
                float x1 = acc[i][j][1] * alpha * rs0 + bv.y;
                float x2 = acc[i][j][2] * alpha * rs1 + bv.x;
                float x3 = acc[i][j][3] * alpha * rs1 + bv.y;
                if constexpr (CMODE == 1) {
                    __half* C = (__half*)Cp;
                    *(__half2*)(C + (size_t)r0 * ldc + c0) = __floats2half2_rn(x0, x1);
                    *(__half2*)(C + (size_t)(r0 + 8) * ldc + c0) = __floats2half2_rn(x2, x3);
                } else {
                    float* C = (float*)Cp;
                    *(float2*)(C + (size_t)r0 * ldc + c0) = make_float2(x0, x1);
                    *(float2*)(C + (size_t)(r0 + 8) * ldc + c0) = make_float2(x2, x3);
                }
            }
        }
    }
}

// ---------------- GEMM wrappers ----------------
__global__ void __launch_bounds__(256) k_proj3(
    const __half* __restrict__ xq, const __half* __restrict__ xk, const __half* __restrict__ xv,
    const __half* __restrict__ wq, const __half* __restrict__ wk, const __half* __restrict__ wv,
    const float* __restrict__ bq, const float* __restrict__ bk, const float* __restrict__ bv,
    __half* __restrict__ qh, __half* __restrict__ kh, __half* __restrict__ vh)
{
    const __half* A; const __half* W; const float* bias; __half* C;
    if (blockIdx.z == 0)      { A = xq; W = wq; bias = bq; C = qh; }
    else if (blockIdx.z == 1) { A = xk; W = wk; bias = bk; C = kh; }
    else                      { A = xv; W = wv; bias = bv; C = vh; }
    mm_core<128, 2, 4, 1, 3>(A, E_DIM, W, E_DIM, C, E_DIM, bias, nullptr, 1.f, E_DIM);
}

__global__ void __launch_bounds__(256) k_proj_f(
    const __half* __restrict__ A, const __half* __restrict__ W,
    const float* __restrict__ bias, float* __restrict__ C)
{
    mm_core<128, 2, 4, 0, 3>(A, E_DIM, W, E_DIM, C, E_DIM, bias, nullptr, 1.f, E_DIM);
}

// scores -> exp(0.125 * qk) as fp16 (unnormalized probs)
__global__ void __launch_bounds__(256) k_scores_exp(
    const __half* __restrict__ q, const __half* __restrict__ k, __half* __restrict__ pt)
{
    int z = blockIdx.z;
    int b = z >> 4, h = z & 15;
    const __half* A = q + (size_t)b * E_DIM + h * HD_DIM;
    const __half* B = k + (size_t)b * E_DIM + h * HD_DIM;
    __half* C = pt + (size_t)z * T_DIM * S_DIM;
    mm_core<128, 2, 4, 2, 1>(A, LDQ, B, LDQ, C, S_DIM, nullptr, nullptr, 0.125f, HD_DIM);
}

// ctx = (ptil @ V) * zinv[row]
__global__ void __launch_bounds__(256) k_av(
    const __half* __restrict__ ptil, const __half* __restrict__ vt,
    const float* __restrict__ zinv, __half* __restrict__ ctx)
{
    int z = blockIdx.z;
    int b = z >> 4, h = z & 15;
    const __half* A = ptil + (size_t)z * T_DIM * S_DIM;
    const __half* B = vt + (size_t)z * HD_DIM * S_DIM;
    __half* C = ctx + (size_t)b * E_DIM + h * HD_DIM;
    mm_core<64, 4, 2, 1, 3>(A, S_DIM, B, S_DIM, C, LDQ, nullptr,
                            zinv + (size_t)z * T_DIM, 1.f, S_DIM);
}

// ---------------- batched fp32 -> fp16 converts ----------------
__global__ void __launch_bounds__(256) k_cvt_in(
    const float* __restrict__ a, const float* __restrict__ b, const float* __restrict__ c,
    __half* __restrict__ oa, __half* __restrict__ ob, __half* __restrict__ oc, int n)
{
    const float* x; __half* y;
    if (blockIdx.z == 0)      { x = a; y = oa; }
    else if (blockIdx.z == 1) { x = b; y = ob; }
    else                      { x = c; y = oc; }
    int i = (blockIdx.x * 256 + threadIdx.x) * 8;
    if (i < n) {
        float4 v0 = *(const float4*)(x + i);
        float4 v1 = *(const float4*)(x + i + 4);
        union { __half2 h[4]; uint4 u; } p;
        p.h[0] = __floats2half2_rn(v0.x, v0.y);
        p.h[1] = __floats2half2_rn(v0.z, v0.w);
        p.h[2] = __floats2half2_rn(v1.x, v1.y);
        p.h[3] = __floats2half2_rn(v1.z, v1.w);
        *(uint4*)(y + i) = p.u;
    }
}

__global__ void __launch_bounds__(256) k_cvt_w(
    const float* __restrict__ a, const float* __restrict__ b,
    const float* __restrict__ c, const float* __restrict__ d,
    __half* __restrict__ oa, __half* __restrict__ ob,
    __half* __restrict__ oc, __half* __restrict__ od, int n)
{
    const float* x; __half* y;
    if (blockIdx.z == 0)      { x = a; y = oa; }
    else if (blockIdx.z == 1) { x = b; y = ob; }
    else if (blockIdx.z == 2) { x = c; y = oc; }
    else                      { x = d; y = od; }
    int i = (blockIdx.x * 256 + threadIdx.x) * 8;
    if (i < n) {
        float4 v0 = *(const float4*)(x + i);
        float4 v1 = *(const float4*)(x + i + 4);
        union { __half2 h[4]; uint4 u; } p;
        p.h[0] = __floats2half2_rn(v0.x, v0.y);
        p.h[1] = __floats2half2_rn(v0.z, v0.w);
        p.h[2] = __floats2half2_rn(v1.x, v1.y);
        p.h[3] = __floats2half2_rn(v1.z, v1.w);
        *(uint4*)(y + i) = p.u;
    }
}

// V transpose fp16: vt[(z*64+d)*S + s] = vh[(s*2+b)*E + h*64+d]
__global__ void __launch_bounds__(256) k_transpose_v(
    const __half* __restrict__ v, __half* __restrict__ vt)
{
    __shared__ __half t[32][34];
    int z = blockIdx.z, b = z >> 4, h = z & 15;
    int s0 = blockIdx.x * 32, d0 = blockIdx.y * 32;
    int lx = threadIdx.x & 31, ly = threadIdx.x >> 5;
#pragma unroll
    for (int i = 0; i < 32; i += 8) {
        int s = s0 + ly + i;
        t[ly + i][lx] = v[(size_t)(s * B_DIM + b) * E_DIM + h * HD_DIM + d0 + lx];
    }
    __syncthreads();
#pragma unroll
    for (int i = 0; i < 32; i += 8) {
        int d = d0 + ly + i;
        vt[((size_t)z * HD_DIM + d) * S_DIM + s0 + lx] = t[lx][ly + i];
    }
}

// ---------------- row-sum + head-average from unnormalized probs ----------------
// Per (t, b): for each head, Z = sum_s ptil; writes zinv table and avgw.
__global__ void __launch_bounds__(256) k_sumavg(
    const __half* __restrict__ ptil, float* __restrict__ zinv,
    float* __restrict__ avgw)
{
    const int t = blockIdx.x;
    const int b = blockIdx.y;
    const int tid = threadIdx.x;
    __shared__ float red[8];

    float2 avg[4];
#pragma unroll
    for (int i = 0; i < 4; i++) avg[i] = make_float2(0.f, 0.f);

    for (int h = 0; h < H_DIM; h++) {
        const __half* row = ptil + (((size_t)(b * H_DIM + h)) * T_DIM + t) * S_DIM;
        float2 v[4];
        float s = 0.f;
#pragma unroll
        for (int i = 0; i < 4; i++) {
            __half2 hv = *(const __half2*)(row + 2 * (tid + i * 256));
            v[i] = __half22float2(hv);
            s += v[i].x + v[i].y;
        }
#pragma unroll
        for (int o = 16; o; o >>= 1) s += __shfl_xor_sync(0xffffffffu, s, o);
        if ((tid & 31) == 0) red[tid >> 5] = s;
        __syncthreads();
        float Z = red[0];
#pragma unroll
        for (int i = 1; i < 8; i++) Z += red[i];
        const float inv = 1.f / Z;
        if (tid == 0) zinv[((size_t)(b * H_DIM + h)) * T_DIM + t] = inv;
#pragma unroll
        for (int i = 0; i < 4; i++) {
            avg[i].x += v[i].x * inv;
            avg[i].y += v[i].y * inv;
        }
        __syncthreads();
    }

    float* arow = avgw + ((size_t)b * T_DIM + t) * S_DIM;
    const float invH = 1.f / (float)H_DIM;
#pragma unroll
    for (int i = 0; i < 4; i++) {
        *(float2*)(arow + 2 * (tid + i * 256)) =
            make_float2(avg[i].x * invH, avg[i].y * invH);
    }
}

// ---------------------------------------------------------------------------
extern "C" void kernel_launch(void* const* d_in, const int* in_sizes, int n_in,
                              void* d_out, int out_size)
{
    const float* query = (const float*)d_in[0];
    const float* key   = (const float*)d_in[1];
    const float* value = (const float*)d_in[2];
    const float* Wq = (const float*)d_in[3];
    const float* bq = (const float*)d_in[4];
    const float* Wk = (const float*)d_in[5];
    const float* bk = (const float*)d_in[6];
    const float* Wv = (const float*)d_in[7];
    const float* bv = (const float*)d_in[8];
    const float* Wo = (const float*)d_in[9];
    const float* bo = (const float*)d_in[10];

    float* out  = (float*)d_out;
    float* avgw = out + (size_t)MB_DIM * E_DIM;

    __half *xq, *xk, *xv, *wq, *wk, *wv, *wo, *qh, *kh, *vh, *ctxh, *vt, *pt;
    float *zi;
    cudaGetSymbolAddress((void**)&xq,   g_xq);
    cudaGetSymbolAddress((void**)&xk,   g_xk);
    cudaGetSymbolAddress((void**)&xv,   g_xv);
    cudaGetSymbolAddress((void**)&wq,   g_wq);
    cudaGetSymbolAddress((void**)&wk,   g_wk);
    cudaGetSymbolAddress((void**)&wv,   g_wv);
    cudaGetSymbolAddress((void**)&wo,   g_wo);
    cudaGetSymbolAddress((void**)&qh,   g_qh);
    cudaGetSymbolAddress((void**)&kh,   g_kh);
    cudaGetSymbolAddress((void**)&vh,   g_vh);
    cudaGetSymbolAddress((void**)&ctxh, g_ctxh);
    cudaGetSymbolAddress((void**)&vt,   g_vt);
    cudaGetSymbolAddress((void**)&pt,   g_ptil);
    cudaGetSymbolAddress((void**)&zi,   g_zinv);

    const int SM_P3 = 3 * (128 + 128) * 72 * 2;   // 110592
    const int SM_SC = 1 * (128 + 128) * 72 * 2;   // 36864
    const int SM_AV = 3 * (128 + 64) * 72 * 2;    // 82944
    cudaFuncSetAttribute(k_proj3,      cudaFuncAttributeMaxDynamicSharedMemorySize, SM_P3);
    cudaFuncSetAttribute(k_proj_f,     cudaFuncAttributeMaxDynamicSharedMemorySize, SM_P3);
    cudaFuncSetAttribute(k_scores_exp, cudaFuncAttributeMaxDynamicSharedMemorySize, SM_SC);
    cudaFuncSetAttribute(k_av,         cudaFuncAttributeMaxDynamicSharedMemorySize, SM_AV);

    const int NXE = MB_DIM * E_DIM;   // 4M
    const int NWW = E_DIM * E_DIM;    // 1M
    dim3 gci(NXE / 2048, 1, 3);
    k_cvt_in<<<gci, 256>>>(query, key, value, xq, xk, xv, NXE);
    dim3 gcw(NWW / 2048, 1, 4);
    k_cvt_w<<<gcw, 256>>>(Wq, Wk, Wv, Wo, wq, wk, wv, wo, NWW);

    dim3 gp3(E_DIM / 128, MB_DIM / 128, 3);             // (8, 32, 3)
    k_proj3<<<gp3, 256, SM_P3>>>(xq, xk, xv, wq, wk, wv, bq, bk, bv, qh, kh, vh);

    dim3 gt(S_DIM / 32, HD_DIM / 32, B_DIM * H_DIM);    // (64, 2, 32)
    k_transpose_v<<<gt, 256>>>(vh, vt);

    dim3 gs(S_DIM / 128, T_DIM / 128, B_DIM * H_DIM);   // (16, 16, 32)
    k_scores_exp<<<gs, 256, SM_SC>>>(qh, kh, pt);

    dim3 gm(T_DIM, B_DIM);                              // (2048, 2)
    k_sumavg<<<gm, 256>>>(pt, zi, avgw);

    dim3 ga(1, T_DIM / 128, B_DIM * H_DIM);             // (1, 16, 32)
    k_av<<<ga, 256, SM_AV>>>(pt, vt, zi, ctxh);

    dim3 gp(E_DIM / 128, MB_DIM / 128);                 // (8, 32)
    k_proj_f<<<gp, 256, SM_P3>>>(ctxh, wo, bo, out);
}

// round 9
// speedup vs baseline: 1.4996x; 1.0282x over previous
#include <cuda_runtime.h>
#include <cuda_fp16.h>
#include <cstdint>

#define T_DIM 2048
#define B_DIM 2
#define E_DIM 1024
#define H_DIM 16
#define HD_DIM 64
#define S_DIM 2048
#define MB_DIM (T_DIM * B_DIM)     // 4096
#define LDQ (B_DIM * E_DIM)        // 2048

// Static device scratch
__device__ __half g_xq[(size_t)MB_DIM * E_DIM];
__device__ __half g_xk[(size_t)MB_DIM * E_DIM];
__device__ __half g_xv[(size_t)MB_DIM * E_DIM];
__device__ __half g_wq[(size_t)E_DIM * E_DIM];
__device__ __half g_wk[(size_t)E_DIM * E_DIM];
__device__ __half g_wv[(size_t)E_DIM * E_DIM];
__device__ __half g_wo[(size_t)E_DIM * E_DIM];
__device__ __half g_qh[(size_t)MB_DIM * E_DIM];
__device__ __half g_kh[(size_t)MB_DIM * E_DIM];
__device__ __half g_vh[(size_t)MB_DIM * E_DIM];
__device__ __half g_ctxh[(size_t)MB_DIM * E_DIM];
__device__ __half g_vt[(size_t)B_DIM * H_DIM * HD_DIM * S_DIM];
__device__ __half g_ptil[(size_t)B_DIM * H_DIM * T_DIM * S_DIM];  // unnormalized exp scores
__device__ float  g_zinv[(size_t)B_DIM * H_DIM * T_DIM];          // per-row 1/Z

__device__ __forceinline__ uint32_t smem_u32(const void* p) {
    uint32_t a;
    asm("{ .reg .u64 t; cvta.to.shared.u64 t, %1; cvt.u32.u64 %0, t; }" : "=r"(a) : "l"(p));
    return a;
}
__device__ __forceinline__ void cp16(uint32_t dst, const void* src) {
    asm volatile("cp.async.ca.shared.global [%0], [%1], 16;" :: "r"(dst), "l"(src) : "memory");
}
#define CP_COMMIT() asm volatile("cp.async.commit_group;" ::: "memory")
#define CP_WAIT1()  asm volatile("cp.async.wait_group 1;" ::: "memory")
#define CP_WAIT0()  asm volatile("cp.async.wait_group 0;" ::: "memory")

__device__ __forceinline__ void ldm_x4(uint32_t r[4], uint32_t a) {
    asm volatile("ldmatrix.sync.aligned.m8n8.x4.shared.b16 {%0,%1,%2,%3}, [%4];"
        : "=r"(r[0]), "=r"(r[1]), "=r"(r[2]), "=r"(r[3]) : "r"(a));
}
__device__ __forceinline__ void mma_f16(float c[4], const uint32_t a[4], const uint32_t b[2]) {
    asm volatile(
        "mma.sync.aligned.m16n8k16.row.col.f32.f16.f16.f32 "
        "{%0,%1,%2,%3}, {%4,%5,%6,%7}, {%8,%9}, {%0,%1,%2,%3};"
        : "+f"(c[0]), "+f"(c[1]), "+f"(c[2]), "+f"(c[3])
        : "r"(a[0]), "r"(a[1]), "r"(a[2]), "r"(a[3]), "r"(b[0]), "r"(b[1]));
}

// ---------------------------------------------------------------------------
// fp16 mma.sync GEMM core (projections). CMODE 0: fp32 out; 1: fp16 out.
// ---------------------------------------------------------------------------
template <int BN, int WARPS_M, int WARPS_N, int CMODE, int STAGES>
__device__ __forceinline__ void mm_core(
    const __half* __restrict__ A, int lda,
    const __half* __restrict__ B, int ldb,
    void* Cp, int ldc,
    const float* __restrict__ bias, float alpha, int K)
{
    constexpr int BM = 128, BK = 64, PAD = 72;
    constexpr int WM = BM / WARPS_M, WN = BN / WARPS_N;
    constexpr int MF = WM / 16, NF = WN / 8;
    constexpr int NCA = (BM * BK / 8) / 256;
    constexpr int NCB = (BN * BK / 8) / 256;
    constexpr uint32_t ASTG = BM * PAD * 2;
    constexpr uint32_t BSTG = BN * PAD * 2;
    constexpr uint32_t STG  = ASTG + BSTG;

    extern __shared__ __align__(16) char dsm[];

    const int tid = threadIdx.x;
    const int wid = tid >> 5;
    const int lane = tid & 31;
    const int lr = lane >> 2;
    const int lc = lane & 3;
    const int warpM = wid % WARPS_M;
    const int warpN = wid / WARPS_M;
    const int m0 = blockIdx.y * BM;
    const int n0 = blockIdx.x * BN;

    const uint32_t smb = smem_u32(dsm);

    float acc[MF][NF][4];
#pragma unroll
    for (int i = 0; i < MF; i++)
#pragma unroll
        for (int j = 0; j < NF; j++)
#pragma unroll
            for (int q = 0; q < 4; q++) acc[i][j][q] = 0.f;

    auto ldgsts = [&](int kt, int p) {
        const int k0 = kt * BK;
        const uint32_t ab = smb + (uint32_t)p * STG;
        const uint32_t bb = ab + ASTG;
#pragma unroll
        for (int i = 0; i < NCA; i++) {
            int ch = tid + i * 256, r = ch >> 3, c = (ch & 7) * 8;
            cp16(ab + (uint32_t)(r * PAD + c) * 2,
                 A + (size_t)(m0 + r) * lda + k0 + c);
        }
#pragma unroll
        for (int i = 0; i < NCB; i++) {
            int ch = tid + i * 256, r = ch >> 3, c = (ch & 7) * 8;
            cp16(bb + (uint32_t)(r * PAD + c) * 2,
                 B + (size_t)(n0 + r) * ldb + k0 + c);
        }
    };

    auto compute = [&](int p) {
        const uint32_t ab = smb + (uint32_t)p * STG;
        const uint32_t bb = ab + ASTG;
#pragma unroll
        for (int ks = 0; ks < BK / 16; ks++) {
            const int kh = ks * 16;
            uint32_t af[MF][4], bf[NF][2];
#pragma unroll
            for (int i = 0; i < MF; i++) {
                uint32_t off = (uint32_t)((warpM * WM + i * 16 + (lane & 15)) * PAD +
                                          kh + ((lane >> 4) << 3));
                ldm_x4(af[i], ab + (off << 1));
            }
#pragma unroll
            for (int j = 0; j < NF; j += 2) {
                int row = warpN * WN + (j + (lane >> 4)) * 8 + (lane & 7);
                int col = kh + ((lane >> 3) & 1) * 8;
                uint32_t r4[4];
                ldm_x4(r4, bb + ((uint32_t)(row * PAD + col) << 1));
                bf[j][0] = r4[0]; bf[j][1] = r4[1];
                bf[j + 1][0] = r4[2]; bf[j + 1][1] = r4[3];
            }
#pragma unroll
            for (int i = 0; i < MF; i++)
#pragma unroll
                for (int j = 0; j < NF; j++)
                    mma_f16(acc[i][j], af[i], bf[j]);
        }
    };

    const int ktiles = K / BK;
    ldgsts(0, 0);
    CP_COMMIT();
    if (ktiles > 1) ldgsts(1, 1);
    CP_COMMIT();
    for (int kt = 0; kt < ktiles; kt++) {
        if (kt + 1 < ktiles) { CP_WAIT1(); } else { CP_WAIT0(); }
        __syncthreads();
        if (kt + 2 < ktiles) ldgsts(kt + 2, (kt + 2) % 3);
        CP_COMMIT();
        compute(kt % 3);
    }

#pragma unroll
    for (int i = 0; i < MF; i++) {
        int r0 = m0 + warpM * WM + i * 16 + lr;
#pragma unroll
        for (int j = 0; j < NF; j++) {
            int c0 = n0 + warpN * WN + j * 8 + 2 * lc;
            float2 bv = bias ? *(const float2*)(bias + c0) : make_float2(0.f, 0.f);
            float x0 = acc[i][j][0] * alpha + bv.x;
            float x1 = acc[i][j][1] * alpha + bv.y;
            float x2 = acc[i][j][2] * alpha + bv.x;
            float x3 = acc[i][j][3] * alpha + bv.y;
            if constexpr (CMODE == 1) {
                __half* C = (__half*)Cp;
                *(__half2*)(C + (size_t)r0 * ldc + c0) = __floats2half2_rn(x0, x1);
                *(__half2*)(C + (size_t)(r0 + 8) * ldc + c0) = __floats2half2_rn(x2, x3);
            } else {
                float* C = (float*)Cp;
                *(float2*)(C + (size_t)r0 * ldc + c0) = make_float2(x0, x1);
                *(float2*)(C + (size_t)(r0 + 8) * ldc + c0) = make_float2(x2, x3);
            }
        }
    }
}

// ---------------- projection wrappers ----------------
__global__ void __launch_bounds__(256) k_proj3(
    const __half* __restrict__ xq, const __half* __restrict__ xk, const __half* __restrict__ xv,
    const __half* __restrict__ wq, const __half* __restrict__ wk, const __half* __restrict__ wv,
    const float* __restrict__ bq, const float* __restrict__ bk, const float* __restrict__ bv,
    __half* __restrict__ qh, __half* __restrict__ kh, __half* __restrict__ vh)
{
    const __half* A; const __half* W; const float* bias; __half* C;
    if (blockIdx.z == 0)      { A = xq; W = wq; bias = bq; C = qh; }
    else if (blockIdx.z == 1) { A = xk; W = wk; bias = bk; C = kh; }
    else                      { A = xv; W = wv; bias = bv; C = vh; }
    mm_core<128, 2, 4, 1, 3>(A, E_DIM, W, E_DIM, C, E_DIM, bias, 1.f, E_DIM);
}

__global__ void __launch_bounds__(256) k_proj_f(
    const __half* __restrict__ A, const __half* __restrict__ W,
    const float* __restrict__ bias, float* __restrict__ C)
{
    mm_core<128, 2, 4, 0, 3>(A, E_DIM, W, E_DIM, C, E_DIM, bias, 1.f, E_DIM);
}

// ---------------------------------------------------------------------------
// Fused attention: QK^T + exp + p~ store + Z + (p~ @ V) per (z, 128-row tblock).
// 256 threads = 8 warps (2 warpM x 4 warpN). 16 s-chunks of 128.
// ---------------------------------------------------------------------------
#define ACH 128
#define NCHK (S_DIM / ACH)     // 16
// smem byte offsets
#define QOFF 0
#define QSZ  (128 * 72 * 2)            // 18432
#define KOFF QSZ
#define KSZ  (128 * 72 * 2)            // 18432 per buf, 3 bufs
#define VOFF (KOFF + 3 * KSZ)          // 73728
#define VSZ  (64 * 136 * 2)            // 17408 per buf, 3 bufs
#define POFF (VOFF + 3 * VSZ)          // 125952
#define PSZ  (128 * 136 * 2)           // 34816
#define ZOFF (POFF + PSZ)              // 160768
#define SM_ATTN (ZOFF + 128 * 4 * 4)   // 162816

__global__ void __launch_bounds__(256) k_attn(
    const __half* __restrict__ qh, const __half* __restrict__ kh,
    const __half* __restrict__ vt, __half* __restrict__ ptil,
    float* __restrict__ zinv, __half* __restrict__ ctx)
{
    extern __shared__ __align__(16) char dsm[];
    const uint32_t smb = smem_u32(dsm);
    float* zred = (float*)(dsm + ZOFF);   // [128][4]

    const int tid = threadIdx.x;
    const int wid = tid >> 5;
    const int lane = tid & 31;
    const int lr = lane >> 2, lc = lane & 3;
    const int warpM = wid & 1;            // 2
    const int warpN = wid >> 1;           // 4
    const int z  = blockIdx.x;            // b*16 + h
    const int t0 = blockIdx.y * 128;
    const int b = z >> 4, h = z & 15;

    const __half* qptr = qh + (size_t)b * E_DIM + h * HD_DIM;   // row stride LDQ (t)
    const __half* kptr = kh + (size_t)b * E_DIM + h * HD_DIM;   // row stride LDQ (s)
    const __half* vptr = vt + (size_t)z * HD_DIM * S_DIM;       // [64][S]
    __half* pout = ptil + ((size_t)z * T_DIM + t0) * S_DIM;

    auto ldgK = [&](int c) {
        const int s0 = c * ACH;
        const uint32_t kb = smb + KOFF + (uint32_t)(c % 3) * KSZ;
#pragma unroll
        for (int i = 0; i < 4; i++) {
            int ch = tid + i * 256, r = ch >> 3, cc = (ch & 7) * 8;
            cp16(kb + (uint32_t)(r * 72 + cc) * 2,
                 kptr + (size_t)(s0 + r) * LDQ + cc);
        }
    };
    auto ldgV = [&](int c) {
        const int s0 = c * ACH;
        const uint32_t vb = smb + VOFF + (uint32_t)(c % 3) * VSZ;
#pragma unroll
        for (int i = 0; i < 4; i++) {
            int ch = tid + i * 256, r = ch >> 4, cc = (ch & 15) * 8;
            cp16(vb + (uint32_t)(r * 136 + cc) * 2,
                 vptr + (size_t)r * S_DIM + s0 + cc);
        }
    };

    // group 0: q + chunk 0; group 1: chunk 1
#pragma unroll
    for (int i = 0; i < 4; i++) {
        int ch = tid + i * 256, r = ch >> 3, cc = (ch & 7) * 8;
        cp16(smb + QOFF + (uint32_t)(r * 72 + cc) * 2,
             qptr + (size_t)(t0 + r) * LDQ + cc);
    }
    ldgK(0); ldgV(0);
    CP_COMMIT();
    ldgK(1); ldgV(1);
    CP_COMMIT();

    float acc2[4][2][4];
#pragma unroll
    for (int i = 0; i < 4; i++)
#pragma unroll
        for (int j = 0; j < 2; j++)
#pragma unroll
            for (int q = 0; q < 4; q++) acc2[i][j][q] = 0.f;
    float z0[4] = {0.f, 0.f, 0.f, 0.f}, z1[4] = {0.f, 0.f, 0.f, 0.f};

    for (int c = 0; c < NCHK; c++) {
        if (c + 1 < NCHK) { CP_WAIT1(); } else { CP_WAIT0(); }
        __syncthreads();
        if (c + 2 < NCHK) { ldgK(c + 2); ldgV(c + 2); }
        CP_COMMIT();

        const uint32_t kb = smb + KOFF + (uint32_t)(c % 3) * KSZ;
        const uint32_t vb = smb + VOFF + (uint32_t)(c % 3) * VSZ;
        const int s0 = c * ACH;

        // ---- mma1: q[128x64] @ K^T -> acc1[128 x 128] ----
        float acc1[4][4][4];
#pragma unroll
        for (int i = 0; i < 4; i++)
#pragma unroll
            for (int j = 0; j < 4; j++)
#pragma unroll
                for (int q = 0; q < 4; q++) acc1[i][j][q] = 0.f;

#pragma unroll
        for (int ks = 0; ks < 4; ks++) {
            const int khc = ks * 16;
            uint32_t af[4][4], bf[4][2];
#pragma unroll
            for (int i = 0; i < 4; i++) {
                uint32_t off = (uint32_t)((warpM * 64 + i * 16 + (lane & 15)) * 72 +
                                          khc + ((lane >> 4) << 3));
                ldm_x4(af[i], smb + QOFF + (off << 1));
            }
#pragma unroll
            for (int j = 0; j < 4; j += 2) {
                int row = warpN * 32 + (j + (lane >> 4)) * 8 + (lane & 7);
                int col = khc + ((lane >> 3) & 1) * 8;
                uint32_t r4[4];
                ldm_x4(r4, kb + ((uint32_t)(row * 72 + col) << 1));
                bf[j][0] = r4[0]; bf[j][1] = r4[1];
                bf[j + 1][0] = r4[2]; bf[j + 1][1] = r4[3];
            }
#pragma unroll
            for (int i = 0; i < 4; i++)
#pragma unroll
                for (int j = 0; j < 4; j++)
                    mma_f16(acc1[i][j], af[i], bf[j]);
        }

        // ---- exp + Z partials + store p~ (smem + gmem) ----
#pragma unroll
        for (int i = 0; i < 4; i++) {
            int rl0 = warpM * 64 + i * 16 + lr;
#pragma unroll
            for (int j = 0; j < 4; j++) {
                int c0 = warpN * 32 + j * 8 + 2 * lc;
                float x0 = __expf(acc1[i][j][0] * 0.125f);
                float x1 = __expf(acc1[i][j][1] * 0.125f);
                float x2 = __expf(acc1[i][j][2] * 0.125f);
                float x3 = __expf(acc1[i][j][3] * 0.125f);
                z0[i] += x0 + x1;
                z1[i] += x2 + x3;
                __half2 h01 = __floats2half2_rn(x0, x1);
                __half2 h23 = __floats2half2_rn(x2, x3);
                *(__half2*)(dsm + POFF + (uint32_t)(rl0 * 136 + c0) * 2) = h01;
                *(__half2*)(dsm + POFF + (uint32_t)((rl0 + 8) * 136 + c0) * 2) = h23;
                *(__half2*)(pout + (size_t)rl0 * S_DIM + s0 + c0) = h01;
                *(__half2*)(pout + (size_t)(rl0 + 8) * S_DIM + s0 + c0) = h23;
            }
        }
        __syncthreads();   // p tile visible

        // ---- mma2: p[128x128] @ V[128x64] -> acc2 += ----
#pragma unroll
        for (int ks = 0; ks < 8; ks++) {
            const int khc = ks * 16;
            uint32_t af[4][4], bf[2][2];
#pragma unroll
            for (int i = 0; i < 4; i++) {
                uint32_t off = (uint32_t)((warpM * 64 + i * 16 + (lane & 15)) * 136 +
                                          khc + ((lane >> 4) << 3));
                ldm_x4(af[i], smb + POFF + (off << 1));
            }
            {
                int row = warpN * 16 + (lane >> 4) * 8 + (lane & 7);
                int col = khc + ((lane >> 3) & 1) * 8;
                uint32_t r4[4];
                ldm_x4(r4, vb + ((uint32_t)(row * 136 + col) << 1));
                bf[0][0] = r4[0]; bf[0][1] = r4[1];
                bf[1][0] = r4[2]; bf[1][1] = r4[3];
            }
#pragma unroll
            for (int i = 0; i < 4; i++)
#pragma unroll
                for (int j = 0; j < 2; j++)
                    mma_f16(acc2[i][j], af[i], bf[j]);
        }
    }

    // ---- Z reduce across quad + warps ----
#pragma unroll
    for (int i = 0; i < 4; i++) {
        z0[i] += __shfl_xor_sync(0xffffffffu, z0[i], 1);
        z0[i] += __shfl_xor_sync(0xffffffffu, z0[i], 2);
        z1[i] += __shfl_xor_sync(0xffffffffu, z1[i], 1);
        z1[i] += __shfl_xor_sync(0xffffffffu, z1[i], 2);
    }
    if (lc == 0) {
#pragma unroll
        for (int i = 0; i < 4; i++) {
            int rl0 = warpM * 64 + i * 16 + lr;
            zred[rl0 * 4 + warpN] = z0[i];
            zred[(rl0 + 8) * 4 + warpN] = z1[i];
        }
    }
    __syncthreads();

    if (tid < 128) {
        float Z = zred[tid * 4] + zred[tid * 4 + 1] + zred[tid * 4 + 2] + zred[tid * 4 + 3];
        zinv[(size_t)z * T_DIM + t0 + tid] = 1.f / Z;
    }

    // ---- ctx epilogue: acc2 * (1/Z) ----
#pragma unroll
    for (int i = 0; i < 4; i++) {
        int rl0 = warpM * 64 + i * 16 + lr;
        float inv0 = 1.f / (zred[rl0 * 4] + zred[rl0 * 4 + 1] +
                            zred[rl0 * 4 + 2] + zred[rl0 * 4 + 3]);
        float inv1 = 1.f / (zred[(rl0 + 8) * 4] + zred[(rl0 + 8) * 4 + 1] +
                            zred[(rl0 + 8) * 4 + 2] + zred[(rl0 + 8) * 4 + 3]);
#pragma unroll
        for (int j = 0; j < 2; j++) {
            int c0 = warpN * 16 + j * 8 + 2 * lc;
            __half* d0 = ctx + ((size_t)(t0 + rl0) * B_DIM + b) * E_DIM + h * HD_DIM + c0;
            __half* d1 = ctx + ((size_t)(t0 + rl0 + 8) * B_DIM + b) * E_DIM + h * HD_DIM + c0;
            *(__half2*)d0 = __floats2half2_rn(acc2[i][j][0] * inv0, acc2[i][j][1] * inv0);
            *(__half2*)d1 = __floats2half2_rn(acc2[i][j][2] * inv1, acc2[i][j][3] * inv1);
        }
    }
}

// ---------------- batched fp32 -> fp16 converts ----------------
__global__ void __launch_bounds__(256) k_cvt_in(
    const float* __restrict__ a, const float* __restrict__ b, const float* __restrict__ c,
    __half* __restrict__ oa, __half* __restrict__ ob, __half* __restrict__ oc, int n)
{
    const float* x; __half* y;
    if (blockIdx.z == 0)      { x = a; y = oa; }
    else if (blockIdx.z == 1) { x = b; y = ob; }
    else                      { x = c; y = oc; }
    int i = (blockIdx.x * 256 + threadIdx.x) * 8;
    if (i < n) {
        float4 v0 = *(const float4*)(x + i);
        float4 v1 = *(const float4*)(x + i + 4);
        union { __half2 h[4]; uint4 u; } p;
        p.h[0] = __floats2half2_rn(v0.x, v0.y);
        p.h[1] = __floats2half2_rn(v0.z, v0.w);
        p.h[2] = __floats2half2_rn(v1.x, v1.y);
        p.h[3] = __floats2half2_rn(v1.z, v1.w);
        *(uint4*)(y + i) = p.u;
    }
}

__global__ void __launch_bounds__(256) k_cvt_w(
    const float* __restrict__ a, const float* __restrict__ b,
    const float* __restrict__ c, const float* __restrict__ d,
    __half* __restrict__ oa, __half* __restrict__ ob,
    __half* __restrict__ oc, __half* __restrict__ od, int n)
{
    const float* x; __half* y;
    if (blockIdx.z == 0)      { x = a; y = oa; }
    else if (blockIdx.z == 1) { x = b; y = ob; }
    else if (blockIdx.z == 2) { x = c; y = oc; }
    else                      { x = d; y = od; }
    int i = (blockIdx.x * 256 + threadIdx.x) * 8;
    if (i < n) {
        float4 v0 = *(const float4*)(x + i);
        float4 v1 = *(const float4*)(x + i + 4);
        union { __half2 h[4]; uint4 u; } p;
        p.h[0] = __floats2half2_rn(v0.x, v0.y);
        p.h[1] = __floats2half2_rn(v0.z, v0.w);
        p.h[2] = __floats2half2_rn(v1.x, v1.y);
        p.h[3] = __floats2half2_rn(v1.z, v1.w);
        *(uint4*)(y + i) = p.u;
    }
}

// V transpose fp16: vt[(z*64+d)*S + s] = vh[(s*2+b)*E + h*64+d]
__global__ void __launch_bounds__(256) k_transpose_v(
    const __half* __restrict__ v, __half* __restrict__ vt)
{
    __shared__ __half t[32][34];
    int z = blockIdx.z, b = z >> 4, h = z & 15;
    int s0 = blockIdx.x * 32, d0 = blockIdx.y * 32;
    int lx = threadIdx.x & 31, ly = threadIdx.x >> 5;
#pragma unroll
    for (int i = 0; i < 32; i += 8) {
        int s = s0 + ly + i;
        t[ly + i][lx] = v[(size_t)(s * B_DIM + b) * E_DIM + h * HD_DIM + d0 + lx];
    }
    __syncthreads();
#pragma unroll
    for (int i = 0; i < 32; i += 8) {
        int d = d0 + ly + i;
        vt[((size_t)z * HD_DIM + d) * S_DIM + s0 + lx] = t[lx][ly + i];
    }
}

// ---------------- head-average from p~ and zinv ----------------
__global__ void __launch_bounds__(256) k_avg(
    const __half* __restrict__ ptil, const float* __restrict__ zinv,
    float* __restrict__ avgw)
{
    const int t = blockIdx.x;
    const int b = blockIdx.y;
    const int tid = threadIdx.x;

    float acc[8];
#pragma unroll
    for (int i = 0; i < 8; i++) acc[i] = 0.f;

#pragma unroll 4
    for (int h = 0; h < H_DIM; h++) {
        const size_t ro = (size_t)(b * H_DIM + h) * T_DIM + t;
        const float inv = __ldg(zinv + ro);
        uint4 u = *(const uint4*)(ptil + ro * S_DIM + tid * 8);
        const __half2* hp = (const __half2*)&u;
#pragma unroll
        for (int q = 0; q < 4; q++) {
            float2 f = __half22float2(hp[q]);
            acc[2 * q]     += f.x * inv;
            acc[2 * q + 1] += f.y * inv;
        }
    }

    const float invH = 1.f / (float)H_DIM;
    float* arow = avgw + ((size_t)b * T_DIM + t) * S_DIM + tid * 8;
    float4 o0 = {acc[0] * invH, acc[1] * invH, acc[2] * invH, acc[3] * invH};
    float4 o1 = {acc[4] * invH, acc[5] * invH, acc[6] * invH, acc[7] * invH};
    *(float4*)(arow) = o0;
    *(float4*)(arow + 4) = o1;
}

// ---------------------------------------------------------------------------
extern "C" void kernel_launch(void* const* d_in, const int* in_sizes, int n_in,
                              void* d_out, int out_size)
{
    const float* query = (const float*)d_in[0];
    const float* key   = (const float*)d_in[1];
    const float* value = (const float*)d_in[2];
    const float* Wq = (const float*)d_in[3];
    const float* bq = (const float*)d_in[4];
    const float* Wk = (const float*)d_in[5];
    const float* bk = (const float*)d_in[6];
    const float* Wv = (const float*)d_in[7];
    const float* bv = (const float*)d_in[8];
    const float* Wo = (const float*)d_in[9];
    const float* bo = (const float*)d_in[10];

    float* out  = (float*)d_out;
    float* avgw = out + (size_t)MB_DIM * E_DIM;

    __half *xq, *xk, *xv, *wq, *wk, *wv, *wo, *qh, *kh, *vh, *ctxh, *vt, *pt;
    float *zi;
    cudaGetSymbolAddress((void**)&xq,   g_xq);
    cudaGetSymbolAddress((void**)&xk,   g_xk);
    cudaGetSymbolAddress((void**)&xv,   g_xv);
    cudaGetSymbolAddress((void**)&wq,   g_wq);
    cudaGetSymbolAddress((void**)&wk,   g_wk);
    cudaGetSymbolAddress((void**)&wv,   g_wv);
    cudaGetSymbolAddress((void**)&wo,   g_wo);
    cudaGetSymbolAddress((void**)&qh,   g_qh);
    cudaGetSymbolAddress((void**)&kh,   g_kh);
    cudaGetSymbolAddress((void**)&vh,   g_vh);
    cudaGetSymbolAddress((void**)&ctxh, g_ctxh);
    cudaGetSymbolAddress((void**)&vt,   g_vt);
    cudaGetSymbolAddress((void**)&pt,   g_ptil);
    cudaGetSymbolAddress((void**)&zi,   g_zinv);

    const int SM_P3 = 3 * (128 + 128) * 72 * 2;   // 110592
    cudaFuncSetAttribute(k_proj3,  cudaFuncAttributeMaxDynamicSharedMemorySize, SM_P3);
    cudaFuncSetAttribute(k_proj_f, cudaFuncAttributeMaxDynamicSharedMemorySize, SM_P3);
    cudaFuncSetAttribute(k_attn,   cudaFuncAttributeMaxDynamicSharedMemorySize, SM_ATTN);

    const int NXE = MB_DIM * E_DIM;   // 4M
    const int NWW = E_DIM * E_DIM;    // 1M
    dim3 gci(NXE / 2048, 1, 3);
    k_cvt_in<<<gci, 256>>>(query, key, value, xq, xk, xv, NXE);
    dim3 gcw(NWW / 2048, 1, 4);
    k_cvt_w<<<gcw, 256>>>(Wq, Wk, Wv, Wo, wq, wk, wv, wo, NWW);

    dim3 gp3(E_DIM / 128, MB_DIM / 128, 3);             // (8, 32, 3)
    k_proj3<<<gp3, 256, SM_P3>>>(xq, xk, xv, wq, wk, wv, bq, bk, bv, qh, kh, vh);

    dim3 gt(S_DIM / 32, HD_DIM / 32, B_DIM * H_DIM);    // (64, 2, 32)
    k_transpose_v<<<gt, 256>>>(vh, vt);

    dim3 gat(B_DIM * H_DIM, T_DIM / 128);               // (32, 16)
    k_attn<<<gat, 256, SM_ATTN>>>(qh, kh, vt, pt, zi, ctxh);

    dim3 gm(T_DIM, B_DIM);                              // (2048, 2)
    k_avg<<<gm, 256>>>(pt, zi, avgw);

    dim3 gp(E_DIM / 128, MB_DIM / 128);                 // (8, 32)
    k_proj_f<<<gp, 256, SM_P3>>>(ctxh, wo, bo, out);
}

// round 10
// speedup vs baseline: 1.5086x; 1.0060x over previous
#include <cuda_runtime.h>
#include <cuda_fp16.h>
#include <cstdint>

#define T_DIM 2048
#define B_DIM 2
#define E_DIM 1024
#define H_DIM 16
#define HD_DIM 64
#define S_DIM 2048
#define MB_DIM (T_DIM * B_DIM)     // 4096
#define LDQ (B_DIM * E_DIM)        // 2048

// Static device scratch
__device__ __half g_xq[(size_t)MB_DIM * E_DIM];
__device__ __half g_xk[(size_t)MB_DIM * E_DIM];
__device__ __half g_xv[(size_t)MB_DIM * E_DIM];
__device__ __half g_wq[(size_t)E_DIM * E_DIM];
__device__ __half g_wk[(size_t)E_DIM * E_DIM];
__device__ __half g_wv[(size_t)E_DIM * E_DIM];
__device__ __half g_wo[(size_t)E_DIM * E_DIM];
__device__ __half g_qh[(size_t)MB_DIM * E_DIM];
__device__ __half g_kh[(size_t)MB_DIM * E_DIM];
__device__ __half g_vh[(size_t)MB_DIM * E_DIM];
__device__ __half g_ctxh[(size_t)MB_DIM * E_DIM];
__device__ __half g_vt[(size_t)B_DIM * H_DIM * HD_DIM * S_DIM];
__device__ __half g_ptil[(size_t)B_DIM * H_DIM * T_DIM * S_DIM];  // unnormalized exp scores
__device__ float  g_zinv[(size_t)B_DIM * H_DIM * T_DIM];          // per-row 1/Z

__device__ __forceinline__ uint32_t smem_u32(const void* p) {
    uint32_t a;
    asm("{ .reg .u64 t; cvta.to.shared.u64 t, %1; cvt.u32.u64 %0, t; }" : "=r"(a) : "l"(p));
    return a;
}
__device__ __forceinline__ void cp16(uint32_t dst, const void* src) {
    asm volatile("cp.async.ca.shared.global [%0], [%1], 16;" :: "r"(dst), "l"(src) : "memory");
}
#define CP_COMMIT() asm volatile("cp.async.commit_group;" ::: "memory")
#define CP_WAIT1()  asm volatile("cp.async.wait_group 1;" ::: "memory")
#define CP_WAIT0()  asm volatile("cp.async.wait_group 0;" ::: "memory")

__device__ __forceinline__ void ldm_x4(uint32_t r[4], uint32_t a) {
    asm volatile("ldmatrix.sync.aligned.m8n8.x4.shared.b16 {%0,%1,%2,%3}, [%4];"
        : "=r"(r[0]), "=r"(r[1]), "=r"(r[2]), "=r"(r[3]) : "r"(a));
}
__device__ __forceinline__ void mma_f16(float c[4], const uint32_t a[4], const uint32_t b[2]) {
    asm volatile(
        "mma.sync.aligned.m16n8k16.row.col.f32.f16.f16.f32 "
        "{%0,%1,%2,%3}, {%4,%5,%6,%7}, {%8,%9}, {%0,%1,%2,%3};"
        : "+f"(c[0]), "+f"(c[1]), "+f"(c[2]), "+f"(c[3])
        : "r"(a[0]), "r"(a[1]), "r"(a[2]), "r"(a[3]), "r"(b[0]), "r"(b[1]));
}

// ---------------------------------------------------------------------------
// fp16 mma.sync GEMM core (projections). CMODE 0: fp32 out; 1: fp16 out.
// 3-stage cp.async pipeline, one __syncthreads per k-tile.
// ---------------------------------------------------------------------------
template <int BN, int WARPS_M, int WARPS_N, int CMODE>
__device__ __forceinline__ void mm_core(
    const __half* __restrict__ A, int lda,
    const __half* __restrict__ B, int ldb,
    void* Cp, int ldc,
    const float* __restrict__ bias, float alpha, int K)
{
    constexpr int BM = 128, BK = 64, PAD = 72;
    constexpr int WM = BM / WARPS_M, WN = BN / WARPS_N;
    constexpr int MF = WM / 16, NF = WN / 8;
    constexpr int NCA = (BM * BK / 8) / 256;
    constexpr int NCB = (BN * BK / 8) / 256;
    constexpr uint32_t ASTG = BM * PAD * 2;
    constexpr uint32_t BSTG = BN * PAD * 2;
    constexpr uint32_t STG  = ASTG + BSTG;

    extern __shared__ __align__(16) char dsm[];

    const int tid = threadIdx.x;
    const int wid = tid >> 5;
    const int lane = tid & 31;
    const int lr = lane >> 2;
    const int lc = lane & 3;
    const int warpM = wid % WARPS_M;
    const int warpN = wid / WARPS_M;
    const int m0 = blockIdx.y * BM;
    const int n0 = blockIdx.x * BN;

    const uint32_t smb = smem_u32(dsm);

    float acc[MF][NF][4];
#pragma unroll
    for (int i = 0; i < MF; i++)
#pragma unroll
        for (int j = 0; j < NF; j++)
#pragma unroll
            for (int q = 0; q < 4; q++) acc[i][j][q] = 0.f;

    auto ldgsts = [&](int kt, int p) {
        const int k0 = kt * BK;
        const uint32_t ab = smb + (uint32_t)p * STG;
        const uint32_t bb = ab + ASTG;
#pragma unroll
        for (int i = 0; i < NCA; i++) {
            int ch = tid + i * 256, r = ch >> 3, c = (ch & 7) * 8;
            cp16(ab + (uint32_t)(r * PAD + c) * 2,
                 A + (size_t)(m0 + r) * lda + k0 + c);
        }
#pragma unroll
        for (int i = 0; i < NCB; i++) {
            int ch = tid + i * 256, r = ch >> 3, c = (ch & 7) * 8;
            cp16(bb + (uint32_t)(r * PAD + c) * 2,
                 B + (size_t)(n0 + r) * ldb + k0 + c);
        }
    };

    auto compute = [&](int p) {
        const uint32_t ab = smb + (uint32_t)p * STG;
        const uint32_t bb = ab + ASTG;
#pragma unroll
        for (int ks = 0; ks < BK / 16; ks++) {
            const int kh = ks * 16;
            uint32_t af[MF][4], bf[NF][2];
#pragma unroll
            for (int i = 0; i < MF; i++) {
                uint32_t off = (uint32_t)((warpM * WM + i * 16 + (lane & 15)) * PAD +
                                          kh + ((lane >> 4) << 3));
                ldm_x4(af[i], ab + (off << 1));
            }
#pragma unroll
            for (int j = 0; j < NF; j += 2) {
                int row = warpN * WN + (j + (lane >> 4)) * 8 + (lane & 7);
                int col = kh + ((lane >> 3) & 1) * 8;
                uint32_t r4[4];
                ldm_x4(r4, bb + ((uint32_t)(row * PAD + col) << 1));
                bf[j][0] = r4[0]; bf[j][1] = r4[1];
                bf[j + 1][0] = r4[2]; bf[j + 1][1] = r4[3];
            }
#pragma unroll
            for (int i = 0; i < MF; i++)
#pragma unroll
                for (int j = 0; j < NF; j++)
                    mma_f16(acc[i][j], af[i], bf[j]);
        }
    };

    const int ktiles = K / BK;
    ldgsts(0, 0);
    CP_COMMIT();
    if (ktiles > 1) ldgsts(1, 1);
    CP_COMMIT();
    for (int kt = 0; kt < ktiles; kt++) {
        if (kt + 1 < ktiles) { CP_WAIT1(); } else { CP_WAIT0(); }
        __syncthreads();
        if (kt + 2 < ktiles) ldgsts(kt + 2, (kt + 2) % 3);
        CP_COMMIT();
        compute(kt % 3);
    }

#pragma unroll
    for (int i = 0; i < MF; i++) {
        int r0 = m0 + warpM * WM + i * 16 + lr;
#pragma unroll
        for (int j = 0; j < NF; j++) {
            int c0 = n0 + warpN * WN + j * 8 + 2 * lc;
            float2 bv = bias ? *(const float2*)(bias + c0) : make_float2(0.f, 0.f);
            float x0 = acc[i][j][0] * alpha + bv.x;
            float x1 = acc[i][j][1] * alpha + bv.y;
            float x2 = acc[i][j][2] * alpha + bv.x;
            float x3 = acc[i][j][3] * alpha + bv.y;
            if constexpr (CMODE == 1) {
                __half* C = (__half*)Cp;
                *(__half2*)(C + (size_t)r0 * ldc + c0) = __floats2half2_rn(x0, x1);
                *(__half2*)(C + (size_t)(r0 + 8) * ldc + c0) = __floats2half2_rn(x2, x3);
            } else {
                float* C = (float*)Cp;
                *(float2*)(C + (size_t)r0 * ldc + c0) = make_float2(x0, x1);
                *(float2*)(C + (size_t)(r0 + 8) * ldc + c0) = make_float2(x2, x3);
            }
        }
    }
}

// ---------------- projection wrappers ----------------
__global__ void __launch_bounds__(256, 2) k_proj3(
    const __half* __restrict__ xq, const __half* __restrict__ xk, const __half* __restrict__ xv,
    const __half* __restrict__ wq, const __half* __restrict__ wk, const __half* __restrict__ wv,
    const float* __restrict__ bq, const float* __restrict__ bk, const float* __restrict__ bv,
    __half* __restrict__ qh, __half* __restrict__ kh, __half* __restrict__ vh)
{
    const __half* A; const __half* W; const float* bias; __half* C;
    if (blockIdx.z == 0)      { A = xq; W = wq; bias = bq; C = qh; }
    else if (blockIdx.z == 1) { A = xk; W = wk; bias = bk; C = kh; }
    else                      { A = xv; W = wv; bias = bv; C = vh; }
    mm_core<128, 2, 4, 1>(A, E_DIM, W, E_DIM, C, E_DIM, bias, 1.f, E_DIM);
}

__global__ void __launch_bounds__(256, 2) k_proj_f(
    const __half* __restrict__ A, const __half* __restrict__ W,
    const float* __restrict__ bias, float* __restrict__ C)
{
    mm_core<128, 2, 4, 0>(A, E_DIM, W, E_DIM, C, E_DIM, bias, 1.f, E_DIM);
}

// ---------------------------------------------------------------------------
// Fused attention: QK^T + exp + p~ store + Z + (p~ @ V) per (z, 128-row tblock).
// 256 threads = 8 warps (2 warpM x 4 warpN). 32 s-chunks of 64. 94KB smem ->
// 2 CTAs/SM so a co-resident CTA fills sync/exp bubbles.
// ---------------------------------------------------------------------------
#define ACH 64
#define NCHK (S_DIM / ACH)     // 32
// smem byte offsets (pitch 72 halfs everywhere)
#define QOFF 0
#define QSZ  (128 * 72 * 2)            // 18432
#define KOFF QSZ                        // 18432
#define KSZ  (64 * 72 * 2)             // 9216 per buf, 3 bufs
#define VOFF (KOFF + 3 * KSZ)          // 46080
#define VSZ  (64 * 72 * 2)             // 9216 per buf, 3 bufs
#define POFF (VOFF + 3 * VSZ)          // 73728
#define PSZ  (128 * 72 * 2)            // 18432
#define ZOFF (POFF + PSZ)              // 92160
#define SM_ATTN (ZOFF + 128 * 4 * 4)   // 94208

__global__ void __launch_bounds__(256, 2) k_attn(
    const __half* __restrict__ qh, const __half* __restrict__ kh,
    const __half* __restrict__ vt, __half* __restrict__ ptil,
    float* __restrict__ zinv, __half* __restrict__ ctx)
{
    extern __shared__ __align__(16) char dsm[];
    const uint32_t smb = smem_u32(dsm);
    float* zred = (float*)(dsm + ZOFF);   // [128][4]

    const int tid = threadIdx.x;
    const int wid = tid >> 5;
    const int lane = tid & 31;
    const int lr = lane >> 2, lc = lane & 3;
    const int warpM = wid & 1;            // 2
    const int warpN = wid >> 1;           // 4
    const int z  = blockIdx.x;            // b*16 + h
    const int t0 = blockIdx.y * 128;
    const int b = z >> 4, h = z & 15;

    const __half* qptr = qh + (size_t)b * E_DIM + h * HD_DIM;   // row stride LDQ (t)
    const __half* kptr = kh + (size_t)b * E_DIM + h * HD_DIM;   // row stride LDQ (s)
    const __half* vptr = vt + (size_t)z * HD_DIM * S_DIM;       // [64][S]
    __half* pout = ptil + ((size_t)z * T_DIM + t0) * S_DIM;

    auto ldgK = [&](int c) {
        const int s0 = c * ACH;
        const uint32_t kb = smb + KOFF + (uint32_t)(c % 3) * KSZ;
#pragma unroll
        for (int i = 0; i < 2; i++) {
            int ch = tid + i * 256, r = ch >> 3, cc = (ch & 7) * 8;
            cp16(kb + (uint32_t)(r * 72 + cc) * 2,
                 kptr + (size_t)(s0 + r) * LDQ + cc);
        }
    };
    auto ldgV = [&](int c) {
        const int s0 = c * ACH;
        const uint32_t vb = smb + VOFF + (uint32_t)(c % 3) * VSZ;
#pragma unroll
        for (int i = 0; i < 2; i++) {
            int ch = tid + i * 256, r = ch >> 3, cc = (ch & 7) * 8;
            cp16(vb + (uint32_t)(r * 72 + cc) * 2,
                 vptr + (size_t)r * S_DIM + s0 + cc);
        }
    };

    // group 0: q + chunk 0; group 1: chunk 1
#pragma unroll
    for (int i = 0; i < 4; i++) {
        int ch = tid + i * 256, r = ch >> 3, cc = (ch & 7) * 8;
        cp16(smb + QOFF + (uint32_t)(r * 72 + cc) * 2,
             qptr + (size_t)(t0 + r) * LDQ + cc);
    }
    ldgK(0); ldgV(0);
    CP_COMMIT();
    ldgK(1); ldgV(1);
    CP_COMMIT();

    float acc2[4][2][4];
#pragma unroll
    for (int i = 0; i < 4; i++)
#pragma unroll
        for (int j = 0; j < 2; j++)
#pragma unroll
            for (int q = 0; q < 4; q++) acc2[i][j][q] = 0.f;
    float z0[4] = {0.f, 0.f, 0.f, 0.f}, z1[4] = {0.f, 0.f, 0.f, 0.f};

    for (int c = 0; c < NCHK; c++) {
        if (c + 1 < NCHK) { CP_WAIT1(); } else { CP_WAIT0(); }
        __syncthreads();
        if (c + 2 < NCHK) { ldgK(c + 2); ldgV(c + 2); }
        CP_COMMIT();

        const uint32_t kb = smb + KOFF + (uint32_t)(c % 3) * KSZ;
        const uint32_t vb = smb + VOFF + (uint32_t)(c % 3) * VSZ;
        const int s0 = c * ACH;

        // ---- mma1: q[128x64] @ K^T[64x64] -> acc1[128 x 64] ----
        float acc1[4][2][4];
#pragma unroll
        for (int i = 0; i < 4; i++)
#pragma unroll
            for (int j = 0; j < 2; j++)
#pragma unroll
                for (int q = 0; q < 4; q++) acc1[i][j][q] = 0.f;

#pragma unroll
        for (int ks = 0; ks < 4; ks++) {
            const int khc = ks * 16;
            uint32_t af[4][4], bf[2][2];
#pragma unroll
            for (int i = 0; i < 4; i++) {
                uint32_t off = (uint32_t)((warpM * 64 + i * 16 + (lane & 15)) * 72 +
                                          khc + ((lane >> 4) << 3));
                ldm_x4(af[i], smb + QOFF + (off << 1));
            }
            {
                int row = warpN * 16 + (lane >> 4) * 8 + (lane & 7);
                int col = khc + ((lane >> 3) & 1) * 8;
                uint32_t r4[4];
                ldm_x4(r4, kb + ((uint32_t)(row * 72 + col) << 1));
                bf[0][0] = r4[0]; bf[0][1] = r4[1];
                bf[1][0] = r4[2]; bf[1][1] = r4[3];
            }
#pragma unroll
            for (int i = 0; i < 4; i++)
#pragma unroll
                for (int j = 0; j < 2; j++)
                    mma_f16(acc1[i][j], af[i], bf[j]);
        }

        // ---- exp + Z partials + store p~ (smem + gmem) ----
#pragma unroll
        for (int i = 0; i < 4; i++) {
            int rl0 = warpM * 64 + i * 16 + lr;
#pragma unroll
            for (int j = 0; j < 2; j++) {
                int c0 = warpN * 16 + j * 8 + 2 * lc;
                float x0 = __expf(acc1[i][j][0] * 0.125f);
                float x1 = __expf(acc1[i][j][1] * 0.125f);
                float x2 = __expf(acc1[i][j][2] * 0.125f);
                float x3 = __expf(acc1[i][j][3] * 0.125f);
                z0[i] += x0 + x1;
                z1[i] += x2 + x3;
                __half2 h01 = __floats2half2_rn(x0, x1);
                __half2 h23 = __floats2half2_rn(x2, x3);
                *(__half2*)(dsm + POFF + (uint32_t)(rl0 * 72 + c0) * 2) = h01;
                *(__half2*)(dsm + POFF + (uint32_t)((rl0 + 8) * 72 + c0) * 2) = h23;
                *(__half2*)(pout + (size_t)rl0 * S_DIM + s0 + c0) = h01;
                *(__half2*)(pout + (size_t)(rl0 + 8) * S_DIM + s0 + c0) = h23;
            }
        }
        __syncthreads();   // p tile visible

        // ---- mma2: p[128x64] @ V^T[64(d) x 64(s)] -> acc2 += ----
#pragma unroll
        for (int ks = 0; ks < 4; ks++) {
            const int khc = ks * 16;
            uint32_t af[4][4], bf[2][2];
#pragma unroll
            for (int i = 0; i < 4; i++) {
                uint32_t off = (uint32_t)((warpM * 64 + i * 16 + (lane & 15)) * 72 +
                                          khc + ((lane >> 4) << 3));
                ldm_x4(af[i], smb + POFF + (off << 1));
            }
            {
                int row = warpN * 16 + (lane >> 4) * 8 + (lane & 7);
                int col = khc + ((lane >> 3) & 1) * 8;
                uint32_t r4[4];
                ldm_x4(r4, vb + ((uint32_t)(row * 72 + col) << 1));
                bf[0][0] = r4[0]; bf[0][1] = r4[1];
                bf[1][0] = r4[2]; bf[1][1] = r4[3];
            }
#pragma unroll
            for (int i = 0; i < 4; i++)
#pragma unroll
                for (int j = 0; j < 2; j++)
                    mma_f16(acc2[i][j], af[i], bf[j]);
        }
    }

    // ---- Z reduce across quad + warps ----
#pragma unroll
    for (int i = 0; i < 4; i++) {
        z0[i] += __shfl_xor_sync(0xffffffffu, z0[i], 1);
        z0[i] += __shfl_xor_sync(0xffffffffu, z0[i], 2);
        z1[i] += __shfl_xor_sync(0xffffffffu, z1[i], 1);
        z1[i] += __shfl_xor_sync(0xffffffffu, z1[i], 2);
    }
    if (lc == 0) {
#pragma unroll
        for (int i = 0; i < 4; i++) {
            int rl0 = warpM * 64 + i * 16 + lr;
            zred[rl0 * 4 + warpN] = z0[i];
            zred[(rl0 + 8) * 4 + warpN] = z1[i];
        }
    }
    __syncthreads();

    if (tid < 128) {
        float Z = zred[tid * 4] + zred[tid * 4 + 1] + zred[tid * 4 + 2] + zred[tid * 4 + 3];
        zinv[(size_t)z * T_DIM + t0 + tid] = 1.f / Z;
    }

    // ---- ctx epilogue: acc2 * (1/Z) ----
#pragma unroll
    for (int i = 0; i < 4; i++) {
        int rl0 = warpM * 64 + i * 16 + lr;
        float inv0 = 1.f / (zred[rl0 * 4] + zred[rl0 * 4 + 1] +
                            zred[rl0 * 4 + 2] + zred[rl0 * 4 + 3]);
        float inv1 = 1.f / (zred[(rl0 + 8) * 4] + zred[(rl0 + 8) * 4 + 1] +
                            zred[(rl0 + 8) * 4 + 2] + zred[(rl0 + 8) * 4 + 3]);
#pragma unroll
        for (int j = 0; j < 2; j++) {
            int c0 = warpN * 16 + j * 8 + 2 * lc;
            __half* d0 = ctx + ((size_t)(t0 + rl0) * B_DIM + b) * E_DIM + h * HD_DIM + c0;
            __half* d1 = ctx + ((size_t)(t0 + rl0 + 8) * B_DIM + b) * E_DIM + h * HD_DIM + c0;
            *(__half2*)d0 = __floats2half2_rn(acc2[i][j][0] * inv0, acc2[i][j][1] * inv0);
            *(__half2*)d1 = __floats2half2_rn(acc2[i][j][2] * inv1, acc2[i][j][3] * inv1);
        }
    }
}

// ---------------- batched fp32 -> fp16 converts ----------------
__global__ void __launch_bounds__(256) k_cvt_in(
    const float* __restrict__ a, const float* __restrict__ b, const float* __restrict__ c,
    __half* __restrict__ oa, __half* __restrict__ ob, __half* __restrict__ oc, int n)
{
    const float* x; __half* y;
    if (blockIdx.z == 0)      { x = a; y = oa; }
    else if (blockIdx.z == 1) { x = b; y = ob; }
    else                      { x = c; y = oc; }
    int i = (blockIdx.x * 256 + threadIdx.x) * 8;
    if (i < n) {
        float4 v0 = *(const float4*)(x + i);
        float4 v1 = *(const float4*)(x + i + 4);
        union { __half2 h[4]; uint4 u; } p;
        p.h[0] = __floats2half2_rn(v0.x, v0.y);
        p.h[1] = __floats2half2_rn(v0.z, v0.w);
        p.h[2] = __floats2half2_rn(v1.x, v1.y);
        p.h[3] = __floats2half2_rn(v1.z, v1.w);
        *(uint4*)(y + i) = p.u;
    }
}

__global__ void __launch_bounds__(256) k_cvt_w(
    const float* __restrict__ a, const float* __restrict__ b,
    const float* __restrict__ c, const float* __restrict__ d,
    __half* __restrict__ oa, __half* __restrict__ ob,
    __half* __restrict__ oc, __half* __restrict__ od, int n)
{
    const float* x; __half* y;
    if (blockIdx.z == 0)      { x = a; y = oa; }
    else if (blockIdx.z == 1) { x = b; y = ob; }
    else if (blockIdx.z == 2) { x = c; y = oc; }
    else                      { x = d; y = od; }
    int i = (blockIdx.x * 256 + threadIdx.x) * 8;
    if (i < n) {
        float4 v0 = *(const float4*)(x + i);
        float4 v1 = *(const float4*)(x + i + 4);
        union { __half2 h[4]; uint4 u; } p;
        p.h[0] = __floats2half2_rn(v0.x, v0.y);
        p.h[1] = __floats2half2_rn(v0.z, v0.w);
        p.h[2] = __floats2half2_rn(v1.x, v1.y);
        p.h[3] = __floats2half2_rn(v1.z, v1.w);
        *(uint4*)(y + i) = p.u;
    }
}

// V transpose fp16: vt[(z*64+d)*S + s] = vh[(s*2+b)*E + h*64+d]
__global__ void __launch_bounds__(256) k_transpose_v(
    const __half* __restrict__ v, __half* __restrict__ vt)
{
    __shared__ __half t[32][34];
    int z = blockIdx.z, b = z >> 4, h = z & 15;
    int s0 = blockIdx.x * 32, d0 = blockIdx.y * 32;
    int lx = threadIdx.x & 31, ly = threadIdx.x >> 5;
#pragma unroll
    for (int i = 0; i < 32; i += 8) {
        int s = s0 + ly + i;
        t[ly + i][lx] = v[(size_t)(s * B_DIM + b) * E_DIM + h * HD_DIM + d0 + lx];
    }
    __syncthreads();
#pragma unroll
    for (int i = 0; i < 32; i += 8) {
        int d = d0 + ly + i;
        vt[((size_t)z * HD_DIM + d) * S_DIM + s0 + lx] = t[lx][ly + i];
    }
}

// ---------------- head-average from p~ and zinv ----------------
__global__ void __launch_bounds__(256) k_avg(
    const __half* __restrict__ ptil, const float* __restrict__ zinv,
    float* __restrict__ avgw)
{
    const int t = blockIdx.x;
    const int b = blockIdx.y;
    const int tid = threadIdx.x;

    float acc[8];
#pragma unroll
    for (int i = 0; i < 8; i++) acc[i] = 0.f;

#pragma unroll 4
    for (int h = 0; h < H_DIM; h++) {
        const size_t ro = (size_t)(b * H_DIM + h) * T_DIM + t;
        const float inv = __ldg(zinv + ro);
        uint4 u = *(const uint4*)(ptil + ro * S_DIM + tid * 8);
        const __half2* hp = (const __half2*)&u;
#pragma unroll
        for (int q = 0; q < 4; q++) {
            float2 f = __half22float2(hp[q]);
            acc[2 * q]     += f.x * inv;
            acc[2 * q + 1] += f.y * inv;
        }
    }

    const float invH = 1.f / (float)H_DIM;
    float* arow = avgw + ((size_t)b * T_DIM + t) * S_DIM + tid * 8;
    float4 o0 = {acc[0] * invH, acc[1] * invH, acc[2] * invH, acc[3] * invH};
    float4 o1 = {acc[4] * invH, acc[5] * invH, acc[6] * invH, acc[7] * invH};
    *(float4*)(arow) = o0;
    *(float4*)(arow + 4) = o1;
}

// ---------------------------------------------------------------------------
extern "C" void kernel_launch(void* const* d_in, const int* in_sizes, int n_in,
                              void* d_out, int out_size)
{
    const float* query = (const float*)d_in[0];
    const float* key   = (const float*)d_in[1];
    const float* value = (const float*)d_in[2];
    const float* Wq = (const float*)d_in[3];
    const float* bq = (const float*)d_in[4];
    const float* Wk = (const float*)d_in[5];
    const float* bk = (const float*)d_in[6];
    const float* Wv = (const float*)d_in[7];
    const float* bv = (const float*)d_in[8];
    const float* Wo = (const float*)d_in[9];
    const float* bo = (const float*)d_in[10];

    float* out  = (float*)d_out;
    float* avgw = out + (size_t)MB_DIM * E_DIM;

    __half *xq, *xk, *xv, *wq, *wk, *wv, *wo, *qh, *kh, *vh, *ctxh, *vt, *pt;
    float *zi;
    cudaGetSymbolAddress((void**)&xq,   g_xq);
    cudaGetSymbolAddress((void**)&xk,   g_xk);
    cudaGetSymbolAddress((void**)&xv,   g_xv);
    cudaGetSymbolAddress((void**)&wq,   g_wq);
    cudaGetSymbolAddress((void**)&wk,   g_wk);
    cudaGetSymbolAddress((void**)&wv,   g_wv);
    cudaGetSymbolAddress((void**)&wo,   g_wo);
    cudaGetSymbolAddress((void**)&qh,   g_qh);
    cudaGetSymbolAddress((void**)&kh,   g_kh);
    cudaGetSymbolAddress((void**)&vh,   g_vh);
    cudaGetSymbolAddress((void**)&ctxh, g_ctxh);
    cudaGetSymbolAddress((void**)&vt,   g_vt);
    cudaGetSymbolAddress((void**)&pt,   g_ptil);
    cudaGetSymbolAddress((void**)&zi,   g_zinv);

    const int SM_P3 = 3 * (128 + 128) * 72 * 2;   // 110592
    cudaFuncSetAttribute(k_proj3,  cudaFuncAttributeMaxDynamicSharedMemorySize, SM_P3);
    cudaFuncSetAttribute(k_proj_f, cudaFuncAttributeMaxDynamicSharedMemorySize, SM_P3);
    cudaFuncSetAttribute(k_attn,   cudaFuncAttributeMaxDynamicSharedMemorySize, SM_ATTN);

    const int NXE = MB_DIM * E_DIM;   // 4M
    const int NWW = E_DIM * E_DIM;    // 1M
    dim3 gci(NXE / 2048, 1, 3);
    k_cvt_in<<<gci, 256>>>(query, key, value, xq, xk, xv, NXE);
    dim3 gcw(NWW / 2048, 1, 4);
    k_cvt_w<<<gcw, 256>>>(Wq, Wk, Wv, Wo, wq, wk, wv, wo, NWW);

    dim3 gp3(E_DIM / 128, MB_DIM / 128, 3);             // (8, 32, 3)
    k_proj3<<<gp3, 256, SM_P3>>>(xq, xk, xv, wq, wk, wv, bq, bk, bv, qh, kh, vh);

    dim3 gt(S_DIM / 32, HD_DIM / 32, B_DIM * H_DIM);    // (64, 2, 32)
    k_transpose_v<<<gt, 256>>>(vh, vt);

    dim3 gat(B_DIM * H_DIM, T_DIM / 128);               // (32, 16)
    k_attn<<<gat, 256, SM_ATTN>>>(qh, kh, vt, pt, zi, ctxh);

    dim3 gm(T_DIM, B_DIM);                              // (2048, 2)
    k_avg<<<gm, 256>>>(pt, zi, avgw);

    dim3 gp(E_DIM / 128, MB_DIM / 128);                 // (8, 32)
    k_proj_f<<<gp, 256, SM_P3>>>(ctxh, wo, bo, out);
}

// round 12
// speedup vs baseline: 1.6749x; 1.1102x over previous
#include <cuda_runtime.h>
#include <cuda_fp16.h>
#include <cstdint>

#define T_DIM 2048
#define B_DIM 2
#define E_DIM 1024
#define H_DIM 16
#define HD_DIM 64
#define S_DIM 2048
#define MB_DIM (T_DIM * B_DIM)     // 4096
#define LDQ (B_DIM * E_DIM)        // 2048

// Static device scratch
__device__ __half g_xq[(size_t)MB_DIM * E_DIM];
__device__ __half g_xk[(size_t)MB_DIM * E_DIM];
__device__ __half g_xv[(size_t)MB_DIM * E_DIM];
__device__ __half g_wq[(size_t)E_DIM * E_DIM];
__device__ __half g_wk[(size_t)E_DIM * E_DIM];
__device__ __half g_wv[(size_t)E_DIM * E_DIM];
__device__ __half g_wo[(size_t)E_DIM * E_DIM];
__device__ __half g_qh[(size_t)MB_DIM * E_DIM];
__device__ __half g_kh[(size_t)MB_DIM * E_DIM];
__device__ __half g_vh[(size_t)MB_DIM * E_DIM];
__device__ __half g_ctxh[(size_t)MB_DIM * E_DIM];
__device__ __half g_vt[(size_t)B_DIM * H_DIM * HD_DIM * S_DIM];
__device__ __half g_ptil[(size_t)B_DIM * H_DIM * T_DIM * S_DIM];  // unnormalized exp scores
__device__ float  g_zinv[(size_t)B_DIM * H_DIM * T_DIM];          // per-row 1/Z

__device__ __forceinline__ uint32_t smem_u32(const void* p) {
    uint32_t a;
    asm("{ .reg .u64 t; cvta.to.shared.u64 t, %1; cvt.u32.u64 %0, t; }" : "=r"(a) : "l"(p));
    return a;
}
__device__ __forceinline__ void cp16(uint32_t dst, const void* src) {
    asm volatile("cp.async.ca.shared.global [%0], [%1], 16;" :: "r"(dst), "l"(src) : "memory");
}
#define CP_COMMIT() asm volatile("cp.async.commit_group;" ::: "memory")
#define CP_WAIT1()  asm volatile("cp.async.wait_group 1;" ::: "memory")
#define CP_WAIT0()  asm volatile("cp.async.wait_group 0;" ::: "memory")

__device__ __forceinline__ void ldm_x4(uint32_t r[4], uint32_t a) {
    asm volatile("ldmatrix.sync.aligned.m8n8.x4.shared.b16 {%0,%1,%2,%3}, [%4];"
        : "=r"(r[0]), "=r"(r[1]), "=r"(r[2]), "=r"(r[3]) : "r"(a));
}
__device__ __forceinline__ void mma_f16(float c[4], const uint32_t a[4], const uint32_t b[2]) {
    asm volatile(
        "mma.sync.aligned.m16n8k16.row.col.f32.f16.f16.f32 "
        "{%0,%1,%2,%3}, {%4,%5,%6,%7}, {%8,%9}, {%0,%1,%2,%3};"
        : "+f"(c[0]), "+f"(c[1]), "+f"(c[2]), "+f"(c[3])
        : "r"(a[0]), "r"(a[1]), "r"(a[2]), "r"(a[3]), "r"(b[0]), "r"(b[1]));
}
// ex2.approx.f32 — MUFU.EX2, same unit/accuracy class as __expf's backend
__device__ __forceinline__ float ex2(float x) {
    float r;
    asm("ex2.approx.f32 %0, %1;" : "=f"(r) : "f"(x));
    return r;
}

// ---------------------------------------------------------------------------
// fp16 mma.sync GEMM core (projections). CMODE 0: fp32 out; 1: fp16 out.
// 3-stage cp.async pipeline, one __syncthreads per k-tile.
// ---------------------------------------------------------------------------
template <int BN, int WARPS_M, int WARPS_N, int CMODE>
__device__ __forceinline__ void mm_core(
    const __half* __restrict__ A, int lda,
    const __half* __restrict__ B, int ldb,
    void* Cp, int ldc,
    const float* __restrict__ bias, float alpha, int K)
{
    constexpr int BM = 128, BK = 64, PAD = 72;
    constexpr int WM = BM / WARPS_M, WN = BN / WARPS_N;
    constexpr int MF = WM / 16, NF = WN / 8;
    constexpr int NCA = (BM * BK / 8) / 256;
    constexpr int NCB = (BN * BK / 8) / 256;
    constexpr uint32_t ASTG = BM * PAD * 2;
    constexpr uint32_t BSTG = BN * PAD * 2;
    constexpr uint32_t STG  = ASTG + BSTG;

    extern __shared__ __align__(16) char dsm[];

    const int tid = threadIdx.x;
    const int wid = tid >> 5;
    const int lane = tid & 31;
    const int lr = lane >> 2;
    const int lc = lane & 3;
    const int warpM = wid % WARPS_M;
    const int warpN = wid / WARPS_M;
    const int m0 = blockIdx.y * BM;
    const int n0 = blockIdx.x * BN;

    const uint32_t smb = smem_u32(dsm);

    float acc[MF][NF][4];
#pragma unroll
    for (int i = 0; i < MF; i++)
#pragma unroll
        for (int j = 0; j < NF; j++)
#pragma unroll
            for (int q = 0; q < 4; q++) acc[i][j][q] = 0.f;

    auto ldgsts = [&](int kt, int p) {
        const int k0 = kt * BK;
        const uint32_t ab = smb + (uint32_t)p * STG;
        const uint32_t bb = ab + ASTG;
#pragma unroll
        for (int i = 0; i < NCA; i++) {
            int ch = tid + i * 256, r = ch >> 3, c = (ch & 7) * 8;
            cp16(ab + (uint32_t)(r * PAD + c) * 2,
                 A + (size_t)(m0 + r) * lda + k0 + c);
        }
#pragma unroll
        for (int i = 0; i < NCB; i++) {
            int ch = tid + i * 256, r = ch >> 3, c = (ch & 7) * 8;
            cp16(bb + (uint32_t)(r * PAD + c) * 2,
                 B + (size_t)(n0 + r) * ldb + k0 + c);
        }
    };

    auto compute = [&](int p) {
        const uint32_t ab = smb + (uint32_t)p * STG;
        const uint32_t bb = ab + ASTG;
#pragma unroll
        for (int ks = 0; ks < BK / 16; ks++) {
            const int kh = ks * 16;
            uint32_t af[MF][4], bf[NF][2];
#pragma unroll
            for (int i = 0; i < MF; i++) {
                uint32_t off = (uint32_t)((warpM * WM + i * 16 + (lane & 15)) * PAD +
                                          kh + ((lane >> 4) << 3));
                ldm_x4(af[i], ab + (off << 1));
            }
#pragma unroll
            for (int j = 0; j < NF; j += 2) {
                int row = warpN * WN + (j + (lane >> 4)) * 8 + (lane & 7);
                int col = kh + ((lane >> 3) & 1) * 8;
                uint32_t r4[4];
                ldm_x4(r4, bb + ((uint32_t)(row * PAD + col) << 1));
                bf[j][0] = r4[0]; bf[j][1] = r4[1];
                bf[j + 1][0] = r4[2]; bf[j + 1][1] = r4[3];
            }
#pragma unroll
            for (int i = 0; i < MF; i++)
#pragma unroll
                for (int j = 0; j < NF; j++)
                    mma_f16(acc[i][j], af[i], bf[j]);
        }
    };

    const int ktiles = K / BK;
    ldgsts(0, 0);
    CP_COMMIT();
    if (ktiles > 1) ldgsts(1, 1);
    CP_COMMIT();
    for (int kt = 0; kt < ktiles; kt++) {
        if (kt + 1 < ktiles) { CP_WAIT1(); } else { CP_WAIT0(); }
        __syncthreads();
        if (kt + 2 < ktiles) ldgsts(kt + 2, (kt + 2) % 3);
        CP_COMMIT();
        compute(kt % 3);
    }

#pragma unroll
    for (int i = 0; i < MF; i++) {
        int r0 = m0 + warpM * WM + i * 16 + lr;
#pragma unroll
        for (int j = 0; j < NF; j++) {
            int c0 = n0 + warpN * WN + j * 8 + 2 * lc;
            float2 bv = bias ? *(const float2*)(bias + c0) : make_float2(0.f, 0.f);
            float x0 = acc[i][j][0] * alpha + bv.x;
            float x1 = acc[i][j][1] * alpha + bv.y;
            float x2 = acc[i][j][2] * alpha + bv.x;
            float x3 = acc[i][j][3] * alpha + bv.y;
            if constexpr (CMODE == 1) {
                __half* C = (__half*)Cp;
                *(__half2*)(C + (size_t)r0 * ldc + c0) = __floats2half2_rn(x0, x1);
                *(__half2*)(C + (size_t)(r0 + 8) * ldc + c0) = __floats2half2_rn(x2, x3);
            } else {
                float* C = (float*)Cp;
                *(float2*)(C + (size_t)r0 * ldc + c0) = make_float2(x0, x1);
                *(float2*)(C + (size_t)(r0 + 8) * ldc + c0) = make_float2(x2, x3);
            }
        }
    }
}

// ---------------- projection wrappers ----------------
__global__ void __launch_bounds__(256, 2) k_proj3(
    const __half* __restrict__ xq, const __half* __restrict__ xk, const __half* __restrict__ xv,
    const __half* __restrict__ wq, const __half* __restrict__ wk, const __half* __restrict__ wv,
    const float* __restrict__ bq, const float* __restrict__ bk, const float* __restrict__ bv,
    __half* __restrict__ qh, __half* __restrict__ kh, __half* __restrict__ vh)
{
    const __half* A; const __half* W; const float* bias; __half* C;
    if (blockIdx.z == 0)      { A = xq; W = wq; bias = bq; C = qh; }
    else if (blockIdx.z == 1) { A = xk; W = wk; bias = bk; C = kh; }
    else                      { A = xv; W = wv; bias = bv; C = vh; }
    mm_core<128, 2, 4, 1>(A, E_DIM, W, E_DIM, C, E_DIM, bias, 1.f, E_DIM);
}

__global__ void __launch_bounds__(256, 2) k_proj_f(
    const __half* __restrict__ A, const __half* __restrict__ W,
    const float* __restrict__ bias, float* __restrict__ C)
{
    mm_core<128, 2, 4, 0>(A, E_DIM, W, E_DIM, C, E_DIM, bias, 1.f, E_DIM);
}

// ---------------------------------------------------------------------------
// Fused attention: QK^T + exp + p~ store + Z + (p~ @ V) per (z, 128-row tblock).
// 256 threads = 8 warps (2 warpM x 4 warpN). 32 s-chunks of 64.
// p~ gmem store goes through the P smem tile -> coalesced STG.128.
// ---------------------------------------------------------------------------
#define ACH 64
#define NCHK (S_DIM / ACH)     // 32
// smem byte offsets (pitch 72 halfs everywhere)
#define QOFF 0
#define QSZ  (128 * 72 * 2)            // 18432
#define KOFF QSZ                        // 18432
#define KSZ  (64 * 72 * 2)             // 9216 per buf, 3 bufs
#define VOFF (KOFF + 3 * KSZ)          // 46080
#define VSZ  (64 * 72 * 2)             // 9216 per buf, 3 bufs
#define POFF (VOFF + 3 * VSZ)          // 73728
#define PSZ  (128 * 72 * 2)            // 18432
#define ZOFF (POFF + PSZ)              // 92160
#define SM_ATTN (ZOFF + 128 * 4 * 4)   // 94208

// exp(x*0.125) == exp2(x * 0.125*log2(e))
#define EXP2_SCALE 0.18033688011112042f

__global__ void __launch_bounds__(256, 2) k_attn(
    const __half* __restrict__ qh, const __half* __restrict__ kh,
    const __half* __restrict__ vt, __half* __restrict__ ptil,
    float* __restrict__ zinv, __half* __restrict__ ctx)
{
    extern __shared__ __align__(16) char dsm[];
    const uint32_t smb = smem_u32(dsm);
    float* zred = (float*)(dsm + ZOFF);   // [128][4]

    const int tid = threadIdx.x;
    const int wid = tid >> 5;
    const int lane = tid & 31;
    const int lr = lane >> 2, lc = lane & 3;
    const int warpM = wid & 1;            // 2
    const int warpN = wid >> 1;           // 4
    const int z  = blockIdx.x;            // b*16 + h
    const int t0 = blockIdx.y * 128;
    const int b = z >> 4, h = z & 15;

    const __half* qptr = qh + (size_t)b * E_DIM + h * HD_DIM;   // row stride LDQ (t)
    const __half* kptr = kh + (size_t)b * E_DIM + h * HD_DIM;   // row stride LDQ (s)
    const __half* vptr = vt + (size_t)z * HD_DIM * S_DIM;       // [64][S]
    __half* pout = ptil + ((size_t)z * T_DIM + t0) * S_DIM;

    auto ldgK = [&](int c) {
        const int s0 = c * ACH;
        const uint32_t kb = smb + KOFF + (uint32_t)(c % 3) * KSZ;
#pragma unroll
        for (int i = 0; i < 2; i++) {
            int ch = tid + i * 256, r = ch >> 3, cc = (ch & 7) * 8;
            cp16(kb + (uint32_t)(r * 72 + cc) * 2,
                 kptr + (size_t)(s0 + r) * LDQ + cc);
        }
    };
    auto ldgV = [&](int c) {
        const int s0 = c * ACH;
        const uint32_t vb = smb + VOFF + (uint32_t)(c % 3) * VSZ;
#pragma unroll
        for (int i = 0; i < 2; i++) {
            int ch = tid + i * 256, r = ch >> 3, cc = (ch & 7) * 8;
            cp16(vb + (uint32_t)(r * 72 + cc) * 2,
                 vptr + (size_t)r * S_DIM + s0 + cc);
        }
    };

    // group 0: q + chunk 0; group 1: chunk 1
#pragma unroll
    for (int i = 0; i < 4; i++) {
        int ch = tid + i * 256, r = ch >> 3, cc = (ch & 7) * 8;
        cp16(smb + QOFF + (uint32_t)(r * 72 + cc) * 2,
             qptr + (size_t)(t0 + r) * LDQ + cc);
    }
    ldgK(0); ldgV(0);
    CP_COMMIT();
    ldgK(1); ldgV(1);
    CP_COMMIT();

    float acc2[4][2][4];
#pragma unroll
    for (int i = 0; i < 4; i++)
#pragma unroll
        for (int j = 0; j < 2; j++)
#pragma unroll
            for (int q = 0; q < 4; q++) acc2[i][j][q] = 0.f;
    float z0[4] = {0.f, 0.f, 0.f, 0.f}, z1[4] = {0.f, 0.f, 0.f, 0.f};

    for (int c = 0; c < NCHK; c++) {
        if (c + 1 < NCHK) { CP_WAIT1(); } else { CP_WAIT0(); }
        __syncthreads();
        if (c + 2 < NCHK) { ldgK(c + 2); ldgV(c + 2); }
        CP_COMMIT();

        const uint32_t kb = smb + KOFF + (uint32_t)(c % 3) * KSZ;
        const uint32_t vb = smb + VOFF + (uint32_t)(c % 3) * VSZ;
        const int s0 = c * ACH;

        // ---- mma1: q[128x64] @ K^T[64x64] -> acc1[128 x 64] ----
        float acc1[4][2][4];
#pragma unroll
        for (int i = 0; i < 4; i++)
#pragma unroll
            for (int j = 0; j < 2; j++)
#pragma unroll
                for (int q = 0; q < 4; q++) acc1[i][j][q] = 0.f;

#pragma unroll
        for (int ks = 0; ks < 4; ks++) {
            const int khc = ks * 16;
            uint32_t af[4][4], bf[2][2];
#pragma unroll
            for (int i = 0; i < 4; i++) {
                uint32_t off = (uint32_t)((warpM * 64 + i * 16 + (lane & 15)) * 72 +
                                          khc + ((lane >> 4) << 3));
                ldm_x4(af[i], smb + QOFF + (off << 1));
            }
            {
                int row = warpN * 16 + (lane >> 4) * 8 + (lane & 7);
                int col = khc + ((lane >> 3) & 1) * 8;
                uint32_t r4[4];
                ldm_x4(r4, kb + ((uint32_t)(row * 72 + col) << 1));
                bf[0][0] = r4[0]; bf[0][1] = r4[1];
                bf[1][0] = r4[2]; bf[1][1] = r4[3];
            }
#pragma unroll
            for (int i = 0; i < 4; i++)
#pragma unroll
                for (int j = 0; j < 2; j++)
                    mma_f16(acc1[i][j], af[i], bf[j]);
        }

        // ---- exp (EX2) + Z partials + store p~ to smem ----
#pragma unroll
        for (int i = 0; i < 4; i++) {
            int rl0 = warpM * 64 + i * 16 + lr;
#pragma unroll
            for (int j = 0; j < 2; j++) {
                int c0 = warpN * 16 + j * 8 + 2 * lc;
                float x0 = ex2(acc1[i][j][0] * EXP2_SCALE);
                float x1 = ex2(acc1[i][j][1] * EXP2_SCALE);
                float x2 = ex2(acc1[i][j][2] * EXP2_SCALE);
                float x3 = ex2(acc1[i][j][3] * EXP2_SCALE);
                z0[i] += x0 + x1;
                z1[i] += x2 + x3;
                *(__half2*)(dsm + POFF + (uint32_t)(rl0 * 72 + c0) * 2) =
                    __floats2half2_rn(x0, x1);
                *(__half2*)(dsm + POFF + (uint32_t)((rl0 + 8) * 72 + c0) * 2) =
                    __floats2half2_rn(x2, x3);
            }
        }
        __syncthreads();   // p tile visible

        // ---- coalesced p~ gmem store from smem (4 x LDS.128 + STG.128) ----
#pragma unroll
        for (int i = 0; i < 4; i++) {
            int idx = tid + i * 256;          // 0..1023
            int row = idx >> 3, col8 = (idx & 7) * 8;
            uint4 v = *(const uint4*)(dsm + POFF + (uint32_t)(row * 72 + col8) * 2);
            *(uint4*)(pout + (size_t)row * S_DIM + s0 + col8) = v;
        }

        // ---- mma2: p[128x64] @ V^T[64(d) x 64(s)] -> acc2 += ----
#pragma unroll
        for (int ks = 0; ks < 4; ks++) {
            const int khc = ks * 16;
            uint32_t af[4][4], bf[2][2];
#pragma unroll
            for (int i = 0; i < 4; i++) {
                uint32_t off = (uint32_t)((warpM * 64 + i * 16 + (lane & 15)) * 72 +
                                          khc + ((lane >> 4) << 3));
                ldm_x4(af[i], smb + POFF + (off << 1));
            }
            {
                int row = warpN * 16 + (lane >> 4) * 8 + (lane & 7);
                int col = khc + ((lane >> 3) & 1) * 8;
                uint32_t r4[4];
                ldm_x4(r4, vb + ((uint32_t)(row * 72 + col) << 1));
                bf[0][0] = r4[0]; bf[0][1] = r4[1];
                bf[1][0] = r4[2]; bf[1][1] = r4[3];
            }
#pragma unroll
            for (int i = 0; i < 4; i++)
#pragma unroll
                for (int j = 0; j < 2; j++)
                    mma_f16(acc2[i][j], af[i], bf[j]);
        }
    }

    // ---- Z reduce across quad + warps ----
#pragma unroll
    for (int i = 0; i < 4; i++) {
        z0[i] += __shfl_xor_sync(0xffffffffu, z0[i], 1);
        z0[i] += __shfl_xor_sync(0xffffffffu, z0[i], 2);
        z1[i] += __shfl_xor_sync(0xffffffffu, z1[i], 1);
        z1[i] += __shfl_xor_sync(0xffffffffu, z1[i], 2);
    }
    if (lc == 0) {
#pragma unroll
        for (int i = 0; i < 4; i++) {
            int rl0 = warpM * 64 + i * 16 + lr;
            zred[rl0 * 4 + warpN] = z0[i];
            zred[(rl0 + 8) * 4 + warpN] = z1[i];
        }
    }
    __syncthreads();

    if (tid < 128) {
        float Z = zred[tid * 4] + zred[tid * 4 + 1] + zred[tid * 4 + 2] + zred[tid * 4 + 3];
        zinv[(size_t)z * T_DIM + t0 + tid] = 1.f / Z;
    }

    // ---- ctx epilogue: acc2 * (1/Z) ----
#pragma unroll
    for (int i = 0; i < 4; i++) {
        int rl0 = warpM * 64 + i * 16 + lr;
        float inv0 = 1.f / (zred[rl0 * 4] + zred[rl0 * 4 + 1] +
                            zred[rl0 * 4 + 2] + zred[rl0 * 4 + 3]);
        float inv1 = 1.f / (zred[(rl0 + 8) * 4] + zred[(rl0 + 8) * 4 + 1] +
                            zred[(rl0 + 8) * 4 + 2] + zred[(rl0 + 8) * 4 + 3]);
#pragma unroll
        for (int j = 0; j < 2; j++) {
            int c0 = warpN * 16 + j * 8 + 2 * lc;
            __half* d0 = ctx + ((size_t)(t0 + rl0) * B_DIM + b) * E_DIM + h * HD_DIM + c0;
            __half* d1 = ctx + ((size_t)(t0 + rl0 + 8) * B_DIM + b) * E_DIM + h * HD_DIM + c0;
            *(__half2*)d0 = __floats2half2_rn(acc2[i][j][0] * inv0, acc2[i][j][1] * inv0);
            *(__half2*)d1 = __floats2half2_rn(acc2[i][j][2] * inv1, acc2[i][j][3] * inv1);
        }
    }
}

// ---------------- batched fp32 -> fp16 converts ----------------
__global__ void __launch_bounds__(256) k_cvt_in(
    const float* __restrict__ a, const float* __restrict__ b, const float* __restrict__ c,
    __half* __restrict__ oa, __half* __restrict__ ob, __half* __restrict__ oc, int n)
{
    const float* x; __half* y;
    if (blockIdx.z == 0)      { x = a; y = oa; }
    else if (blockIdx.z == 1) { x = b; y = ob; }
    else                      { x = c; y = oc; }
    int i = (blockIdx.x * 256 + threadIdx.x) * 8;
    if (i < n) {
        float4 v0 = *(const float4*)(x + i);
        float4 v1 = *(const float4*)(x + i + 4);
        union { __half2 h[4]; uint4 u; } p;
        p.h[0] = __floats2half2_rn(v0.x, v0.y);
        p.h[1] = __floats2half2_rn(v0.z, v0.w);
        p.h[2] = __floats2half2_rn(v1.x, v1.y);
        p.h[3] = __floats2half2_rn(v1.z, v1.w);
        *(uint4*)(y + i) = p.u;
    }
}

__global__ void __launch_bounds__(256) k_cvt_w(
    const float* __restrict__ a, const float* __restrict__ b,
    const float* __restrict__ c, const float* __restrict__ d,
    __half* __restrict__ oa, __half* __restrict__ ob,
    __half* __restrict__ oc, __half* __restrict__ od, int n)
{
    const float* x; __half* y;
    if (blockIdx.z == 0)      { x = a; y = oa; }
    else if (blockIdx.z == 1) { x = b; y = ob; }
    else if (blockIdx.z == 2) { x = c; y = oc; }
    else                      { x = d; y = od; }
    int i = (blockIdx.x * 256 + threadIdx.x) * 8;
    if (i < n) {
        float4 v0 = *(const float4*)(x + i);
        float4 v1 = *(const float4*)(x + i + 4);
        union { __half2 h[4]; uint4 u; } p;
        p.h[0] = __floats2half2_rn(v0.x, v0.y);
        p.h[1] = __floats2half2_rn(v0.z, v0.w);
        p.h[2] = __floats2half2_rn(v1.x, v1.y);
        p.h[3] = __floats2half2_rn(v1.z, v1.w);
        *(uint4*)(y + i) = p.u;
    }
}

// V transpose fp16: vt[(z*64+d)*S + s] = vh[(s*2+b)*E + h*64+d]
__global__ void __launch_bounds__(256) k_transpose_v(
    const __half* __restrict__ v, __half* __restrict__ vt)
{
    __shared__ __half t[32][34];
    int z = blockIdx.z, b = z >> 4, h = z & 15;
    int s0 = blockIdx.x * 32, d0 = blockIdx.y * 32;
    int lx = threadIdx.x & 31, ly = threadIdx.x >> 5;
#pragma unroll
    for (int i = 0; i < 32; i += 8) {
        int s = s0 + ly + i;
        t[ly + i][lx] = v[(size_t)(s * B_DIM + b) * E_DIM + h * HD_DIM + d0 + lx];
    }
    __syncthreads();
#pragma unroll
    for (int i = 0; i < 32; i += 8) {
        int d = d0 + ly + i;
        vt[((size_t)z * HD_DIM + d) * S_DIM + s0 + lx] = t[lx][ly + i];
    }
}

// ---------------- head-average from p~ and zinv ----------------
__global__ void __launch_bounds__(256) k_avg(
    const __half* __restrict__ ptil, const float* __restrict__ zinv,
    float* __restrict__ avgw)
{
    const int t = blockIdx.x;
    const int b = blockIdx.y;
    const int tid = threadIdx.x;

    // preload all 16 per-head 1/Z (independent LDGs)
    float inv[H_DIM];
#pragma unroll
    for (int h = 0; h < H_DIM; h++)
        inv[h] = __ldg(zinv + (size_t)(b * H_DIM + h) * T_DIM + t);

    float acc[8];
#pragma unroll
    for (int i = 0; i < 8; i++) acc[i] = 0.f;

    // fully unrolled: 16 independent LDG.128 for max MLP
    uint4 u[H_DIM];
#pragma unroll
    for (int h = 0; h < H_DIM; h++)
        u[h] = *(const uint4*)(ptil + ((size_t)(b * H_DIM + h) * T_DIM + t) * S_DIM + tid * 8);

#pragma unroll
    for (int h = 0; h < H_DIM; h++) {
        const __half2* hp = (const __half2*)&u[h];
#pragma unroll
        for (int q = 0; q < 4; q++) {
            float2 f = __half22float2(hp[q]);
            acc[2 * q]     += f.x * inv[h];
            acc[2 * q + 1] += f.y * inv[h];
        }
    }

    const float invH = 1.f / (float)H_DIM;
    float* arow = avgw + ((size_t)b * T_DIM + t) * S_DIM + tid * 8;
    float4 o0 = {acc[0] * invH, acc[1] * invH, acc[2] * invH, acc[3] * invH};
    float4 o1 = {acc[4] * invH, acc[5] * invH, acc[6] * invH, acc[7] * invH};
    *(float4*)(arow) = o0;
    *(float4*)(arow + 4) = o1;
}

// ---------------------------------------------------------------------------
extern "C" void kernel_launch(void* const* d_in, const int* in_sizes, int n_in,
                              void* d_out, int out_size)
{
    const float* query = (const float*)d_in[0];
    const float* key   = (const float*)d_in[1];
    const float* value = (const float*)d_in[2];
    const float* Wq = (const float*)d_in[3];
    const float* bq = (const float*)d_in[4];
    const float* Wk = (const float*)d_in[5];
    const float* bk = (const float*)d_in[6];
    const float* Wv = (const float*)d_in[7];
    const float* bv = (const float*)d_in[8];
    const float* Wo = (const float*)d_in[9];
    const float* bo = (const float*)d_in[10];

    float* out  = (float*)d_out;
    float* avgw = out + (size_t)MB_DIM * E_DIM;

    __half *xq, *xk, *xv, *wq, *wk, *wv, *wo, *qh, *kh, *vh, *ctxh, *vt, *pt;
    float *zi;
    cudaGetSymbolAddress((void**)&xq,   g_xq);
    cudaGetSymbolAddress((void**)&xk,   g_xk);
    cudaGetSymbolAddress((void**)&xv,   g_xv);
    cudaGetSymbolAddress((void**)&wq,   g_wq);
    cudaGetSymbolAddress((void**)&wk,   g_wk);
    cudaGetSymbolAddress((void**)&wv,   g_wv);
    cudaGetSymbolAddress((void**)&wo,   g_wo);
    cudaGetSymbolAddress((void**)&qh,   g_qh);
    cudaGetSymbolAddress((void**)&kh,   g_kh);
    cudaGetSymbolAddress((void**)&vh,   g_vh);
    cudaGetSymbolAddress((void**)&ctxh, g_ctxh);
    cudaGetSymbolAddress((void**)&vt,   g_vt);
    cudaGetSymbolAddress((void**)&pt,   g_ptil);
    cudaGetSymbolAddress((void**)&zi,   g_zinv);

    const int SM_P3 = 3 * (128 + 128) * 72 * 2;   // 110592
    cudaFuncSetAttribute(k_proj3,  cudaFuncAttributeMaxDynamicSharedMemorySize, SM_P3);
    cudaFuncSetAttribute(k_proj_f, cudaFuncAttributeMaxDynamicSharedMemorySize, SM_P3);
    cudaFuncSetAttribute(k_attn,   cudaFuncAttributeMaxDynamicSharedMemorySize, SM_ATTN);

    const int NXE = MB_DIM * E_DIM;   // 4M
    const int NWW = E_DIM * E_DIM;    // 1M
    dim3 gci(NXE / 2048, 1, 3);
    k_cvt_in<<<gci, 256>>>(query, key, value, xq, xk, xv, NXE);
    dim3 gcw(NWW / 2048, 1, 4);
    k_cvt_w<<<gcw, 256>>>(Wq, Wk, Wv, Wo, wq, wk, wv, wo, NWW);

    dim3 gp3(E_DIM / 128, MB_DIM / 128, 3);             // (8, 32, 3)
    k_proj3<<<gp3, 256, SM_P3>>>(xq, xk, xv, wq, wk, wv, bq, bk, bv, qh, kh, vh);

    dim3 gt(S_DIM / 32, HD_DIM / 32, B_DIM * H_DIM);    // (64, 2, 32)
    k_transpose_v<<<gt, 256>>>(vh, vt);

    dim3 gat(B_DIM * H_DIM, T_DIM / 128);               // (32, 16)
    k_attn<<<gat, 256, SM_ATTN>>>(qh, kh, vt, pt, zi, ctxh);

    dim3 gm(T_DIM, B_DIM);                              // (2048, 2)
    k_avg<<<gm, 256>>>(pt, zi, avgw);

    dim3 gp(E_DIM / 128, MB_DIM / 128);                 // (8, 32)
    k_proj_f<<<gp, 256, SM_P3>>>(ctxh, wo, bo, out);
}

// round 13
// speedup vs baseline: 1.7746x; 1.0596x over previous
#include <cuda_runtime.h>
#include <cuda_fp16.h>
#include <cstdint>

#define T_DIM 2048
#define B_DIM 2
#define E_DIM 1024
#define H_DIM 16
#define HD_DIM 64
#define S_DIM 2048
#define MB_DIM (T_DIM * B_DIM)     // 4096
#define LDQ (B_DIM * E_DIM)        // 2048

// Static device scratch
__device__ __half g_xq[(size_t)MB_DIM * E_DIM];
__device__ __half g_xk[(size_t)MB_DIM * E_DIM];
__device__ __half g_xv[(size_t)MB_DIM * E_DIM];
__device__ __half g_wq[(size_t)E_DIM * E_DIM];
__device__ __half g_wk[(size_t)E_DIM * E_DIM];
__device__ __half g_wv[(size_t)E_DIM * E_DIM];
__device__ __half g_wo[(size_t)E_DIM * E_DIM];
__device__ __half g_qh[(size_t)MB_DIM * E_DIM];
__device__ __half g_kh[(size_t)MB_DIM * E_DIM];
__device__ __half g_vh[(size_t)MB_DIM * E_DIM];
__device__ __half g_ctxh[(size_t)MB_DIM * E_DIM];
__device__ __half g_vt[(size_t)B_DIM * H_DIM * HD_DIM * S_DIM];
__device__ __half g_ptil[(size_t)B_DIM * H_DIM * T_DIM * S_DIM];  // unnormalized exp scores
__device__ float  g_zinv[(size_t)B_DIM * H_DIM * T_DIM];          // per-row 1/Z

__device__ __forceinline__ uint32_t smem_u32(const void* p) {
    uint32_t a;
    asm("{ .reg .u64 t; cvta.to.shared.u64 t, %1; cvt.u32.u64 %0, t; }" : "=r"(a) : "l"(p));
    return a;
}
__device__ __forceinline__ void cp16(uint32_t dst, const void* src) {
    asm volatile("cp.async.ca.shared.global [%0], [%1], 16;" :: "r"(dst), "l"(src) : "memory");
}
#define CP_COMMIT() asm volatile("cp.async.commit_group;" ::: "memory")
#define CP_WAIT1()  asm volatile("cp.async.wait_group 1;" ::: "memory")
#define CP_WAIT0()  asm volatile("cp.async.wait_group 0;" ::: "memory")

__device__ __forceinline__ void ldm_x4(uint32_t r[4], uint32_t a) {
    asm volatile("ldmatrix.sync.aligned.m8n8.x4.shared.b16 {%0,%1,%2,%3}, [%4];"
        : "=r"(r[0]), "=r"(r[1]), "=r"(r[2]), "=r"(r[3]) : "r"(a));
}
__device__ __forceinline__ void mma_f16(float c[4], const uint32_t a[4], const uint32_t b[2]) {
    asm volatile(
        "mma.sync.aligned.m16n8k16.row.col.f32.f16.f16.f32 "
        "{%0,%1,%2,%3}, {%4,%5,%6,%7}, {%8,%9}, {%0,%1,%2,%3};"
        : "+f"(c[0]), "+f"(c[1]), "+f"(c[2]), "+f"(c[3])
        : "r"(a[0]), "r"(a[1]), "r"(a[2]), "r"(a[3]), "r"(b[0]), "r"(b[1]));
}
// ex2.approx.f32 — MUFU.EX2
__device__ __forceinline__ float ex2(float x) {
    float r;
    asm("ex2.approx.f32 %0, %1;" : "=f"(r) : "f"(x));
    return r;
}

// ---------------------------------------------------------------------------
// fp16 mma.sync GEMM core (projections). CMODE 0: fp32 out; 1: fp16 out.
// 3-stage cp.async pipeline, one __syncthreads per k-tile.
// ---------------------------------------------------------------------------
template <int BN, int WARPS_M, int WARPS_N, int CMODE>
__device__ __forceinline__ void mm_core(
    const __half* __restrict__ A, int lda,
    const __half* __restrict__ B, int ldb,
    void* Cp, int ldc,
    const float* __restrict__ bias, float alpha, int K)
{
    constexpr int BM = 128, BK = 64, PAD = 72;
    constexpr int WM = BM / WARPS_M, WN = BN / WARPS_N;
    constexpr int MF = WM / 16, NF = WN / 8;
    constexpr int NCA = (BM * BK / 8) / 256;
    constexpr int NCB = (BN * BK / 8) / 256;
    constexpr uint32_t ASTG = BM * PAD * 2;
    constexpr uint32_t BSTG = BN * PAD * 2;
    constexpr uint32_t STG  = ASTG + BSTG;

    extern __shared__ __align__(16) char dsm[];

    const int tid = threadIdx.x;
    const int wid = tid >> 5;
    const int lane = tid & 31;
    const int lr = lane >> 2;
    const int lc = lane & 3;
    const int warpM = wid % WARPS_M;
    const int warpN = wid / WARPS_M;
    const int m0 = blockIdx.y * BM;
    const int n0 = blockIdx.x * BN;

    const uint32_t smb = smem_u32(dsm);

    float acc[MF][NF][4];
#pragma unroll
    for (int i = 0; i < MF; i++)
#pragma unroll
        for (int j = 0; j < NF; j++)
#pragma unroll
            for (int q = 0; q < 4; q++) acc[i][j][q] = 0.f;

    auto ldgsts = [&](int kt, int p) {
        const int k0 = kt * BK;
        const uint32_t ab = smb + (uint32_t)p * STG;
        const uint32_t bb = ab + ASTG;
#pragma unroll
        for (int i = 0; i < NCA; i++) {
            int ch = tid + i * 256, r = ch >> 3, c = (ch & 7) * 8;
            cp16(ab + (uint32_t)(r * PAD + c) * 2,
                 A + (size_t)(m0 + r) * lda + k0 + c);
        }
#pragma unroll
        for (int i = 0; i < NCB; i++) {
            int ch = tid + i * 256, r = ch >> 3, c = (ch & 7) * 8;
            cp16(bb + (uint32_t)(r * PAD + c) * 2,
                 B + (size_t)(n0 + r) * ldb + k0 + c);
        }
    };

    auto compute = [&](int p) {
        const uint32_t ab = smb + (uint32_t)p * STG;
        const uint32_t bb = ab + ASTG;
#pragma unroll
        for (int ks = 0; ks < BK / 16; ks++) {
            const int kh = ks * 16;
            uint32_t af[MF][4], bf[NF][2];
#pragma unroll
            for (int i = 0; i < MF; i++) {
                uint32_t off = (uint32_t)((warpM * WM + i * 16 + (lane & 15)) * PAD +
                                          kh + ((lane >> 4) << 3));
                ldm_x4(af[i], ab + (off << 1));
            }
#pragma unroll
            for (int j = 0; j < NF; j += 2) {
                int row = warpN * WN + (j + (lane >> 4)) * 8 + (lane & 7);
                int col = kh + ((lane >> 3) & 1) * 8;
                uint32_t r4[4];
                ldm_x4(r4, bb + ((uint32_t)(row * PAD + col) << 1));
                bf[j][0] = r4[0]; bf[j][1] = r4[1];
                bf[j + 1][0] = r4[2]; bf[j + 1][1] = r4[3];
            }
#pragma unroll
            for (int i = 0; i < MF; i++)
#pragma unroll
                for (int j = 0; j < NF; j++)
                    mma_f16(acc[i][j], af[i], bf[j]);
        }
    };

    const int ktiles = K / BK;
    ldgsts(0, 0);
    CP_COMMIT();
    if (ktiles > 1) ldgsts(1, 1);
    CP_COMMIT();
    for (int kt = 0; kt < ktiles; kt++) {
        if (kt + 1 < ktiles) { CP_WAIT1(); } else { CP_WAIT0(); }
        __syncthreads();
        if (kt + 2 < ktiles) ldgsts(kt + 2, (kt + 2) % 3);
        CP_COMMIT();
        compute(kt % 3);
    }

#pragma unroll
    for (int i = 0; i < MF; i++) {
        int r0 = m0 + warpM * WM + i * 16 + lr;
#pragma unroll
        for (int j = 0; j < NF; j++) {
            int c0 = n0 + warpN * WN + j * 8 + 2 * lc;
            float2 bv = bias ? *(const float2*)(bias + c0) : make_float2(0.f, 0.f);
            float x0 = acc[i][j][0] * alpha + bv.x;
            float x1 = acc[i][j][1] * alpha + bv.y;
            float x2 = acc[i][j][2] * alpha + bv.x;
            float x3 = acc[i][j][3] * alpha + bv.y;
            if constexpr (CMODE == 1) {
                __half* C = (__half*)Cp;
                *(__half2*)(C + (size_t)r0 * ldc + c0) = __floats2half2_rn(x0, x1);
                *(__half2*)(C + (size_t)(r0 + 8) * ldc + c0) = __floats2half2_rn(x2, x3);
            } else {
                float* C = (float*)Cp;
                *(float2*)(C + (size_t)r0 * ldc + c0) = make_float2(x0, x1);
                *(float2*)(C + (size_t)(r0 + 8) * ldc + c0) = make_float2(x2, x3);
            }
        }
    }
}

// ---------------- projection wrappers ----------------
__global__ void __launch_bounds__(256, 2) k_proj3(
    const __half* __restrict__ xq, const __half* __restrict__ xk, const __half* __restrict__ xv,
    const __half* __restrict__ wq, const __half* __restrict__ wk, const __half* __restrict__ wv,
    const float* __restrict__ bq, const float* __restrict__ bk, const float* __restrict__ bv,
    __half* __restrict__ qh, __half* __restrict__ kh, __half* __restrict__ vh)
{
    const __half* A; const __half* W; const float* bias; __half* C;
    if (blockIdx.z == 0)      { A = xq; W = wq; bias = bq; C = qh; }
    else if (blockIdx.z == 1) { A = xk; W = wk; bias = bk; C = kh; }
    else                      { A = xv; W = wv; bias = bv; C = vh; }
    mm_core<128, 2, 4, 1>(A, E_DIM, W, E_DIM, C, E_DIM, bias, 1.f, E_DIM);
}

__global__ void __launch_bounds__(256, 2) k_proj_f(
    const __half* __restrict__ A, const __half* __restrict__ W,
    const float* __restrict__ bias, float* __restrict__ C)
{
    mm_core<128, 2, 4, 0>(A, E_DIM, W, E_DIM, C, E_DIM, bias, 1.f, E_DIM);
}

// ---------------------------------------------------------------------------
// Fused attention: QK^T + exp + p~ store + Z + (p~ @ V) per (z, 128-row tblock).
// 256 threads = 8 warps, warpM=4 x warpN=2 (balanced ldmatrix), q A-frags
// hoisted to registers for all 32 s-chunks of 64.
// ---------------------------------------------------------------------------
#define ACH 64
#define NCHK (S_DIM / ACH)     // 32
// smem byte offsets (pitch 72 halfs everywhere)
#define QOFF 0
#define QSZ  (128 * 72 * 2)            // 18432
#define KOFF QSZ                        // 18432
#define KSZ  (64 * 72 * 2)             // 9216 per buf, 3 bufs
#define VOFF (KOFF + 3 * KSZ)          // 46080
#define VSZ  (64 * 72 * 2)             // 9216 per buf, 3 bufs
#define POFF (VOFF + 3 * VSZ)          // 73728
#define PSZ  (128 * 72 * 2)            // 18432
#define ZOFF (POFF + PSZ)              // 92160
#define SM_ATTN (ZOFF + 128 * 2 * 4)   // 93184

// exp(x*0.125) == exp2(x * 0.125*log2(e))
#define EXP2_SCALE 0.18033688011112042f

__global__ void __launch_bounds__(256) k_attn(
    const __half* __restrict__ qh, const __half* __restrict__ kh,
    const __half* __restrict__ vt, __half* __restrict__ ptil,
    float* __restrict__ zinv, __half* __restrict__ ctx)
{
    extern __shared__ __align__(16) char dsm[];
    const uint32_t smb = smem_u32(dsm);
    float* zred = (float*)(dsm + ZOFF);   // [128][2]

    const int tid = threadIdx.x;
    const int wid = tid >> 5;
    const int lane = tid & 31;
    const int lr = lane >> 2, lc = lane & 3;
    const int warpM = wid & 3;            // 4
    const int warpN = wid >> 2;           // 2
    const int z  = blockIdx.x;            // b*16 + h
    const int t0 = blockIdx.y * 128;
    const int b = z >> 4, h = z & 15;

    const __half* qptr = qh + (size_t)b * E_DIM + h * HD_DIM;   // row stride LDQ (t)
    const __half* kptr = kh + (size_t)b * E_DIM + h * HD_DIM;   // row stride LDQ (s)
    const __half* vptr = vt + (size_t)z * HD_DIM * S_DIM;       // [64][S]
    __half* pout = ptil + ((size_t)z * T_DIM + t0) * S_DIM;

    auto ldgK = [&](int c) {
        const int s0 = c * ACH;
        const uint32_t kb = smb + KOFF + (uint32_t)(c % 3) * KSZ;
#pragma unroll
        for (int i = 0; i < 2; i++) {
            int ch = tid + i * 256, r = ch >> 3, cc = (ch & 7) * 8;
            cp16(kb + (uint32_t)(r * 72 + cc) * 2,
                 kptr + (size_t)(s0 + r) * LDQ + cc);
        }
    };
    auto ldgV = [&](int c) {
        const int s0 = c * ACH;
        const uint32_t vb = smb + VOFF + (uint32_t)(c % 3) * VSZ;
#pragma unroll
        for (int i = 0; i < 2; i++) {
            int ch = tid + i * 256, r = ch >> 3, cc = (ch & 7) * 8;
            cp16(vb + (uint32_t)(r * 72 + cc) * 2,
                 vptr + (size_t)r * S_DIM + s0 + cc);
        }
    };

    // group 0: q + chunk 0; group 1: chunk 1
#pragma unroll
    for (int i = 0; i < 4; i++) {
        int ch = tid + i * 256, r = ch >> 3, cc = (ch & 7) * 8;
        cp16(smb + QOFF + (uint32_t)(r * 72 + cc) * 2,
             qptr + (size_t)(t0 + r) * LDQ + cc);
    }
    ldgK(0); ldgV(0);
    CP_COMMIT();
    ldgK(1); ldgV(1);
    CP_COMMIT();

    uint32_t afq[4][2][4];                 // q fragments, loaded once
    float acc2[2][4][4];
#pragma unroll
    for (int i = 0; i < 2; i++)
#pragma unroll
        for (int j = 0; j < 4; j++)
#pragma unroll
            for (int q = 0; q < 4; q++) acc2[i][j][q] = 0.f;
    float z0[2] = {0.f, 0.f}, z1[2] = {0.f, 0.f};

    for (int c = 0; c < NCHK; c++) {
        if (c + 1 < NCHK) { CP_WAIT1(); } else { CP_WAIT0(); }
        __syncthreads();

        if (c == 0) {
            // hoist q A-frags for the whole t-block
#pragma unroll
            for (int ks = 0; ks < 4; ks++)
#pragma unroll
                for (int i = 0; i < 2; i++) {
                    uint32_t off = (uint32_t)((warpM * 32 + i * 16 + (lane & 15)) * 72 +
                                              ks * 16 + ((lane >> 4) << 3));
                    ldm_x4(afq[ks][i], smb + QOFF + (off << 1));
                }
        }

        if (c + 2 < NCHK) { ldgK(c + 2); ldgV(c + 2); }
        CP_COMMIT();

        const uint32_t kb = smb + KOFF + (uint32_t)(c % 3) * KSZ;
        const uint32_t vb = smb + VOFF + (uint32_t)(c % 3) * VSZ;
        const int s0 = c * ACH;

        // ---- mma1: q[32rows x64] @ K^T -> acc1[32 x 32cols] per warp ----
        float acc1[2][4][4];
#pragma unroll
        for (int i = 0; i < 2; i++)
#pragma unroll
            for (int j = 0; j < 4; j++)
#pragma unroll
                for (int q = 0; q < 4; q++) acc1[i][j][q] = 0.f;

#pragma unroll
        for (int ks = 0; ks < 4; ks++) {
            const int khc = ks * 16;
            uint32_t bf[4][2];
#pragma unroll
            for (int j = 0; j < 4; j += 2) {
                int row = warpN * 32 + (j + (lane >> 4)) * 8 + (lane & 7);
                int col = khc + ((lane >> 3) & 1) * 8;
                uint32_t r4[4];
                ldm_x4(r4, kb + ((uint32_t)(row * 72 + col) << 1));
                bf[j][0] = r4[0]; bf[j][1] = r4[1];
                bf[j + 1][0] = r4[2]; bf[j + 1][1] = r4[3];
            }
#pragma unroll
            for (int i = 0; i < 2; i++)
#pragma unroll
                for (int j = 0; j < 4; j++)
                    mma_f16(acc1[i][j], afq[ks][i], bf[j]);
        }

        // ---- exp (EX2) + Z partials + store p~ to smem ----
#pragma unroll
        for (int i = 0; i < 2; i++) {
            int rl0 = warpM * 32 + i * 16 + lr;
#pragma unroll
            for (int j = 0; j < 4; j++) {
                int c0 = warpN * 32 + j * 8 + 2 * lc;
                float x0 = ex2(acc1[i][j][0] * EXP2_SCALE);
                float x1 = ex2(acc1[i][j][1] * EXP2_SCALE);
                float x2 = ex2(acc1[i][j][2] * EXP2_SCALE);
                float x3 = ex2(acc1[i][j][3] * EXP2_SCALE);
                z0[i] += x0 + x1;
                z1[i] += x2 + x3;
                *(__half2*)(dsm + POFF + (uint32_t)(rl0 * 72 + c0) * 2) =
                    __floats2half2_rn(x0, x1);
                *(__half2*)(dsm + POFF + (uint32_t)((rl0 + 8) * 72 + c0) * 2) =
                    __floats2half2_rn(x2, x3);
            }
        }
        __syncthreads();   // p tile visible

        // ---- coalesced p~ gmem store from smem (4 x LDS.128 + STG.128) ----
#pragma unroll
        for (int i = 0; i < 4; i++) {
            int idx = tid + i * 256;          // 0..1023
            int row = idx >> 3, col8 = (idx & 7) * 8;
            uint4 v = *(const uint4*)(dsm + POFF + (uint32_t)(row * 72 + col8) * 2);
            *(uint4*)(pout + (size_t)row * S_DIM + s0 + col8) = v;
        }

        // ---- mma2: p[32 x 64s] @ V^T[32d x 64s] -> acc2 += ----
#pragma unroll
        for (int ks = 0; ks < 4; ks++) {
            const int khc = ks * 16;
            uint32_t af[2][4], bf[4][2];
#pragma unroll
            for (int i = 0; i < 2; i++) {
                uint32_t off = (uint32_t)((warpM * 32 + i * 16 + (lane & 15)) * 72 +
                                          khc + ((lane >> 4) << 3));
                ldm_x4(af[i], smb + POFF + (off << 1));
            }
#pragma unroll
            for (int j = 0; j < 4; j += 2) {
                int row = warpN * 32 + (j + (lane >> 4)) * 8 + (lane & 7);
                int col = khc + ((lane >> 3) & 1) * 8;
                uint32_t r4[4];
                ldm_x4(r4, vb + ((uint32_t)(row * 72 + col) << 1));
                bf[j][0] = r4[0]; bf[j][1] = r4[1];
                bf[j + 1][0] = r4[2]; bf[j + 1][1] = r4[3];
            }
#pragma unroll
            for (int i = 0; i < 2; i++)
#pragma unroll
                for (int j = 0; j < 4; j++)
                    mma_f16(acc2[i][j], af[i], bf[j]);
        }
    }

    // ---- Z reduce across quad + warps ----
#pragma unroll
    for (int i = 0; i < 2; i++) {
        z0[i] += __shfl_xor_sync(0xffffffffu, z0[i], 1);
        z0[i] += __shfl_xor_sync(0xffffffffu, z0[i], 2);
        z1[i] += __shfl_xor_sync(0xffffffffu, z1[i], 1);
        z1[i] += __shfl_xor_sync(0xffffffffu, z1[i], 2);
    }
    if (lc == 0) {
#pragma unroll
        for (int i = 0; i < 2; i++) {
            int rl0 = warpM * 32 + i * 16 + lr;
            zred[rl0 * 2 + warpN] = z0[i];
            zred[(rl0 + 8) * 2 + warpN] = z1[i];
        }
    }
    __syncthreads();

    if (tid < 128) {
        float Z = zred[tid * 2] + zred[tid * 2 + 1];
        zinv[(size_t)z * T_DIM + t0 + tid] = 1.f / Z;
    }

    // ---- ctx epilogue: acc2 * (1/Z) ----
#pragma unroll
    for (int i = 0; i < 2; i++) {
        int rl0 = warpM * 32 + i * 16 + lr;
        float inv0 = 1.f / (zred[rl0 * 2] + zred[rl0 * 2 + 1]);
        float inv1 = 1.f / (zred[(rl0 + 8) * 2] + zred[(rl0 + 8) * 2 + 1]);
#pragma unroll
        for (int j = 0; j < 4; j++) {
            int c0 = warpN * 32 + j * 8 + 2 * lc;
            __half* d0 = ctx + ((size_t)(t0 + rl0) * B_DIM + b) * E_DIM + h * HD_DIM + c0;
            __half* d1 = ctx + ((size_t)(t0 + rl0 + 8) * B_DIM + b) * E_DIM + h * HD_DIM + c0;
            *(__half2*)d0 = __floats2half2_rn(acc2[i][j][0] * inv0, acc2[i][j][1] * inv0);
            *(__half2*)d1 = __floats2half2_rn(acc2[i][j][2] * inv1, acc2[i][j][3] * inv1);
        }
    }
}

// ---------------- batched fp32 -> fp16 converts ----------------
__global__ void __launch_bounds__(256) k_cvt_in(
    const float* __restrict__ a, const float* __restrict__ b, const float* __restrict__ c,
    __half* __restrict__ oa, __half* __restrict__ ob, __half* __restrict__ oc, int n)
{
    const float* x; __half* y;
    if (blockIdx.z == 0)      { x = a; y = oa; }
    else if (blockIdx.z == 1) { x = b; y = ob; }
    else                      { x = c; y = oc; }
    int i = (blockIdx.x * 256 + threadIdx.x) * 8;
    if (i < n) {
        float4 v0 = *(const float4*)(x + i);
        float4 v1 = *(const float4*)(x + i + 4);
        union { __half2 h[4]; uint4 u; } p;
        p.h[0] = __floats2half2_rn(v0.x, v0.y);
        p.h[1] = __floats2half2_rn(v0.z, v0.w);
        p.h[2] = __floats2half2_rn(v1.x, v1.y);
        p.h[3] = __floats2half2_rn(v1.z, v1.w);
        *(uint4*)(y + i) = p.u;
    }
}

__global__ void __launch_bounds__(256) k_cvt_w(
    const float* __restrict__ a, const float* __restrict__ b,
    const float* __restrict__ c, const float* __restrict__ d,
    __half* __restrict__ oa, __half* __restrict__ ob,
    __half* __restrict__ oc, __half* __restrict__ od, int n)
{
    const float* x; __half* y;
    if (blockIdx.z == 0)      { x = a; y = oa; }
    else if (blockIdx.z == 1) { x = b; y = ob; }
    else if (blockIdx.z == 2) { x = c; y = oc; }
    else                      { x = d; y = od; }
    int i = (blockIdx.x * 256 + threadIdx.x) * 8;
    if (i < n) {
        float4 v0 = *(const float4*)(x + i);
        float4 v1 = *(const float4*)(x + i + 4);
        union { __half2 h[4]; uint4 u; } p;
        p.h[0] = __floats2half2_rn(v0.x, v0.y);
        p.h[1] = __floats2half2_rn(v0.z, v0.w);
        p.h[2] = __floats2half2_rn(v1.x, v1.y);
        p.h[3] = __floats2half2_rn(v1.z, v1.w);
        *(uint4*)(y + i) = p.u;
    }
}

// V transpose fp16: vt[(z*64+d)*S + s] = vh[(s*2+b)*E + h*64+d]
__global__ void __launch_bounds__(256) k_transpose_v(
    const __half* __restrict__ v, __half* __restrict__ vt)
{
    __shared__ __half t[32][34];
    int z = blockIdx.z, b = z >> 4, h = z & 15;
    int s0 = blockIdx.x * 32, d0 = blockIdx.y * 32;
    int lx = threadIdx.x & 31, ly = threadIdx.x >> 5;
#pragma unroll
    for (int i = 0; i < 32; i += 8) {
        int s = s0 + ly + i;
        t[ly + i][lx] = v[(size_t)(s * B_DIM + b) * E_DIM + h * HD_DIM + d0 + lx];
    }
    __syncthreads();
#pragma unroll
    for (int i = 0; i < 32; i += 8) {
        int d = d0 + ly + i;
        vt[((size_t)z * HD_DIM + d) * S_DIM + s0 + lx] = t[lx][ly + i];
    }
}

// ---------------- head-average from p~ and zinv ----------------
__global__ void __launch_bounds__(256) k_avg(
    const __half* __restrict__ ptil, const float* __restrict__ zinv,
    float* __restrict__ avgw)
{
    const int t = blockIdx.x;
    const int b = blockIdx.y;
    const int tid = threadIdx.x;

    // preload all 16 per-head 1/Z (independent LDGs)
    float inv[H_DIM];
#pragma unroll
    for (int h = 0; h < H_DIM; h++)
        inv[h] = __ldg(zinv + (size_t)(b * H_DIM + h) * T_DIM + t);

    float acc[8];
#pragma unroll
    for (int i = 0; i < 8; i++) acc[i] = 0.f;

    // fully unrolled: 16 independent LDG.128 for max MLP
    uint4 u[H_DIM];
#pragma unroll
    for (int h = 0; h < H_DIM; h++)
        u[h] = *(const uint4*)(ptil + ((size_t)(b * H_DIM + h) * T_DIM + t) * S_DIM + tid * 8);

#pragma unroll
    for (int h = 0; h < H_DIM; h++) {
        const __half2* hp = (const __half2*)&u[h];
#pragma unroll
        for (int q = 0; q < 4; q++) {
            float2 f = __half22float2(hp[q]);
            acc[2 * q]     += f.x * inv[h];
            acc[2 * q + 1] += f.y * inv[h];
        }
    }

    const float invH = 1.f / (float)H_DIM;
    float* arow = avgw + ((size_t)b * T_DIM + t) * S_DIM + tid * 8;
    float4 o0 = {acc[0] * invH, acc[1] * invH, acc[2] * invH, acc[3] * invH};
    float4 o1 = {acc[4] * invH, acc[5] * invH, acc[6] * invH, acc[7] * invH};
    *(float4*)(arow) = o0;
    *(float4*)(arow + 4) = o1;
}

// ---------------------------------------------------------------------------
extern "C" void kernel_launch(void* const* d_in, const int* in_sizes, int n_in,
                              void* d_out, int out_size)
{
    const float* query = (const float*)d_in[0];
    const float* key   = (const float*)d_in[1];
    const float* value = (const float*)d_in[2];
    const float* Wq = (const float*)d_in[3];
    const float* bq = (const float*)d_in[4];
    const float* Wk = (const float*)d_in[5];
    const float* bk = (const float*)d_in[6];
    const float* Wv = (const float*)d_in[7];
    const float* bv = (const float*)d_in[8];
    const float* Wo = (const float*)d_in[9];
    const float* bo = (const float*)d_in[10];

    float* out  = (float*)d_out;
    float* avgw = out + (size_t)MB_DIM * E_DIM;

    __half *xq, *xk, *xv, *wq, *wk, *wv, *wo, *qh, *kh, *vh, *ctxh, *vt, *pt;
    float *zi;
    cudaGetSymbolAddress((void**)&xq,   g_xq);
    cudaGetSymbolAddress((void**)&xk,   g_xk);
    cudaGetSymbolAddress((void**)&xv,   g_xv);
    cudaGetSymbolAddress((void**)&wq,   g_wq);
    cudaGetSymbolAddress((void**)&wk,   g_wk);
    cudaGetSymbolAddress((void**)&wv,   g_wv);
    cudaGetSymbolAddress((void**)&wo,   g_wo);
    cudaGetSymbolAddress((void**)&qh,   g_qh);
    cudaGetSymbolAddress((void**)&kh,   g_kh);
    cudaGetSymbolAddress((void**)&vh,   g_vh);
    cudaGetSymbolAddress((void**)&ctxh, g_ctxh);
    cudaGetSymbolAddress((void**)&vt,   g_vt);
    cudaGetSymbolAddress((void**)&pt,   g_ptil);
    cudaGetSymbolAddress((void**)&zi,   g_zinv);

    const int SM_P3 = 3 * (128 + 128) * 72 * 2;   // 110592
    cudaFuncSetAttribute(k_proj3,  cudaFuncAttributeMaxDynamicSharedMemorySize, SM_P3);
    cudaFuncSetAttribute(k_proj_f, cudaFuncAttributeMaxDynamicSharedMemorySize, SM_P3);
    cudaFuncSetAttribute(k_attn,   cudaFuncAttributeMaxDynamicSharedMemorySize, SM_ATTN);

    const int NXE = MB_DIM * E_DIM;   // 4M
    const int NWW = E_DIM * E_DIM;    // 1M
    dim3 gci(NXE / 2048, 1, 3);
    k_cvt_in<<<gci, 256>>>(query, key, value, xq, xk, xv, NXE);
    dim3 gcw(NWW / 2048, 1, 4);
    k_cvt_w<<<gcw, 256>>>(Wq, Wk, Wv, Wo, wq, wk, wv, wo, NWW);

    dim3 gp3(E_DIM / 128, MB_DIM / 128, 3);             // (8, 32, 3)
    k_proj3<<<gp3, 256, SM_P3>>>(xq, xk, xv, wq, wk, wv, bq, bk, bv, qh, kh, vh);

    dim3 gt(S_DIM / 32, HD_DIM / 32, B_DIM * H_DIM);    // (64, 2, 32)
    k_transpose_v<<<gt, 256>>>(vh, vt);

    dim3 gat(B_DIM * H_DIM, T_DIM / 128);               // (32, 16)
    k_attn<<<gat, 256, SM_ATTN>>>(qh, kh, vt, pt, zi, ctxh);

    dim3 gm(T_DIM, B_DIM);                              // (2048, 2)
    k_avg<<<gm, 256>>>(pt, zi, avgw);

    dim3 gp(E_DIM / 128, MB_DIM / 128);                 // (8, 32)
    k_proj_f<<<gp, 256, SM_P3>>>(ctxh, wo, bo, out);
}

// round 14
// speedup vs baseline: 1.8065x; 1.0179x over previous
#include <cuda_runtime.h>
#include <cuda_fp16.h>
#include <cstdint>

#define T_DIM 2048
#define B_DIM 2
#define E_DIM 1024
#define H_DIM 16
#define HD_DIM 64
#define S_DIM 2048
#define MB_DIM (T_DIM * B_DIM)     // 4096
#define LDQ (B_DIM * E_DIM)        // 2048

// Static device scratch
__device__ __half g_xq[(size_t)MB_DIM * E_DIM];
__device__ __half g_xk[(size_t)MB_DIM * E_DIM];
__device__ __half g_xv[(size_t)MB_DIM * E_DIM];
__device__ __half g_wq[(size_t)E_DIM * E_DIM];
__device__ __half g_wk[(size_t)E_DIM * E_DIM];
__device__ __half g_wv[(size_t)E_DIM * E_DIM];
__device__ __half g_wo[(size_t)E_DIM * E_DIM];
__device__ __half g_qh[(size_t)MB_DIM * E_DIM];
__device__ __half g_kh[(size_t)MB_DIM * E_DIM];
__device__ __half g_vh[(size_t)MB_DIM * E_DIM];
__device__ __half g_ctxh[(size_t)MB_DIM * E_DIM];
__device__ __half g_vt[(size_t)B_DIM * H_DIM * HD_DIM * S_DIM];
__device__ __half g_ptil[(size_t)B_DIM * H_DIM * T_DIM * S_DIM];  // unnormalized exp scores
__device__ float  g_zinv[(size_t)B_DIM * H_DIM * T_DIM];          // per-row 1/Z

__device__ __forceinline__ uint32_t smem_u32(const void* p) {
    uint32_t a;
    asm("{ .reg .u64 t; cvta.to.shared.u64 t, %1; cvt.u32.u64 %0, t; }" : "=r"(a) : "l"(p));
    return a;
}
__device__ __forceinline__ void cp16(uint32_t dst, const void* src) {
    asm volatile("cp.async.ca.shared.global [%0], [%1], 16;" :: "r"(dst), "l"(src) : "memory");
}
#define CP_COMMIT() asm volatile("cp.async.commit_group;" ::: "memory")
#define CP_WAIT1()  asm volatile("cp.async.wait_group 1;" ::: "memory")
#define CP_WAIT0()  asm volatile("cp.async.wait_group 0;" ::: "memory")

__device__ __forceinline__ void ldm_x4(uint32_t r[4], uint32_t a) {
    asm volatile("ldmatrix.sync.aligned.m8n8.x4.shared.b16 {%0,%1,%2,%3}, [%4];"
        : "=r"(r[0]), "=r"(r[1]), "=r"(r[2]), "=r"(r[3]) : "r"(a));
}
__device__ __forceinline__ void mma_f16(float c[4], const uint32_t a[4], const uint32_t b[2]) {
    asm volatile(
        "mma.sync.aligned.m16n8k16.row.col.f32.f16.f16.f32 "
        "{%0,%1,%2,%3}, {%4,%5,%6,%7}, {%8,%9}, {%0,%1,%2,%3};"
        : "+f"(c[0]), "+f"(c[1]), "+f"(c[2]), "+f"(c[3])
        : "r"(a[0]), "r"(a[1]), "r"(a[2]), "r"(a[3]), "r"(b[0]), "r"(b[1]));
}
// ex2.approx.f32 — MUFU.EX2
__device__ __forceinline__ float ex2(float x) {
    float r;
    asm("ex2.approx.f32 %0, %1;" : "=f"(r) : "f"(x));
    return r;
}

// ---------------------------------------------------------------------------
// fp16 mma.sync GEMM core (projections). CMODE 0: fp32 out; 1: fp16 out.
// 3-stage cp.async pipeline, one __syncthreads per k-tile. m0/n0 passed in.
// ---------------------------------------------------------------------------
template <int BN, int WARPS_M, int WARPS_N, int CMODE>
__device__ __forceinline__ void mm_core(
    const __half* __restrict__ A, int lda,
    const __half* __restrict__ B, int ldb,
    void* Cp, int ldc,
    const float* __restrict__ bias, float alpha, int K,
    int m0, int n0)
{
    constexpr int BM = 128, BK = 64, PAD = 72;
    constexpr int WM = BM / WARPS_M, WN = BN / WARPS_N;
    constexpr int MF = WM / 16, NF = WN / 8;
    constexpr int NCA = (BM * BK / 8) / 256;
    constexpr int NCB = (BN * BK / 8) / 256;
    constexpr uint32_t ASTG = BM * PAD * 2;
    constexpr uint32_t BSTG = BN * PAD * 2;
    constexpr uint32_t STG  = ASTG + BSTG;

    extern __shared__ __align__(16) char dsm[];

    const int tid = threadIdx.x;
    const int wid = tid >> 5;
    const int lane = tid & 31;
    const int lr = lane >> 2;
    const int lc = lane & 3;
    const int warpM = wid % WARPS_M;
    const int warpN = wid / WARPS_M;

    const uint32_t smb = smem_u32(dsm);

    float acc[MF][NF][4];
#pragma unroll
    for (int i = 0; i < MF; i++)
#pragma unroll
        for (int j = 0; j < NF; j++)
#pragma unroll
            for (int q = 0; q < 4; q++) acc[i][j][q] = 0.f;

    auto ldgsts = [&](int kt, int p) {
        const int k0 = kt * BK;
        const uint32_t ab = smb + (uint32_t)p * STG;
        const uint32_t bb = ab + ASTG;
#pragma unroll
        for (int i = 0; i < NCA; i++) {
            int ch = tid + i * 256, r = ch >> 3, c = (ch & 7) * 8;
            cp16(ab + (uint32_t)(r * PAD + c) * 2,
                 A + (size_t)(m0 + r) * lda + k0 + c);
        }
#pragma unroll
        for (int i = 0; i < NCB; i++) {
            int ch = tid + i * 256, r = ch >> 3, c = (ch & 7) * 8;
            cp16(bb + (uint32_t)(r * PAD + c) * 2,
                 B + (size_t)(n0 + r) * ldb + k0 + c);
        }
    };

    auto compute = [&](int p) {
        const uint32_t ab = smb + (uint32_t)p * STG;
        const uint32_t bb = ab + ASTG;
#pragma unroll
        for (int ks = 0; ks < BK / 16; ks++) {
            const int kh = ks * 16;
            uint32_t af[MF][4], bf[NF][2];
#pragma unroll
            for (int i = 0; i < MF; i++) {
                uint32_t off = (uint32_t)((warpM * WM + i * 16 + (lane & 15)) * PAD +
                                          kh + ((lane >> 4) << 3));
                ldm_x4(af[i], ab + (off << 1));
            }
#pragma unroll
            for (int j = 0; j < NF; j += 2) {
                int row = warpN * WN + (j + (lane >> 4)) * 8 + (lane & 7);
                int col = kh + ((lane >> 3) & 1) * 8;
                uint32_t r4[4];
                ldm_x4(r4, bb + ((uint32_t)(row * PAD + col) << 1));
                bf[j][0] = r4[0]; bf[j][1] = r4[1];
                bf[j + 1][0] = r4[2]; bf[j + 1][1] = r4[3];
            }
#pragma unroll
            for (int i = 0; i < MF; i++)
#pragma unroll
                for (int j = 0; j < NF; j++)
                    mma_f16(acc[i][j], af[i], bf[j]);
        }
    };

    const int ktiles = K / BK;
    ldgsts(0, 0);
    CP_COMMIT();
    if (ktiles > 1) ldgsts(1, 1);
    CP_COMMIT();
    for (int kt = 0; kt < ktiles; kt++) {
        if (kt + 1 < ktiles) { CP_WAIT1(); } else { CP_WAIT0(); }
        __syncthreads();
        if (kt + 2 < ktiles) ldgsts(kt + 2, (kt + 2) % 3);
        CP_COMMIT();
        compute(kt % 3);
    }

#pragma unroll
    for (int i = 0; i < MF; i++) {
        int r0 = m0 + warpM * WM + i * 16 + lr;
#pragma unroll
        for (int j = 0; j < NF; j++) {
            int c0 = n0 + warpN * WN + j * 8 + 2 * lc;
            float2 bv = bias ? *(const float2*)(bias + c0) : make_float2(0.f, 0.f);
            float x0 = acc[i][j][0] * alpha + bv.x;
            float x1 = acc[i][j][1] * alpha + bv.y;
            float x2 = acc[i][j][2] * alpha + bv.x;
            float x3 = acc[i][j][3] * alpha + bv.y;
            if constexpr (CMODE == 1) {
                __half* C = (__half*)Cp;
                *(__half2*)(C + (size_t)r0 * ldc + c0) = __floats2half2_rn(x0, x1);
                *(__half2*)(C + (size_t)(r0 + 8) * ldc + c0) = __floats2half2_rn(x2, x3);
            } else {
                float* C = (float*)Cp;
                *(float2*)(C + (size_t)r0 * ldc + c0) = make_float2(x0, x1);
                *(float2*)(C + (size_t)(r0 + 8) * ldc + c0) = make_float2(x2, x3);
            }
        }
    }
}

// ---------------- projection wrappers ----------------
__global__ void __launch_bounds__(256, 2) k_proj3(
    const __half* __restrict__ xq, const __half* __restrict__ xk, const __half* __restrict__ xv,
    const __half* __restrict__ wq, const __half* __restrict__ wk, const __half* __restrict__ wv,
    const float* __restrict__ bq, const float* __restrict__ bk, const float* __restrict__ bv,
    __half* __restrict__ qh, __half* __restrict__ kh, __half* __restrict__ vh)
{
    const __half* A; const __half* W; const float* bias; __half* C;
    if (blockIdx.z == 0)      { A = xq; W = wq; bias = bq; C = qh; }
    else if (blockIdx.z == 1) { A = xk; W = wk; bias = bk; C = kh; }
    else                      { A = xv; W = wv; bias = bv; C = vh; }
    mm_core<128, 2, 4, 1>(A, E_DIM, W, E_DIM, C, E_DIM, bias, 1.f, E_DIM,
                          blockIdx.y * 128, blockIdx.x * 128);
}

// ---------------------------------------------------------------------------
// Merged final wave: first NPROJ blocks do out = ctxh @ Wo^T + bo (tensor-
// bound), remaining 4096 blocks do the avg_w reduction (DRAM-bound). The two
// are independent; merging overlaps tensor and memory pipes.
// ---------------------------------------------------------------------------
#define NPROJ 256   // (E/128) * (MB/128) = 8 * 32

__global__ void __launch_bounds__(256, 2) k_avg_proj(
    const __half* __restrict__ ctxh, const __half* __restrict__ wo,
    const float* __restrict__ bo, float* __restrict__ out,
    const __half* __restrict__ ptil, const float* __restrict__ zinv,
    float* __restrict__ avgw)
{
    const int bidx = blockIdx.x;
    if (bidx < NPROJ) {
        // projection tile: n-tile = bidx & 7, m-tile = bidx >> 3
        mm_core<128, 2, 4, 0>(ctxh, E_DIM, wo, E_DIM, out, E_DIM, bo, 1.f, E_DIM,
                              (bidx >> 3) * 128, (bidx & 7) * 128);
        return;
    }

    // ---- avg path ----
    const int j = bidx - NPROJ;       // 0..4095
    const int t = j & (T_DIM - 1);
    const int b = j >> 11;
    const int tid = threadIdx.x;

    float inv[H_DIM];
#pragma unroll
    for (int h = 0; h < H_DIM; h++)
        inv[h] = __ldg(zinv + (size_t)(b * H_DIM + h) * T_DIM + t);

    float acc[8];
#pragma unroll
    for (int i = 0; i < 8; i++) acc[i] = 0.f;

    uint4 u[H_DIM];
#pragma unroll
    for (int h = 0; h < H_DIM; h++)
        u[h] = *(const uint4*)(ptil + ((size_t)(b * H_DIM + h) * T_DIM + t) * S_DIM + tid * 8);

#pragma unroll
    for (int h = 0; h < H_DIM; h++) {
        const __half2* hp = (const __half2*)&u[h];
#pragma unroll
        for (int q = 0; q < 4; q++) {
            float2 f = __half22float2(hp[q]);
            acc[2 * q]     += f.x * inv[h];
            acc[2 * q + 1] += f.y * inv[h];
        }
    }

    const float invH = 1.f / (float)H_DIM;
    float* arow = avgw + ((size_t)b * T_DIM + t) * S_DIM + tid * 8;
    float4 o0 = {acc[0] * invH, acc[1] * invH, acc[2] * invH, acc[3] * invH};
    float4 o1 = {acc[4] * invH, acc[5] * invH, acc[6] * invH, acc[7] * invH};
    *(float4*)(arow) = o0;
    *(float4*)(arow + 4) = o1;
}

// ---------------------------------------------------------------------------
// Fused attention: QK^T + exp + p~ store + Z + (p~ @ V) per (z, 128-row tblock).
// 256 threads = 8 warps, warpM=4 x warpN=2, q A-frags hoisted. 32 s-chunks.
// ---------------------------------------------------------------------------
#define ACH 64
#define NCHK (S_DIM / ACH)     // 32
#define QOFF 0
#define QSZ  (128 * 72 * 2)            // 18432
#define KOFF QSZ                        // 18432
#define KSZ  (64 * 72 * 2)             // 9216 per buf, 3 bufs
#define VOFF (KOFF + 3 * KSZ)          // 46080
#define VSZ  (64 * 72 * 2)             // 9216 per buf, 3 bufs
#define POFF (VOFF + 3 * VSZ)          // 73728
#define PSZ  (128 * 72 * 2)            // 18432
#define ZOFF (POFF + PSZ)              // 92160
#define SM_ATTN (ZOFF + 128 * 2 * 4)   // 93184

#define EXP2_SCALE 0.18033688011112042f

__global__ void __launch_bounds__(256) k_attn(
    const __half* __restrict__ qh, const __half* __restrict__ kh,
    const __half* __restrict__ vt, __half* __restrict__ ptil,
    float* __restrict__ zinv, __half* __restrict__ ctx)
{
    extern __shared__ __align__(16) char dsm[];
    const uint32_t smb = smem_u32(dsm);
    float* zred = (float*)(dsm + ZOFF);   // [128][2]

    const int tid = threadIdx.x;
    const int wid = tid >> 5;
    const int lane = tid & 31;
    const int lr = lane >> 2, lc = lane & 3;
    const int warpM = wid & 3;            // 4
    const int warpN = wid >> 2;           // 2
    const int z  = blockIdx.x;            // b*16 + h
    const int t0 = blockIdx.y * 128;
    const int b = z >> 4, h = z & 15;

    const __half* qptr = qh + (size_t)b * E_DIM + h * HD_DIM;
    const __half* kptr = kh + (size_t)b * E_DIM + h * HD_DIM;
    const __half* vptr = vt + (size_t)z * HD_DIM * S_DIM;
    __half* pout = ptil + ((size_t)z * T_DIM + t0) * S_DIM;

    auto ldgK = [&](int c) {
        const int s0 = c * ACH;
        const uint32_t kb = smb + KOFF + (uint32_t)(c % 3) * KSZ;
#pragma unroll
        for (int i = 0; i < 2; i++) {
            int ch = tid + i * 256, r = ch >> 3, cc = (ch & 7) * 8;
            cp16(kb + (uint32_t)(r * 72 + cc) * 2,
                 kptr + (size_t)(s0 + r) * LDQ + cc);
        }
    };
    auto ldgV = [&](int c) {
        const int s0 = c * ACH;
        const uint32_t vb = smb + VOFF + (uint32_t)(c % 3) * VSZ;
#pragma unroll
        for (int i = 0; i < 2; i++) {
            int ch = tid + i * 256, r = ch >> 3, cc = (ch & 7) * 8;
            cp16(vb + (uint32_t)(r * 72 + cc) * 2,
                 vptr + (size_t)r * S_DIM + s0 + cc);
        }
    };

#pragma unroll
    for (int i = 0; i < 4; i++) {
        int ch = tid + i * 256, r = ch >> 3, cc = (ch & 7) * 8;
        cp16(smb + QOFF + (uint32_t)(r * 72 + cc) * 2,
             qptr + (size_t)(t0 + r) * LDQ + cc);
    }
    ldgK(0); ldgV(0);
    CP_COMMIT();
    ldgK(1); ldgV(1);
    CP_COMMIT();

    uint32_t afq[4][2][4];
    float acc2[2][4][4];
#pragma unroll
    for (int i = 0; i < 2; i++)
#pragma unroll
        for (int j = 0; j < 4; j++)
#pragma unroll
            for (int q = 0; q < 4; q++) acc2[i][j][q] = 0.f;
    float z0[2] = {0.f, 0.f}, z1[2] = {0.f, 0.f};

    for (int c = 0; c < NCHK; c++) {
        if (c + 1 < NCHK) { CP_WAIT1(); } else { CP_WAIT0(); }
        __syncthreads();

        if (c == 0) {
#pragma unroll
            for (int ks = 0; ks < 4; ks++)
#pragma unroll
                for (int i = 0; i < 2; i++) {
                    uint32_t off = (uint32_t)((warpM * 32 + i * 16 + (lane & 15)) * 72 +
                                              ks * 16 + ((lane >> 4) << 3));
                    ldm_x4(afq[ks][i], smb + QOFF + (off << 1));
                }
        }

        if (c + 2 < NCHK) { ldgK(c + 2); ldgV(c + 2); }
        CP_COMMIT();

        const uint32_t kb = smb + KOFF + (uint32_t)(c % 3) * KSZ;
        const uint32_t vb = smb + VOFF + (uint32_t)(c % 3) * VSZ;
        const int s0 = c * ACH;

        float acc1[2][4][4];
#pragma unroll
        for (int i = 0; i < 2; i++)
#pragma unroll
            for (int j = 0; j < 4; j++)
#pragma unroll
                for (int q = 0; q < 4; q++) acc1[i][j][q] = 0.f;

#pragma unroll
        for (int ks = 0; ks < 4; ks++) {
            const int khc = ks * 16;
            uint32_t bf[4][2];
#pragma unroll
            for (int j = 0; j < 4; j += 2) {
                int row = warpN * 32 + (j + (lane >> 4)) * 8 + (lane & 7);
                int col = khc + ((lane >> 3) & 1) * 8;
                uint32_t r4[4];
                ldm_x4(r4, kb + ((uint32_t)(row * 72 + col) << 1));
                bf[j][0] = r4[0]; bf[j][1] = r4[1];
                bf[j + 1][0] = r4[2]; bf[j + 1][1] = r4[3];
            }
#pragma unroll
            for (int i = 0; i < 2; i++)
#pragma unroll
                for (int j = 0; j < 4; j++)
                    mma_f16(acc1[i][j], afq[ks][i], bf[j]);
        }

#pragma unroll
        for (int i = 0; i < 2; i++) {
            int rl0 = warpM * 32 + i * 16 + lr;
#pragma unroll
            for (int j = 0; j < 4; j++) {
                int c0 = warpN * 32 + j * 8 + 2 * lc;
                float x0 = ex2(acc1[i][j][0] * EXP2_SCALE);
                float x1 = ex2(acc1[i][j][1] * EXP2_SCALE);
                float x2 = ex2(acc1[i][j][2] * EXP2_SCALE);
                float x3 = ex2(acc1[i][j][3] * EXP2_SCALE);
                z0[i] += x0 + x1;
                z1[i] += x2 + x3;
                *(__half2*)(dsm + POFF + (uint32_t)(rl0 * 72 + c0) * 2) =
                    __floats2half2_rn(x0, x1);
                *(__half2*)(dsm + POFF + (uint32_t)((rl0 + 8) * 72 + c0) * 2) =
                    __floats2half2_rn(x2, x3);
            }
        }
        __syncthreads();

#pragma unroll
        for (int i = 0; i < 4; i++) {
            int idx = tid + i * 256;
            int row = idx >> 3, col8 = (idx & 7) * 8;
            uint4 v = *(const uint4*)(dsm + POFF + (uint32_t)(row * 72 + col8) * 2);
            *(uint4*)(pout + (size_t)row * S_DIM + s0 + col8) = v;
        }

#pragma unroll
        for (int ks = 0; ks < 4; ks++) {
            const int khc = ks * 16;
            uint32_t af[2][4], bf[4][2];
#pragma unroll
            for (int i = 0; i < 2; i++) {
                uint32_t off = (uint32_t)((warpM * 32 + i * 16 + (lane & 15)) * 72 +
                                          khc + ((lane >> 4) << 3));
                ldm_x4(af[i], smb + POFF + (off << 1));
            }
#pragma unroll
            for (int j = 0; j < 4; j += 2) {
                int row = warpN * 32 + (j + (lane >> 4)) * 8 + (lane & 7);
                int col = khc + ((lane >> 3) & 1) * 8;
                uint32_t r4[4];
                ldm_x4(r4, vb + ((uint32_t)(row * 72 + col) << 1));
                bf[j][0] = r4[0]; bf[j][1] = r4[1];
                bf[j + 1][0] = r4[2]; bf[j + 1][1] = r4[3];
            }
#pragma unroll
            for (int i = 0; i < 2; i++)
#pragma unroll
                for (int j = 0; j < 4; j++)
                    mma_f16(acc2[i][j], af[i], bf[j]);
        }
    }

#pragma unroll
    for (int i = 0; i < 2; i++) {
        z0[i] += __shfl_xor_sync(0xffffffffu, z0[i], 1);
        z0[i] += __shfl_xor_sync(0xffffffffu, z0[i], 2);
        z1[i] += __shfl_xor_sync(0xffffffffu, z1[i], 1);
        z1[i] += __shfl_xor_sync(0xffffffffu, z1[i], 2);
    }
    if (lc == 0) {
#pragma unroll
        for (int i = 0; i < 2; i++) {
            int rl0 = warpM * 32 + i * 16 + lr;
            zred[rl0 * 2 + warpN] = z0[i];
            zred[(rl0 + 8) * 2 + warpN] = z1[i];
        }
    }
    __syncthreads();

    if (tid < 128) {
        float Z = zred[tid * 2] + zred[tid * 2 + 1];
        zinv[(size_t)z * T_DIM + t0 + tid] = 1.f / Z;
    }

#pragma unroll
    for (int i = 0; i < 2; i++) {
        int rl0 = warpM * 32 + i * 16 + lr;
        float inv0 = 1.f / (zred[rl0 * 2] + zred[rl0 * 2 + 1]);
        float inv1 = 1.f / (zred[(rl0 + 8) * 2] + zred[(rl0 + 8) * 2 + 1]);
#pragma unroll
        for (int j = 0; j < 4; j++) {
            int c0 = warpN * 32 + j * 8 + 2 * lc;
            __half* d0 = ctx + ((size_t)(t0 + rl0) * B_DIM + b) * E_DIM + h * HD_DIM + c0;
            __half* d1 = ctx + ((size_t)(t0 + rl0 + 8) * B_DIM + b) * E_DIM + h * HD_DIM + c0;
            *(__half2*)d0 = __floats2half2_rn(acc2[i][j][0] * inv0, acc2[i][j][1] * inv0);
            *(__half2*)d1 = __floats2half2_rn(acc2[i][j][2] * inv1, acc2[i][j][3] * inv1);
        }
    }
}

// ---------------- single batched fp32 -> fp16 convert (7 tensors) ----------
__global__ void __launch_bounds__(256) k_cvt7(
    const float* __restrict__ i0, const float* __restrict__ i1, const float* __restrict__ i2,
    const float* __restrict__ w0, const float* __restrict__ w1,
    const float* __restrict__ w2, const float* __restrict__ w3,
    __half* __restrict__ o0, __half* __restrict__ o1, __half* __restrict__ o2,
    __half* __restrict__ p0, __half* __restrict__ p1,
    __half* __restrict__ p2, __half* __restrict__ p3,
    int n_in, int n_w)
{
    const float* x; __half* y; int n;
    switch (blockIdx.z) {
        case 0: x = i0; y = o0; n = n_in; break;
        case 1: x = i1; y = o1; n = n_in; break;
        case 2: x = i2; y = o2; n = n_in; break;
        case 3: x = w0; y = p0; n = n_w; break;
        case 4: x = w1; y = p1; n = n_w; break;
        case 5: x = w2; y = p2; n = n_w; break;
        default: x = w3; y = p3; n = n_w; break;
    }
    int i = (blockIdx.x * 256 + threadIdx.x) * 8;
    if (i < n) {
        float4 v0 = *(const float4*)(x + i);
        float4 v1 = *(const float4*)(x + i + 4);
        union { __half2 h[4]; uint4 u; } p;
        p.h[0] = __floats2half2_rn(v0.x, v0.y);
        p.h[1] = __floats2half2_rn(v0.z, v0.w);
        p.h[2] = __floats2half2_rn(v1.x, v1.y);
        p.h[3] = __floats2half2_rn(v1.z, v1.w);
        *(uint4*)(y + i) = p.u;
    }
}

// V transpose fp16: vt[(z*64+d)*S + s] = vh[(s*2+b)*E + h*64+d]
__global__ void __launch_bounds__(256) k_transpose_v(
    const __half* __restrict__ v, __half* __restrict__ vt)
{
    __shared__ __half t[32][34];
    int z = blockIdx.z, b = z >> 4, h = z & 15;
    int s0 = blockIdx.x * 32, d0 = blockIdx.y * 32;
    int lx = threadIdx.x & 31, ly = threadIdx.x >> 5;
#pragma unroll
    for (int i = 0; i < 32; i += 8) {
        int s = s0 + ly + i;
        t[ly + i][lx] = v[(size_t)(s * B_DIM + b) * E_DIM + h * HD_DIM + d0 + lx];
    }
    __syncthreads();
#pragma unroll
    for (int i = 0; i < 32; i += 8) {
        int d = d0 + ly + i;
        vt[((size_t)z * HD_DIM + d) * S_DIM + s0 + lx] = t[lx][ly + i];
    }
}

// ---------------------------------------------------------------------------
extern "C" void kernel_launch(void* const* d_in, const int* in_sizes, int n_in,
                              void* d_out, int out_size)
{
    const float* query = (const float*)d_in[0];
    const float* key   = (const float*)d_in[1];
    const float* value = (const float*)d_in[2];
    const float* Wq = (const float*)d_in[3];
    const float* bq = (const float*)d_in[4];
    const float* Wk = (const float*)d_in[5];
    const float* bk = (const float*)d_in[6];
    const float* Wv = (const float*)d_in[7];
    const float* bv = (const float*)d_in[8];
    const float* Wo = (const float*)d_in[9];
    const float* bo = (const float*)d_in[10];

    float* out  = (float*)d_out;
    float* avgw = out + (size_t)MB_DIM * E_DIM;

    __half *xq, *xk, *xv, *wq, *wk, *wv, *wo, *qh, *kh, *vh, *ctxh, *vt, *pt;
    float *zi;
    cudaGetSymbolAddress((void**)&xq,   g_xq);
    cudaGetSymbolAddress((void**)&xk,   g_xk);
    cudaGetSymbolAddress((void**)&xv,   g_xv);
    cudaGetSymbolAddress((void**)&wq,   g_wq);
    cudaGetSymbolAddress((void**)&wk,   g_wk);
    cudaGetSymbolAddress((void**)&wv,   g_wv);
    cudaGetSymbolAddress((void**)&wo,   g_wo);
    cudaGetSymbolAddress((void**)&qh,   g_qh);
    cudaGetSymbolAddress((void**)&kh,   g_kh);
    cudaGetSymbolAddress((void**)&vh,   g_vh);
    cudaGetSymbolAddress((void**)&ctxh, g_ctxh);
    cudaGetSymbolAddress((void**)&vt,   g_vt);
    cudaGetSymbolAddress((void**)&pt,   g_ptil);
    cudaGetSymbolAddress((void**)&zi,   g_zinv);

    const int SM_P3 = 3 * (128 + 128) * 72 * 2;   // 110592
    cudaFuncSetAttribute(k_proj3,    cudaFuncAttributeMaxDynamicSharedMemorySize, SM_P3);
    cudaFuncSetAttribute(k_avg_proj, cudaFuncAttributeMaxDynamicSharedMemorySize, SM_P3);
    cudaFuncSetAttribute(k_attn,     cudaFuncAttributeMaxDynamicSharedMemorySize, SM_ATTN);

    const int NXE = MB_DIM * E_DIM;   // 4M
    const int NWW = E_DIM * E_DIM;    // 1M
    dim3 gc(NXE / 2048, 1, 7);
    k_cvt7<<<gc, 256>>>(query, key, value, Wq, Wk, Wv, Wo,
                        xq, xk, xv, wq, wk, wv, wo, NXE, NWW);

    dim3 gp3(E_DIM / 128, MB_DIM / 128, 3);             // (8, 32, 3)
    k_proj3<<<gp3, 256, SM_P3>>>(xq, xk, xv, wq, wk, wv, bq, bk, bv, qh, kh, vh);

    dim3 gt(S_DIM / 32, HD_DIM / 32, B_DIM * H_DIM);    // (64, 2, 32)
    k_transpose_v<<<gt, 256>>>(vh, vt);

    dim3 gat(B_DIM * H_DIM, T_DIM / 128);               // (32, 16)
    k_attn<<<gat, 256, SM_ATTN>>>(qh, kh, vt, pt, zi, ctxh);

    // merged: out-projection (256 blocks) + avg_w (4096 blocks), overlapped
    k_avg_proj<<<NPROJ + MB_DIM, 256, SM_P3>>>(ctxh, wo, bo, out, pt, zi, avgw);
}